// round 8
// baseline (speedup 1.0000x reference)
#include <cuda_runtime.h>
#include <cuda_bf16.h>
#include <math.h>

// Problem constants
#define Bq  4
#define Hh  64
#define Ww  64
#define Cc  128
#define NHh 4
#define Kk  7
#define HDd 32
#define MLPD 512
#define NTOK (Bq*Hh*Ww)   // 16384

typedef __nv_bfloat16  bf16;
typedef __nv_bfloat162 bf162;

// Scratch (device globals — no allocation allowed in kernel_launch)
__device__ __align__(16) bf16  g_qn    [NTOK*Cc];
__device__ __align__(16) bf16  g_kvn   [NTOK*Cc];
__device__ __align__(16) float g_q     [NTOK*Cc];
__device__ __align__(16) bf16  g_kv    [NTOK*2*Cc];
__device__ __align__(16) bf16  g_attn  [NTOK*Cc];
__device__ __align__(16) float g_x     [NTOK*Cc];
__device__ __align__(16) bf16  g_hln   [NTOK*Cc];
__device__ __align__(16) bf16  g_hidden[NTOK*MLPD];

__device__ __forceinline__ unsigned s2u(const void* p) {
    return (unsigned)__cvta_generic_to_shared(p);
}

// ---------------------------------------------------------------------------
// LayerNorm: one warp per token, bf16 output
// ---------------------------------------------------------------------------
__global__ void ln_kernel_bf16(const float* __restrict__ in,
                               const float* __restrict__ g,
                               const float* __restrict__ b,
                               bf16* __restrict__ out, int ntok)
{
    int warp = (blockIdx.x * blockDim.x + threadIdx.x) >> 5;
    int lane = threadIdx.x & 31;
    if (warp >= ntok) return;

    const float4 v = *(const float4*)&in[(size_t)warp*Cc + lane*4];
    float s  = v.x + v.y + v.z + v.w;
    float sq = v.x*v.x + v.y*v.y + v.z*v.z + v.w*v.w;
    #pragma unroll
    for (int off = 16; off; off >>= 1) {
        s  += __shfl_xor_sync(0xffffffff, s,  off);
        sq += __shfl_xor_sync(0xffffffff, sq, off);
    }
    float mean = s * (1.0f/Cc);
    float var  = sq * (1.0f/Cc) - mean*mean;
    float inv  = rsqrtf(var + 1e-5f);

    const float4 gv = *(const float4*)&g[lane*4];
    const float4 bv = *(const float4*)&b[lane*4];
    bf162 o0 = __float22bfloat162_rn(make_float2((v.x-mean)*inv*gv.x + bv.x,
                                                 (v.y-mean)*inv*gv.y + bv.y));
    bf162 o1 = __float22bfloat162_rn(make_float2((v.z-mean)*inv*gv.z + bv.z,
                                                 (v.w-mean)*inv*gv.w + bv.w));
    uint2 pk; pk.x = *(unsigned*)&o0; pk.y = *(unsigned*)&o1;
    *(uint2*)&out[(size_t)warp*Cc + lane*4] = pk;
}

// ---------------------------------------------------------------------------
// bf16 tensor-core GEMM: C = epilogue(A[MxK](bf16) @ W[KxN](fp32) + bias)
//   MODE 0: +bias | 1: (+bias)*scale | 2: gelu(+bias) | 3: +bias+res
//   OUTBF: 1 -> write bf16, 0 -> write fp32
// CTA 64x128, BK=32 double buffered, 128 threads (2m x 2n warps, warp 32x64),
// mma.sync m16n8k16 bf16, fragments via ldmatrix.
// A smem [m][k] pitch 40 bf16 (80B); B smem [k][n] pitch 136 bf16 (272B).
// Requires M%64==0, N%128==0, K%32==0.
// ---------------------------------------------------------------------------
#define APITCH 40
#define BPITCH 136

template <int MODE, int OUTBF>
__global__ __launch_bounds__(128)
void gemm_bf(const bf16* __restrict__ A,
             const float* __restrict__ W,
             const float* __restrict__ bias,
             const float* __restrict__ res,
             void* __restrict__ Cout,
             int M, int N, int K, float scale)
{
    __shared__ bf16 As[2][64*APITCH];
    __shared__ bf16 Bs[2][32*BPITCH];

    const int tid  = threadIdx.x;
    const int bm   = blockIdx.y * 64;
    const int bn   = blockIdx.x * 128;
    const int warp = tid >> 5;
    const int lane = tid & 31;
    const int g    = lane >> 2;
    const int t    = lane & 3;
    const int warpM = warp >> 1;       // 0..1
    const int warpN = warp & 1;        // 0..1

    // global staging maps
    const int arow = tid >> 2;              // not used directly; see chunk map
    (void)arow;
    // A: 256 chunks of 8 bf16; thread handles chunk tid and tid+128
    const int ch0_r = tid >> 2,      ch0_c = tid & 3;
    const int ch1_r = (tid+128) >> 2, ch1_c = (tid+128) & 3;
    // B: thread row/colbase
    const int brow = tid >> 2;
    const int bcol = (tid & 3) * 32;

    const uint4* A4r0 = (const uint4*)(A + (size_t)(bm + ch0_r) * K);
    const uint4* A4r1 = (const uint4*)(A + (size_t)(bm + ch1_r) * K);
    const float* Wg   = W + (size_t)brow * N + bn + bcol;

    float acc[2][8][4];
    #pragma unroll
    for (int mt = 0; mt < 2; mt++)
        #pragma unroll
        for (int nt = 0; nt < 8; nt++)
            #pragma unroll
            for (int e = 0; e < 4; e++) acc[mt][nt][e] = 0.0f;

    const int ntile = K / 32;

    // lane-dependent ldmatrix address components
    const unsigned aBase0 = s2u(As[0]);
    const unsigned bBase0 = s2u(Bs[0]);
    const unsigned aBufSz = 64*APITCH*2;
    const unsigned bBufSz = 32*BPITCH*2;
    const int a_row_sel = lane & 15;
    const int a_k_sel   = (lane >> 4) << 3;
    const int b_k_sel   = (lane & 7) + (((lane >> 3) & 1) << 3);
    const int b_n_sel   = (lane >> 4) << 3;

    uint4  av0, av1;
    float4 wv[8];

    // prologue: tile 0
    av0 = A4r0[0*4 + ch0_c];
    av1 = A4r1[0*4 + ch1_c];
    #pragma unroll
    for (int u = 0; u < 8; u++) wv[u] = *(const float4*)(Wg + u*4);
    {
        *(uint4*)&As[0][ch0_r*APITCH + ch0_c*8] = av0;
        *(uint4*)&As[0][ch1_r*APITCH + ch1_c*8] = av1;
        #pragma unroll
        for (int u = 0; u < 8; u++) {
            bf162 lo = __float22bfloat162_rn(make_float2(wv[u].x, wv[u].y));
            bf162 hi = __float22bfloat162_rn(make_float2(wv[u].z, wv[u].w));
            uint2 pk; pk.x = *(unsigned*)&lo; pk.y = *(unsigned*)&hi;
            *(uint2*)&Bs[0][brow*BPITCH + bcol + u*4] = pk;
        }
    }
    __syncthreads();

    for (int kt = 0; kt < ntile; kt++) {
        const int cur = kt & 1;
        if (kt + 1 < ntile) {
            av0 = A4r0[(kt+1)*4 + ch0_c];
            av1 = A4r1[(kt+1)*4 + ch1_c];
            const float* Wp = Wg + (size_t)(kt+1) * 32 * N;
            #pragma unroll
            for (int u = 0; u < 8; u++) wv[u] = *(const float4*)(Wp + u*4);
        }

        const unsigned aB = aBase0 + cur*aBufSz;
        const unsigned bB = bBase0 + cur*bBufSz;
        #pragma unroll
        for (int kk = 0; kk < 32; kk += 16) {
            unsigned af[2][4], bf[8][2];
            #pragma unroll
            for (int mt = 0; mt < 2; mt++) {
                unsigned addr = aB + ((warpM*32 + mt*16 + a_row_sel)*APITCH + kk + a_k_sel)*2;
                asm volatile("ldmatrix.sync.aligned.m8n8.x4.shared.b16 {%0,%1,%2,%3}, [%4];"
                    : "=r"(af[mt][0]), "=r"(af[mt][1]), "=r"(af[mt][2]), "=r"(af[mt][3])
                    : "r"(addr));
            }
            #pragma unroll
            for (int np = 0; np < 4; np++) {
                unsigned r0, r1, r2, r3;
                unsigned addr = bB + ((kk + b_k_sel)*BPITCH + warpN*64 + np*16 + b_n_sel)*2;
                asm volatile("ldmatrix.sync.aligned.m8n8.x4.trans.shared.b16 {%0,%1,%2,%3}, [%4];"
                    : "=r"(r0), "=r"(r1), "=r"(r2), "=r"(r3)
                    : "r"(addr));
                bf[2*np  ][0] = r0; bf[2*np  ][1] = r1;
                bf[2*np+1][0] = r2; bf[2*np+1][1] = r3;
            }
            #pragma unroll
            for (int mt = 0; mt < 2; mt++)
                #pragma unroll
                for (int nt = 0; nt < 8; nt++)
                    asm volatile(
                        "mma.sync.aligned.m16n8k16.row.col.f32.bf16.bf16.f32 "
                        "{%0,%1,%2,%3}, {%4,%5,%6,%7}, {%8,%9}, {%0,%1,%2,%3};"
                        : "+f"(acc[mt][nt][0]), "+f"(acc[mt][nt][1]),
                          "+f"(acc[mt][nt][2]), "+f"(acc[mt][nt][3])
                        : "r"(af[mt][0]), "r"(af[mt][1]), "r"(af[mt][2]), "r"(af[mt][3]),
                          "r"(bf[nt][0]), "r"(bf[nt][1]));
        }

        if (kt + 1 < ntile) {
            const int nxt = cur ^ 1;
            *(uint4*)&As[nxt][ch0_r*APITCH + ch0_c*8] = av0;
            *(uint4*)&As[nxt][ch1_r*APITCH + ch1_c*8] = av1;
            #pragma unroll
            for (int u = 0; u < 8; u++) {
                bf162 lo = __float22bfloat162_rn(make_float2(wv[u].x, wv[u].y));
                bf162 hi = __float22bfloat162_rn(make_float2(wv[u].z, wv[u].w));
                uint2 pk; pk.x = *(unsigned*)&lo; pk.y = *(unsigned*)&hi;
                *(uint2*)&Bs[nxt][brow*BPITCH + bcol + u*4] = pk;
            }
        }
        __syncthreads();
    }

    // epilogue
    float* Cf  = (float*)Cout;
    bf16*  Cb  = (bf16*)Cout;
    #pragma unroll
    for (int mt = 0; mt < 2; mt++) {
        int row0 = bm + warpM*32 + mt*16 + g;
        int row1 = row0 + 8;
        #pragma unroll
        for (int nt = 0; nt < 8; nt++) {
            int col = bn + warpN*64 + nt*8 + 2*t;
            float b0 = bias[col], b1 = bias[col+1];
            float v00 = acc[mt][nt][0] + b0;
            float v01 = acc[mt][nt][1] + b1;
            float v10 = acc[mt][nt][2] + b0;
            float v11 = acc[mt][nt][3] + b1;
            if (MODE == 1) { v00 *= scale; v01 *= scale; v10 *= scale; v11 *= scale; }
            if (MODE == 2) {
                v00 = 0.5f*v00*(1.0f + erff(v00*0.70710678118654752f));
                v01 = 0.5f*v01*(1.0f + erff(v01*0.70710678118654752f));
                v10 = 0.5f*v10*(1.0f + erff(v10*0.70710678118654752f));
                v11 = 0.5f*v11*(1.0f + erff(v11*0.70710678118654752f));
            }
            if (MODE == 3) {
                float2 r0 = *(const float2*)&res[(size_t)row0*N + col];
                float2 r1 = *(const float2*)&res[(size_t)row1*N + col];
                v00 += r0.x; v01 += r0.y; v10 += r1.x; v11 += r1.y;
            }
            if (OUTBF) {
                bf162 p0 = __float22bfloat162_rn(make_float2(v00, v01));
                bf162 p1 = __float22bfloat162_rn(make_float2(v10, v11));
                *(unsigned*)&Cb[(size_t)row0*N + col] = *(unsigned*)&p0;
                *(unsigned*)&Cb[(size_t)row1*N + col] = *(unsigned*)&p1;
            } else {
                *(float2*)&Cf[(size_t)row0*N + col] = make_float2(v00, v01);
                *(float2*)&Cf[(size_t)row1*N + col] = make_float2(v10, v11);
            }
        }
    }
}

// ---------------------------------------------------------------------------
// Neighborhood attention v2: block = 8x4 query tile, 512 threads (16 warps).
// KV patch 14x10 = 140 tokens staged as bf16. q fp32. Softmax weights kept in
// registers, broadcast via shfl for the V pass. Output bf16.
// ---------------------------------------------------------------------------
#define PR 14
#define PC 10
#define PTOK 140
#define DPAD 40
#define AT_THREADS 512

__global__ __launch_bounds__(AT_THREADS)
void nat_attn2(const float* __restrict__ q,
               const bf16* __restrict__ kv,
               const float* __restrict__ rpb,
               bf16* __restrict__ out)
{
    extern __shared__ char smraw[];
    bf16*  Ks = (bf16*)smraw;                  // [4][140][40]
    bf16*  Vs = Ks + 4*PTOK*DPAD;              // [4][140][40]
    float* qs = (float*)(Vs + 4*PTOK*DPAD);    // [32][128]
    float* rs = qs + 32*128;                   // [676]

    const int blk = blockIdx.x;                // 512 = 4 * 8 * 16
    const int b   = blk >> 7;
    const int rem = blk & 127;
    const int it  = (rem >> 4) << 3;
    const int jt  = (rem & 15) << 2;

    int ip0 = it - 3; if (ip0 < 0) ip0 = 0; if (ip0 > Hh - PR) ip0 = Hh - PR;
    int jp0 = jt - 3; if (jp0 < 0) jp0 = 0; if (jp0 > Ww - PC) jp0 = Ww - PC;

    const int tid  = threadIdx.x;
    const int base = b * (Hh*Ww);

    // stage KV (140 tokens x 256 bf16 = 140*32 uint4)
    const uint4* kv4 = (const uint4*)kv;
    for (int f = tid; f < PTOK*32; f += AT_THREADS) {
        int tok = f >> 5;
        int c8  = f & 31;
        int r   = tok / PC;
        int cc  = tok - r*PC;
        int g   = base + (ip0 + r)*Ww + (jp0 + cc);
        uint4 v = kv4[(size_t)g*32 + c8];
        int c = c8 * 8;
        if (c < Cc) {
            *(uint4*)&Ks[((c>>5)*PTOK + tok)*DPAD + (c & 31)] = v;
        } else {
            int c2 = c - Cc;
            *(uint4*)&Vs[((c2>>5)*PTOK + tok)*DPAD + (c2 & 31)] = v;
        }
    }
    // stage q fp32 (32 queries x 128)
    for (int f = tid; f < 32*32; f += AT_THREADS) {
        int qq = f >> 5, c4 = f & 31;
        int qi = qq >> 2, qj = qq & 3;
        int g = base + (it + qi)*Ww + (jt + qj);
        *(float4*)&qs[qq*Cc + c4*4] = *(const float4*)&q[(size_t)g*Cc + c4*4];
    }
    for (int f = tid; f < 676; f += AT_THREADS) rs[f] = rpb[f];
    __syncthreads();

    const int w    = tid >> 5;
    const int lane = tid & 31;

    #pragma unroll
    for (int s = 0; s < 8; s++) {
        const int task = w*8 + s;            // 0..127
        const int qq = task >> 2;
        const int h  = task & 3;
        const int qi = qq >> 2, qj = qq & 3;
        const int gi = it + qi, gj = jt + qj;
        int i0 = gi - 3; if (i0 < 0) i0 = 0; if (i0 > Hh - Kk) i0 = Hh - Kk;
        int j0 = gj - 3; if (j0 < 0) j0 = 0; if (j0 > Ww - Kk) j0 = Ww - Kk;
        const int ioff = i0 - ip0;
        const int joff = j0 - jp0;

        // q slice (broadcast loads)
        float qf[32];
        #pragma unroll
        for (int u = 0; u < 8; u++) {
            float4 t4 = *(const float4*)&qs[qq*Cc + h*32 + u*4];
            qf[u*4+0] = t4.x; qf[u*4+1] = t4.y; qf[u*4+2] = t4.z; qf[u*4+3] = t4.w;
        }

        // scores: lane handles neighbors lane and lane+32
        float sc[2];
        #pragma unroll
        for (int r = 0; r < 2; r++) {
            int n = r*32 + lane;
            float val = -INFINITY;
            if (n < 49) {
                int ni = n / 7;
                int nj = n - ni*7;
                int lt = (ioff + ni)*PC + joff + nj;
                const uint4* kp = (const uint4*)&Ks[(h*PTOK + lt)*DPAD];
                float a0 = 0.f;
                #pragma unroll
                for (int u = 0; u < 4; u++) {
                    uint4 kk4 = kp[u];
                    float2 f0 = __bfloat1622float2(*(const bf162*)&kk4.x);
                    float2 f1 = __bfloat1622float2(*(const bf162*)&kk4.y);
                    float2 f2 = __bfloat1622float2(*(const bf162*)&kk4.z);
                    float2 f3 = __bfloat1622float2(*(const bf162*)&kk4.w);
                    a0 = fmaf(qf[u*8+0], f0.x, a0);
                    a0 = fmaf(qf[u*8+1], f0.y, a0);
                    a0 = fmaf(qf[u*8+2], f1.x, a0);
                    a0 = fmaf(qf[u*8+3], f1.y, a0);
                    a0 = fmaf(qf[u*8+4], f2.x, a0);
                    a0 = fmaf(qf[u*8+5], f2.y, a0);
                    a0 = fmaf(qf[u*8+6], f3.x, a0);
                    a0 = fmaf(qf[u*8+7], f3.y, a0);
                }
                int ri = i0 + ni - gi + (Kk - 1);
                int rj = j0 + nj - gj + (Kk - 1);
                val = a0 + rs[h*169 + ri*13 + rj];
            }
            sc[r] = val;
        }

        // softmax over 49 within warp
        float mx = fmaxf(sc[0], sc[1]);
        #pragma unroll
        for (int off = 16; off; off >>= 1)
            mx = fmaxf(mx, __shfl_xor_sync(0xffffffff, mx, off));
        float e0 = __expf(sc[0] - mx);
        float e1 = __expf(sc[1] - mx);
        float sum = e0 + e1;
        #pragma unroll
        for (int off = 16; off; off >>= 1)
            sum += __shfl_xor_sync(0xffffffff, sum, off);
        float rinv = 1.0f / sum;
        float p0 = e0 * rinv;
        float p1 = e1 * rinv;

        // V pass: lane = dim, p broadcast via shfl
        float o = 0.0f;
        #pragma unroll
        for (int n = 0; n < 49; n++) {
            float pn = (n < 32) ? __shfl_sync(0xffffffff, p0, n)
                                : __shfl_sync(0xffffffff, p1, n - 32);
            int ni = n / 7;
            int nj = n - ni*7;
            int lt = (ioff + ni)*PC + joff + nj;
            float vv = __bfloat162float(Vs[(h*PTOK + lt)*DPAD + lane]);
            o = fmaf(pn, vv, o);
        }
        int g = base + gi*Ww + gj;
        out[(size_t)g*Cc + h*32 + lane] = __float2bfloat16(o);
    }
}

// ---------------------------------------------------------------------------
// Launch
// ---------------------------------------------------------------------------
extern "C" void kernel_launch(void* const* d_in, const int* in_sizes, int n_in,
                              void* d_out, int out_size)
{
    const float* query     = (const float*)d_in[0];
    const float* key_value = (const float*)d_in[1];
    const float* g1  = (const float*)d_in[2];
    const float* b1  = (const float*)d_in[3];
    const float* g2  = (const float*)d_in[4];
    const float* b2  = (const float*)d_in[5];
    const float* g3  = (const float*)d_in[6];
    const float* b3  = (const float*)d_in[7];
    const float* Wq  = (const float*)d_in[8];
    const float* bq  = (const float*)d_in[9];
    const float* Wkv = (const float*)d_in[10];
    const float* bkv = (const float*)d_in[11];
    const float* Wp  = (const float*)d_in[12];
    const float* bp  = (const float*)d_in[13];
    const float* rpb = (const float*)d_in[14];
    const float* W1  = (const float*)d_in[15];
    const float* bm1 = (const float*)d_in[16];
    const float* W2  = (const float*)d_in[17];
    const float* bm2 = (const float*)d_in[18];
    float* out = (float*)d_out;

    bf16*  qn     = nullptr; cudaGetSymbolAddress((void**)&qn,     g_qn);
    bf16*  kvn    = nullptr; cudaGetSymbolAddress((void**)&kvn,    g_kvn);
    float* qbuf   = nullptr; cudaGetSymbolAddress((void**)&qbuf,   g_q);
    bf16*  kvbuf  = nullptr; cudaGetSymbolAddress((void**)&kvbuf,  g_kv);
    bf16*  attn   = nullptr; cudaGetSymbolAddress((void**)&attn,   g_attn);
    float* xbuf   = nullptr; cudaGetSymbolAddress((void**)&xbuf,   g_x);
    bf16*  hln    = nullptr; cudaGetSymbolAddress((void**)&hln,    g_hln);
    bf16*  hidden = nullptr; cudaGetSymbolAddress((void**)&hidden, g_hidden);

    static bool attr_set = false;
    const int at_smem = (2*4*PTOK*DPAD)*2 + (32*128 + 676)*4;   // 108688 B
    if (!attr_set) {
        cudaFuncSetAttribute(nat_attn2,
                             cudaFuncAttributeMaxDynamicSharedMemorySize, at_smem);
        attr_set = true;
    }

    const int lnBlocks = (NTOK * 32) / 256;

    // 1) LayerNorms -> bf16
    ln_kernel_bf16<<<lnBlocks, 256>>>(query,     g1, b1, qn,  NTOK);
    ln_kernel_bf16<<<lnBlocks, 256>>>(key_value, g2, b2, kvn, NTOK);

    // 2) Q projection (scaled, fp32 out) and KV projection (bf16 out)
    gemm_bf<1,0><<<dim3(Cc/128,   NTOK/64), 128>>>(qn,  Wq,  bq,  nullptr, qbuf,  NTOK, Cc,   Cc, 0.17677669529663689f);
    gemm_bf<0,1><<<dim3(2*Cc/128, NTOK/64), 128>>>(kvn, Wkv, bkv, nullptr, kvbuf, NTOK, 2*Cc, Cc, 1.0f);

    // 3) Neighborhood attention (bf16 KV, bf16 out)
    nat_attn2<<<Bq*(Hh/8)*(Ww/4), AT_THREADS, at_smem>>>(qbuf, kvbuf, rpb, attn);

    // 4) Output projection + residual (fp32 out)
    gemm_bf<3,0><<<dim3(Cc/128, NTOK/64), 128>>>(attn, Wp, bp, key_value, xbuf, NTOK, Cc, Cc, 1.0f);

    // 5) LN3 + MLP
    ln_kernel_bf16<<<lnBlocks, 256>>>(xbuf, g3, b3, hln, NTOK);
    gemm_bf<2,1><<<dim3(MLPD/128, NTOK/64), 128>>>(hln,    W1, bm1, nullptr, hidden, NTOK, MLPD, Cc,   1.0f);
    gemm_bf<3,0><<<dim3(Cc/128,   NTOK/64), 128>>>(hidden, W2, bm2, xbuf,    out,    NTOK, Cc,   MLPD, 1.0f);
}

// round 9
// speedup vs baseline: 1.3878x; 1.3878x over previous
#include <cuda_runtime.h>
#include <cuda_bf16.h>
#include <math.h>

// Problem constants
#define Bq  4
#define Hh  64
#define Ww  64
#define Cc  128
#define NHh 4
#define Kk  7
#define HDd 32
#define MLPD 512
#define NTOK (Bq*Hh*Ww)   // 16384

typedef __nv_bfloat16  bf16;
typedef __nv_bfloat162 bf162;

// Scratch (device globals — no allocation allowed in kernel_launch)
__device__ __align__(16) bf16  g_qn    [NTOK*Cc];
__device__ __align__(16) bf16  g_kvn   [NTOK*Cc];
__device__ __align__(16) float g_q     [NTOK*Cc];
__device__ __align__(16) bf16  g_kv    [NTOK*2*Cc];
__device__ __align__(16) bf16  g_attn  [NTOK*Cc];
__device__ __align__(16) float g_x     [NTOK*Cc];
__device__ __align__(16) bf16  g_hln   [NTOK*Cc];
__device__ __align__(16) bf16  g_hidden[NTOK*MLPD];

// bf16 weights (converted once per launch)
__device__ __align__(16) bf16  g_wq [Cc*Cc];
__device__ __align__(16) bf16  g_wkv[Cc*2*Cc];
__device__ __align__(16) bf16  g_wp [Cc*Cc];
__device__ __align__(16) bf16  g_w1 [Cc*MLPD];
__device__ __align__(16) bf16  g_w2 [MLPD*Cc];

__device__ __forceinline__ unsigned s2u(const void* p) {
    return (unsigned)__cvta_generic_to_shared(p);
}

// ---------------------------------------------------------------------------
// Weight conversion fp32 -> bf16 (once per launch; all 5 weights, float4 lanes)
// totals (float4 units): Wq 4096 | Wkv 8192 | Wp 4096 | W1 16384 | W2 16384
// ---------------------------------------------------------------------------
__global__ void cvt_weights(const float* __restrict__ Wq,
                            const float* __restrict__ Wkv,
                            const float* __restrict__ Wp,
                            const float* __restrict__ W1,
                            const float* __restrict__ W2)
{
    int i = blockIdx.x * blockDim.x + threadIdx.x;   // 0..49151
    const float* src; bf16* dst; int off;
    if      (i < 4096)  { src = Wq;  dst = g_wq;  off = i; }
    else if (i < 12288) { src = Wkv; dst = g_wkv; off = i - 4096; }
    else if (i < 16384) { src = Wp;  dst = g_wp;  off = i - 12288; }
    else if (i < 32768) { src = W1;  dst = g_w1;  off = i - 16384; }
    else                { src = W2;  dst = g_w2;  off = i - 32768; }
    float4 v = ((const float4*)src)[off];
    bf162 lo = __float22bfloat162_rn(make_float2(v.x, v.y));
    bf162 hi = __float22bfloat162_rn(make_float2(v.z, v.w));
    uint2 pk; pk.x = *(unsigned*)&lo; pk.y = *(unsigned*)&hi;
    ((uint2*)dst)[off] = pk;
}

// ---------------------------------------------------------------------------
// LayerNorm: one warp per token, bf16 output
// ---------------------------------------------------------------------------
__global__ void ln_kernel_bf16(const float* __restrict__ in,
                               const float* __restrict__ g,
                               const float* __restrict__ b,
                               bf16* __restrict__ out, int ntok)
{
    int warp = (blockIdx.x * blockDim.x + threadIdx.x) >> 5;
    int lane = threadIdx.x & 31;
    if (warp >= ntok) return;

    const float4 v = *(const float4*)&in[(size_t)warp*Cc + lane*4];
    float s  = v.x + v.y + v.z + v.w;
    float sq = v.x*v.x + v.y*v.y + v.z*v.z + v.w*v.w;
    #pragma unroll
    for (int off = 16; off; off >>= 1) {
        s  += __shfl_xor_sync(0xffffffff, s,  off);
        sq += __shfl_xor_sync(0xffffffff, sq, off);
    }
    float mean = s * (1.0f/Cc);
    float var  = sq * (1.0f/Cc) - mean*mean;
    float inv  = rsqrtf(var + 1e-5f);

    const float4 gv = *(const float4*)&g[lane*4];
    const float4 bv = *(const float4*)&b[lane*4];
    bf162 o0 = __float22bfloat162_rn(make_float2((v.x-mean)*inv*gv.x + bv.x,
                                                 (v.y-mean)*inv*gv.y + bv.y));
    bf162 o1 = __float22bfloat162_rn(make_float2((v.z-mean)*inv*gv.z + bv.z,
                                                 (v.w-mean)*inv*gv.w + bv.w));
    uint2 pk; pk.x = *(unsigned*)&o0; pk.y = *(unsigned*)&o1;
    *(uint2*)&out[(size_t)warp*Cc + lane*4] = pk;
}

// ---------------------------------------------------------------------------
// bf16 tensor-core GEMM: C = epilogue(A[MxK](bf16) @ W[KxN](bf16) + bias)
//   MODE 0: +bias | 1: (+bias)*scale | 2: gelu(+bias) | 3: +bias+res
//   OUTBF: 1 -> bf16 out, 0 -> fp32 out
// CTA 128x128, BK=32, 256 threads (4m x 2n warps, warp tile 32x64),
// cp.async double-buffered staging, ldmatrix fragments, m16n8k16 bf16 MMA.
// Requires M%128==0, N%128==0, K%32==0.
// ---------------------------------------------------------------------------
#define APITCH 40
#define BPITCH 136

#define CP_ASYNC16(dst, src) \
    asm volatile("cp.async.ca.shared.global [%0], [%1], 16;" :: "r"(dst), "l"(src))

template <int MODE, int OUTBF>
__global__ __launch_bounds__(256)
void gemm_bf(const bf16* __restrict__ A,
             const bf16* __restrict__ Wb,
             const float* __restrict__ bias,
             const float* __restrict__ res,
             void* __restrict__ Cout,
             int M, int N, int K, float scale)
{
    __shared__ bf16 As[2][128*APITCH];
    __shared__ bf16 Bs[2][32*BPITCH];

    const int tid  = threadIdx.x;
    const int bm   = blockIdx.y * 128;
    const int bn   = blockIdx.x * 128;
    const int warp = tid >> 5;
    const int lane = tid & 31;
    const int g    = lane >> 2;
    const int t    = lane & 3;
    const int warpM = warp >> 1;       // 0..3
    const int warpN = warp & 1;        // 0..1
    const int m_base = warpM * 32;
    const int n_base = warpN * 64;

    // staging maps (16B chunks). A tile 128x32: 512 chunks; B tile 32x128: 512.
    const int a_r0 = tid >> 2,        a_c = tid & 3;
    const int a_r1 = (tid + 256) >> 2;           // a_c identical
    const int b_r0 = tid >> 4,        b_c = tid & 15;
    const int b_r1 = (tid + 256) >> 4;           // b_c identical

    const bf16* Ag = A  + (size_t)bm * K;
    const bf16* Bg = Wb + bn;

    const unsigned aS = s2u(&As[0][0]);
    const unsigned bS = s2u(&Bs[0][0]);
    const unsigned aBufSz = 128*APITCH*2;
    const unsigned bBufSz = 32*BPITCH*2;

    const unsigned ad0 = aS + (a_r0*APITCH + a_c*8)*2;
    const unsigned ad1 = aS + (a_r1*APITCH + a_c*8)*2;
    const unsigned bd0 = bS + (b_r0*BPITCH + b_c*8)*2;
    const unsigned bd1 = bS + (b_r1*BPITCH + b_c*8)*2;

    float acc[2][8][4];
    #pragma unroll
    for (int mt = 0; mt < 2; mt++)
        #pragma unroll
        for (int nt = 0; nt < 8; nt++)
            #pragma unroll
            for (int e = 0; e < 4; e++) acc[mt][nt][e] = 0.0f;

    const int ntile = K / 32;

    // ldmatrix lane selectors
    const int a_row_sel = lane & 15;
    const int a_k_sel   = (lane >> 4) << 3;
    const int b_k_sel   = (lane & 7) + (((lane >> 3) & 1) << 3);
    const int b_n_sel   = (lane >> 4) << 3;

    // stage tile kt into buffer buf
    auto stage = [&](int buf, int kt) {
        unsigned ao = buf * aBufSz, bo = buf * bBufSz;
        CP_ASYNC16(ad0 + ao, Ag + (size_t)a_r0*K + kt*32 + a_c*8);
        CP_ASYNC16(ad1 + ao, Ag + (size_t)a_r1*K + kt*32 + a_c*8);
        CP_ASYNC16(bd0 + bo, Bg + (size_t)(kt*32 + b_r0)*N + b_c*8);
        CP_ASYNC16(bd1 + bo, Bg + (size_t)(kt*32 + b_r1)*N + b_c*8);
        asm volatile("cp.async.commit_group;");
    };

    stage(0, 0);
    asm volatile("cp.async.wait_group 0;");
    __syncthreads();

    for (int kt = 0; kt < ntile; kt++) {
        const int cur = kt & 1;
        if (kt + 1 < ntile) stage(cur ^ 1, kt + 1);

        const unsigned aB = aS + cur*aBufSz;
        const unsigned bB = bS + cur*bBufSz;
        #pragma unroll
        for (int kk = 0; kk < 32; kk += 16) {
            unsigned af[2][4], bf[8][2];
            #pragma unroll
            for (int mt = 0; mt < 2; mt++) {
                unsigned addr = aB + ((m_base + mt*16 + a_row_sel)*APITCH + kk + a_k_sel)*2;
                asm volatile("ldmatrix.sync.aligned.m8n8.x4.shared.b16 {%0,%1,%2,%3}, [%4];"
                    : "=r"(af[mt][0]), "=r"(af[mt][1]), "=r"(af[mt][2]), "=r"(af[mt][3])
                    : "r"(addr));
            }
            #pragma unroll
            for (int np = 0; np < 4; np++) {
                unsigned r0, r1, r2, r3;
                unsigned addr = bB + ((kk + b_k_sel)*BPITCH + n_base + np*16 + b_n_sel)*2;
                asm volatile("ldmatrix.sync.aligned.m8n8.x4.trans.shared.b16 {%0,%1,%2,%3}, [%4];"
                    : "=r"(r0), "=r"(r1), "=r"(r2), "=r"(r3)
                    : "r"(addr));
                bf[2*np  ][0] = r0; bf[2*np  ][1] = r1;
                bf[2*np+1][0] = r2; bf[2*np+1][1] = r3;
            }
            #pragma unroll
            for (int mt = 0; mt < 2; mt++)
                #pragma unroll
                for (int nt = 0; nt < 8; nt++)
                    asm volatile(
                        "mma.sync.aligned.m16n8k16.row.col.f32.bf16.bf16.f32 "
                        "{%0,%1,%2,%3}, {%4,%5,%6,%7}, {%8,%9}, {%0,%1,%2,%3};"
                        : "+f"(acc[mt][nt][0]), "+f"(acc[mt][nt][1]),
                          "+f"(acc[mt][nt][2]), "+f"(acc[mt][nt][3])
                        : "r"(af[mt][0]), "r"(af[mt][1]), "r"(af[mt][2]), "r"(af[mt][3]),
                          "r"(bf[nt][0]), "r"(bf[nt][1]));
        }

        if (kt + 1 < ntile) asm volatile("cp.async.wait_group 0;");
        __syncthreads();
    }

    // epilogue
    float* Cf = (float*)Cout;
    bf16*  Cb = (bf16*)Cout;
    #pragma unroll
    for (int mt = 0; mt < 2; mt++) {
        int row0 = bm + m_base + mt*16 + g;
        int row1 = row0 + 8;
        #pragma unroll
        for (int nt = 0; nt < 8; nt++) {
            int col = bn + n_base + nt*8 + 2*t;
            float b0 = bias[col], b1 = bias[col+1];
            float v00 = acc[mt][nt][0] + b0;
            float v01 = acc[mt][nt][1] + b1;
            float v10 = acc[mt][nt][2] + b0;
            float v11 = acc[mt][nt][3] + b1;
            if (MODE == 1) { v00 *= scale; v01 *= scale; v10 *= scale; v11 *= scale; }
            if (MODE == 2) {
                v00 = 0.5f*v00*(1.0f + erff(v00*0.70710678118654752f));
                v01 = 0.5f*v01*(1.0f + erff(v01*0.70710678118654752f));
                v10 = 0.5f*v10*(1.0f + erff(v10*0.70710678118654752f));
                v11 = 0.5f*v11*(1.0f + erff(v11*0.70710678118654752f));
            }
            if (MODE == 3) {
                float2 r0 = *(const float2*)&res[(size_t)row0*N + col];
                float2 r1 = *(const float2*)&res[(size_t)row1*N + col];
                v00 += r0.x; v01 += r0.y; v10 += r1.x; v11 += r1.y;
            }
            if (OUTBF) {
                bf162 p0 = __float22bfloat162_rn(make_float2(v00, v01));
                bf162 p1 = __float22bfloat162_rn(make_float2(v10, v11));
                *(unsigned*)&Cb[(size_t)row0*N + col] = *(unsigned*)&p0;
                *(unsigned*)&Cb[(size_t)row1*N + col] = *(unsigned*)&p1;
            } else {
                *(float2*)&Cf[(size_t)row0*N + col] = make_float2(v00, v01);
                *(float2*)&Cf[(size_t)row1*N + col] = make_float2(v10, v11);
            }
        }
    }
}

// ---------------------------------------------------------------------------
// Neighborhood attention v2: block = 8x4 query tile, 512 threads (16 warps).
// KV patch 14x10 = 140 tokens staged as bf16. q fp32. Softmax weights kept in
// registers, broadcast via shfl for the V pass. Output bf16.
// ---------------------------------------------------------------------------
#define PR 14
#define PC 10
#define PTOK 140
#define DPAD 40
#define AT_THREADS 512

__global__ __launch_bounds__(AT_THREADS)
void nat_attn2(const float* __restrict__ q,
               const bf16* __restrict__ kv,
               const float* __restrict__ rpb,
               bf16* __restrict__ out)
{
    extern __shared__ char smraw[];
    bf16*  Ks = (bf16*)smraw;                  // [4][140][40]
    bf16*  Vs = Ks + 4*PTOK*DPAD;              // [4][140][40]
    float* qs = (float*)(Vs + 4*PTOK*DPAD);    // [32][128]
    float* rs = qs + 32*128;                   // [676]

    const int blk = blockIdx.x;
    const int b   = blk >> 7;
    const int rem = blk & 127;
    const int it  = (rem >> 4) << 3;
    const int jt  = (rem & 15) << 2;

    int ip0 = it - 3; if (ip0 < 0) ip0 = 0; if (ip0 > Hh - PR) ip0 = Hh - PR;
    int jp0 = jt - 3; if (jp0 < 0) jp0 = 0; if (jp0 > Ww - PC) jp0 = Ww - PC;

    const int tid  = threadIdx.x;
    const int base = b * (Hh*Ww);

    const uint4* kv4 = (const uint4*)kv;
    for (int f = tid; f < PTOK*32; f += AT_THREADS) {
        int tok = f >> 5;
        int c8  = f & 31;
        int r   = tok / PC;
        int cc  = tok - r*PC;
        int g   = base + (ip0 + r)*Ww + (jp0 + cc);
        uint4 v = kv4[(size_t)g*32 + c8];
        int c = c8 * 8;
        if (c < Cc) {
            *(uint4*)&Ks[((c>>5)*PTOK + tok)*DPAD + (c & 31)] = v;
        } else {
            int c2 = c - Cc;
            *(uint4*)&Vs[((c2>>5)*PTOK + tok)*DPAD + (c2 & 31)] = v;
        }
    }
    for (int f = tid; f < 32*32; f += AT_THREADS) {
        int qq = f >> 5, c4 = f & 31;
        int qi = qq >> 2, qj = qq & 3;
        int g = base + (it + qi)*Ww + (jt + qj);
        *(float4*)&qs[qq*Cc + c4*4] = *(const float4*)&q[(size_t)g*Cc + c4*4];
    }
    for (int f = tid; f < 676; f += AT_THREADS) rs[f] = rpb[f];
    __syncthreads();

    const int w    = tid >> 5;
    const int lane = tid & 31;

    #pragma unroll
    for (int s = 0; s < 8; s++) {
        const int task = w*8 + s;
        const int qq = task >> 2;
        const int h  = task & 3;
        const int qi = qq >> 2, qj = qq & 3;
        const int gi = it + qi, gj = jt + qj;
        int i0 = gi - 3; if (i0 < 0) i0 = 0; if (i0 > Hh - Kk) i0 = Hh - Kk;
        int j0 = gj - 3; if (j0 < 0) j0 = 0; if (j0 > Ww - Kk) j0 = Ww - Kk;
        const int ioff = i0 - ip0;
        const int joff = j0 - jp0;

        float qf[32];
        #pragma unroll
        for (int u = 0; u < 8; u++) {
            float4 t4 = *(const float4*)&qs[qq*Cc + h*32 + u*4];
            qf[u*4+0] = t4.x; qf[u*4+1] = t4.y; qf[u*4+2] = t4.z; qf[u*4+3] = t4.w;
        }

        float sc[2];
        #pragma unroll
        for (int r = 0; r < 2; r++) {
            int n = r*32 + lane;
            float val = -INFINITY;
            if (n < 49) {
                int ni = n / 7;
                int nj = n - ni*7;
                int lt = (ioff + ni)*PC + joff + nj;
                const uint4* kp = (const uint4*)&Ks[(h*PTOK + lt)*DPAD];
                float a0 = 0.f;
                #pragma unroll
                for (int u = 0; u < 4; u++) {
                    uint4 kk4 = kp[u];
                    float2 f0 = __bfloat1622float2(*(const bf162*)&kk4.x);
                    float2 f1 = __bfloat1622float2(*(const bf162*)&kk4.y);
                    float2 f2 = __bfloat1622float2(*(const bf162*)&kk4.z);
                    float2 f3 = __bfloat1622float2(*(const bf162*)&kk4.w);
                    a0 = fmaf(qf[u*8+0], f0.x, a0);
                    a0 = fmaf(qf[u*8+1], f0.y, a0);
                    a0 = fmaf(qf[u*8+2], f1.x, a0);
                    a0 = fmaf(qf[u*8+3], f1.y, a0);
                    a0 = fmaf(qf[u*8+4], f2.x, a0);
                    a0 = fmaf(qf[u*8+5], f2.y, a0);
                    a0 = fmaf(qf[u*8+6], f3.x, a0);
                    a0 = fmaf(qf[u*8+7], f3.y, a0);
                }
                int ri = i0 + ni - gi + (Kk - 1);
                int rj = j0 + nj - gj + (Kk - 1);
                val = a0 + rs[h*169 + ri*13 + rj];
            }
            sc[r] = val;
        }

        float mx = fmaxf(sc[0], sc[1]);
        #pragma unroll
        for (int off = 16; off; off >>= 1)
            mx = fmaxf(mx, __shfl_xor_sync(0xffffffff, mx, off));
        float e0 = __expf(sc[0] - mx);
        float e1 = __expf(sc[1] - mx);
        float sum = e0 + e1;
        #pragma unroll
        for (int off = 16; off; off >>= 1)
            sum += __shfl_xor_sync(0xffffffff, sum, off);
        float rinv = 1.0f / sum;
        float p0 = e0 * rinv;
        float p1 = e1 * rinv;

        float o = 0.0f;
        #pragma unroll
        for (int n = 0; n < 49; n++) {
            float pn = (n < 32) ? __shfl_sync(0xffffffff, p0, n)
                                : __shfl_sync(0xffffffff, p1, n - 32);
            int ni = n / 7;
            int nj = n - ni*7;
            int lt = (ioff + ni)*PC + joff + nj;
            float vv = __bfloat162float(Vs[(h*PTOK + lt)*DPAD + lane]);
            o = fmaf(pn, vv, o);
        }
        int g = base + gi*Ww + gj;
        out[(size_t)g*Cc + h*32 + lane] = __float2bfloat16(o);
    }
}

// ---------------------------------------------------------------------------
// Launch
// ---------------------------------------------------------------------------
extern "C" void kernel_launch(void* const* d_in, const int* in_sizes, int n_in,
                              void* d_out, int out_size)
{
    const float* query     = (const float*)d_in[0];
    const float* key_value = (const float*)d_in[1];
    const float* g1  = (const float*)d_in[2];
    const float* b1  = (const float*)d_in[3];
    const float* g2  = (const float*)d_in[4];
    const float* b2  = (const float*)d_in[5];
    const float* g3  = (const float*)d_in[6];
    const float* b3  = (const float*)d_in[7];
    const float* Wq  = (const float*)d_in[8];
    const float* bq  = (const float*)d_in[9];
    const float* Wkv = (const float*)d_in[10];
    const float* bkv = (const float*)d_in[11];
    const float* Wp  = (const float*)d_in[12];
    const float* bp  = (const float*)d_in[13];
    const float* rpb = (const float*)d_in[14];
    const float* W1  = (const float*)d_in[15];
    const float* bm1 = (const float*)d_in[16];
    const float* W2  = (const float*)d_in[17];
    const float* bm2 = (const float*)d_in[18];
    float* out = (float*)d_out;

    bf16*  qn     = nullptr; cudaGetSymbolAddress((void**)&qn,     g_qn);
    bf16*  kvn    = nullptr; cudaGetSymbolAddress((void**)&kvn,    g_kvn);
    float* qbuf   = nullptr; cudaGetSymbolAddress((void**)&qbuf,   g_q);
    bf16*  kvbuf  = nullptr; cudaGetSymbolAddress((void**)&kvbuf,  g_kv);
    bf16*  attn   = nullptr; cudaGetSymbolAddress((void**)&attn,   g_attn);
    float* xbuf   = nullptr; cudaGetSymbolAddress((void**)&xbuf,   g_x);
    bf16*  hln    = nullptr; cudaGetSymbolAddress((void**)&hln,    g_hln);
    bf16*  hidden = nullptr; cudaGetSymbolAddress((void**)&hidden, g_hidden);
    bf16*  wqb    = nullptr; cudaGetSymbolAddress((void**)&wqb,    g_wq);
    bf16*  wkvb   = nullptr; cudaGetSymbolAddress((void**)&wkvb,   g_wkv);
    bf16*  wpb    = nullptr; cudaGetSymbolAddress((void**)&wpb,    g_wp);
    bf16*  w1b    = nullptr; cudaGetSymbolAddress((void**)&w1b,    g_w1);
    bf16*  w2b    = nullptr; cudaGetSymbolAddress((void**)&w2b,    g_w2);

    static bool attr_set = false;
    const int at_smem = (2*4*PTOK*DPAD)*2 + (32*128 + 676)*4;
    if (!attr_set) {
        cudaFuncSetAttribute(nat_attn2,
                             cudaFuncAttributeMaxDynamicSharedMemorySize, at_smem);
        attr_set = true;
    }

    const int lnBlocks = (NTOK * 32) / 256;

    // 0) weight conversion (bf16)
    cvt_weights<<<192, 256>>>(Wq, Wkv, Wp, W1, W2);

    // 1) LayerNorms -> bf16
    ln_kernel_bf16<<<lnBlocks, 256>>>(query,     g1, b1, qn,  NTOK);
    ln_kernel_bf16<<<lnBlocks, 256>>>(key_value, g2, b2, kvn, NTOK);

    // 2) Q projection (scaled, fp32 out) and KV projection (bf16 out)
    gemm_bf<1,0><<<dim3(Cc/128,   NTOK/128), 256>>>(qn,  wqb,  bq,  nullptr, qbuf,  NTOK, Cc,   Cc, 0.17677669529663689f);
    gemm_bf<0,1><<<dim3(2*Cc/128, NTOK/128), 256>>>(kvn, wkvb, bkv, nullptr, kvbuf, NTOK, 2*Cc, Cc, 1.0f);

    // 3) Neighborhood attention (bf16 KV, bf16 out)
    nat_attn2<<<Bq*(Hh/8)*(Ww/4), AT_THREADS, at_smem>>>(qbuf, kvbuf, rpb, attn);

    // 4) Output projection + residual (fp32 out)
    gemm_bf<3,0><<<dim3(Cc/128, NTOK/128), 256>>>(attn, wpb, bp, key_value, xbuf, NTOK, Cc, Cc, 1.0f);

    // 5) LN3 + MLP
    ln_kernel_bf16<<<lnBlocks, 256>>>(xbuf, g3, b3, hln, NTOK);
    gemm_bf<2,1><<<dim3(MLPD/128, NTOK/128), 256>>>(hln,    w1b, bm1, nullptr, hidden, NTOK, MLPD, Cc,   1.0f);
    gemm_bf<3,0><<<dim3(Cc/128,   NTOK/128), 256>>>(hidden, w2b, bm2, xbuf,    out,    NTOK, Cc,   MLPD, 1.0f);
}

// round 10
// speedup vs baseline: 1.4836x; 1.0690x over previous
#include <cuda_runtime.h>
#include <cuda_bf16.h>
#include <math.h>

// Problem constants
#define Bq  4
#define Hh  64
#define Ww  64
#define Cc  128
#define NHh 4
#define Kk  7
#define HDd 32
#define MLPD 512
#define NTOK (Bq*Hh*Ww)   // 16384

typedef __nv_bfloat16  bf16;
typedef __nv_bfloat162 bf162;

// Scratch (device globals)
__device__ __align__(16) bf16  g_qn    [NTOK*Cc];
__device__ __align__(16) bf16  g_kvn   [NTOK*Cc];
__device__ __align__(16) bf16  g_q     [NTOK*Cc];
__device__ __align__(16) bf16  g_kv    [NTOK*2*Cc];
__device__ __align__(16) bf16  g_attn  [NTOK*Cc];
__device__ __align__(16) float g_x     [NTOK*Cc];
__device__ __align__(16) bf16  g_hln   [NTOK*Cc];
__device__ __align__(16) bf16  g_hidden[NTOK*MLPD];

// bf16 weights (converted once per launch)
__device__ __align__(16) bf16  g_wq [Cc*Cc];
__device__ __align__(16) bf16  g_wkv[Cc*2*Cc];
__device__ __align__(16) bf16  g_wp [Cc*Cc];
__device__ __align__(16) bf16  g_w1 [Cc*MLPD];
__device__ __align__(16) bf16  g_w2 [MLPD*Cc];

__device__ __forceinline__ unsigned s2u(const void* p) {
    return (unsigned)__cvta_generic_to_shared(p);
}

#define CP_ASYNC16(dst, src) \
    asm volatile("cp.async.ca.shared.global [%0], [%1], 16;" :: "r"(dst), "l"(src))

// ---------------------------------------------------------------------------
// Weight conversion fp32 -> bf16
// ---------------------------------------------------------------------------
__global__ void cvt_weights(const float* __restrict__ Wq,
                            const float* __restrict__ Wkv,
                            const float* __restrict__ Wp,
                            const float* __restrict__ W1,
                            const float* __restrict__ W2)
{
    int i = blockIdx.x * blockDim.x + threadIdx.x;   // 0..49151
    const float* src; bf16* dst; int off;
    if      (i < 4096)  { src = Wq;  dst = g_wq;  off = i; }
    else if (i < 12288) { src = Wkv; dst = g_wkv; off = i - 4096; }
    else if (i < 16384) { src = Wp;  dst = g_wp;  off = i - 12288; }
    else if (i < 32768) { src = W1;  dst = g_w1;  off = i - 16384; }
    else                { src = W2;  dst = g_w2;  off = i - 32768; }
    float4 v = ((const float4*)src)[off];
    bf162 lo = __float22bfloat162_rn(make_float2(v.x, v.y));
    bf162 hi = __float22bfloat162_rn(make_float2(v.z, v.w));
    uint2 pk; pk.x = *(unsigned*)&lo; pk.y = *(unsigned*)&hi;
    ((uint2*)dst)[off] = pk;
}

// ---------------------------------------------------------------------------
// LayerNorm: one warp per token, bf16 output
// ---------------------------------------------------------------------------
__global__ void ln_kernel_bf16(const float* __restrict__ in,
                               const float* __restrict__ g,
                               const float* __restrict__ b,
                               bf16* __restrict__ out, int ntok)
{
    int warp = (blockIdx.x * blockDim.x + threadIdx.x) >> 5;
    int lane = threadIdx.x & 31;
    if (warp >= ntok) return;

    const float4 v = *(const float4*)&in[(size_t)warp*Cc + lane*4];
    float s  = v.x + v.y + v.z + v.w;
    float sq = v.x*v.x + v.y*v.y + v.z*v.z + v.w*v.w;
    #pragma unroll
    for (int off = 16; off; off >>= 1) {
        s  += __shfl_xor_sync(0xffffffff, s,  off);
        sq += __shfl_xor_sync(0xffffffff, sq, off);
    }
    float mean = s * (1.0f/Cc);
    float var  = sq * (1.0f/Cc) - mean*mean;
    float inv  = rsqrtf(var + 1e-5f);

    const float4 gv = *(const float4*)&g[lane*4];
    const float4 bv = *(const float4*)&b[lane*4];
    bf162 o0 = __float22bfloat162_rn(make_float2((v.x-mean)*inv*gv.x + bv.x,
                                                 (v.y-mean)*inv*gv.y + bv.y));
    bf162 o1 = __float22bfloat162_rn(make_float2((v.z-mean)*inv*gv.z + bv.z,
                                                 (v.w-mean)*inv*gv.w + bv.w));
    uint2 pk; pk.x = *(unsigned*)&o0; pk.y = *(unsigned*)&o1;
    *(uint2*)&out[(size_t)warp*Cc + lane*4] = pk;
}

// ---------------------------------------------------------------------------
// GEMM core: CTA 64x128, BK=32, 3-stage cp.async ring, 256 threads (8 warps:
// 4m x 2n, warp tile 16x64), ldmatrix + m16n8k16 bf16 MMA, fp32 accum.
// ---------------------------------------------------------------------------
#define APITCH 40
#define BPITCH 136
#define NSTAGE 3

struct GemmFrag { float acc[8][4]; };

// compute one BK=32 tile from smem buffers
__device__ __forceinline__ void gemm_tile(
    unsigned aB, unsigned bB, int m_base, int n_base, int lane, float acc[8][4])
{
    const int a_row_sel = lane & 15;
    const int a_k_sel   = (lane >> 4) << 3;
    const int b_k_sel   = (lane & 7) + (((lane >> 3) & 1) << 3);
    const int b_n_sel   = (lane >> 4) << 3;
    #pragma unroll
    for (int kk = 0; kk < 32; kk += 16) {
        unsigned af[4], bf[8][2];
        {
            unsigned addr = aB + ((m_base + a_row_sel)*APITCH + kk + a_k_sel)*2;
            asm volatile("ldmatrix.sync.aligned.m8n8.x4.shared.b16 {%0,%1,%2,%3}, [%4];"
                : "=r"(af[0]), "=r"(af[1]), "=r"(af[2]), "=r"(af[3]) : "r"(addr));
        }
        #pragma unroll
        for (int np = 0; np < 4; np++) {
            unsigned r0, r1, r2, r3;
            unsigned addr = bB + ((kk + b_k_sel)*BPITCH + n_base + np*16 + b_n_sel)*2;
            asm volatile("ldmatrix.sync.aligned.m8n8.x4.trans.shared.b16 {%0,%1,%2,%3}, [%4];"
                : "=r"(r0), "=r"(r1), "=r"(r2), "=r"(r3) : "r"(addr));
            bf[2*np  ][0] = r0; bf[2*np  ][1] = r1;
            bf[2*np+1][0] = r2; bf[2*np+1][1] = r3;
        }
        #pragma unroll
        for (int nt = 0; nt < 8; nt++)
            asm volatile(
                "mma.sync.aligned.m16n8k16.row.col.f32.bf16.bf16.f32 "
                "{%0,%1,%2,%3}, {%4,%5,%6,%7}, {%8,%9}, {%0,%1,%2,%3};"
                : "+f"(acc[nt][0]), "+f"(acc[nt][1]), "+f"(acc[nt][2]), "+f"(acc[nt][3])
                : "r"(af[0]), "r"(af[1]), "r"(af[2]), "r"(af[3]),
                  "r"(bf[nt][0]), "r"(bf[nt][1]));
    }
}

// ---------------------------------------------------------------------------
// Generic GEMM: C = epilogue(A @ W + bias)
//   MODE 0: +bias | 1: (+bias)*scale | 2: gelu(+bias) | 3: +bias+res
//   OUTBF: 1 -> bf16 out, 0 -> fp32 out
// ---------------------------------------------------------------------------
template <int MODE, int OUTBF>
__global__ __launch_bounds__(256)
void gemm_bf(const bf16* __restrict__ A,
             const bf16* __restrict__ Wb,
             const float* __restrict__ bias,
             const float* __restrict__ res,
             void* __restrict__ Cout,
             int M, int N, int K, float scale)
{
    __shared__ bf16 As[NSTAGE][64*APITCH];
    __shared__ bf16 Bs[NSTAGE][32*BPITCH];

    const int tid  = threadIdx.x;
    const int bm   = blockIdx.y * 64;
    const int bn   = blockIdx.x * 128;
    const int warp = tid >> 5;
    const int lane = tid & 31;
    const int g    = lane >> 2;
    const int t    = lane & 3;
    const int m_base = (warp >> 1) * 16;
    const int n_base = (warp & 1) * 64;

    const int a_r = tid >> 2, a_c = tid & 3;
    const int b_r0 = tid >> 4, b_c = tid & 15;
    const int b_r1 = b_r0 + 16;

    const bf16* Ag = A  + (size_t)bm * K;
    const bf16* Bg = Wb + bn;

    const unsigned aS = s2u(&As[0][0]);
    const unsigned bS = s2u(&Bs[0][0]);
    const unsigned aBufSz = 64*APITCH*2;
    const unsigned bBufSz = 32*BPITCH*2;
    const unsigned ad = aS + (a_r*APITCH + a_c*8)*2;
    const unsigned bd0 = bS + (b_r0*BPITCH + b_c*8)*2;
    const unsigned bd1 = bS + (b_r1*BPITCH + b_c*8)*2;

    float acc[8][4];
    #pragma unroll
    for (int nt = 0; nt < 8; nt++)
        #pragma unroll
        for (int e = 0; e < 4; e++) acc[nt][e] = 0.0f;

    const int ntile = K / 32;

    auto stage = [&](int buf, int kt) {
        CP_ASYNC16(ad  + buf*aBufSz, Ag + (size_t)a_r*K + kt*32 + a_c*8);
        CP_ASYNC16(bd0 + buf*bBufSz, Bg + (size_t)(kt*32 + b_r0)*N + b_c*8);
        CP_ASYNC16(bd1 + buf*bBufSz, Bg + (size_t)(kt*32 + b_r1)*N + b_c*8);
        asm volatile("cp.async.commit_group;");
    };

    stage(0, 0);
    if (ntile > 1) stage(1, 1);

    for (int kt = 0; kt < ntile; kt++) {
        if (kt + 1 < ntile) asm volatile("cp.async.wait_group 1;");
        else                asm volatile("cp.async.wait_group 0;");
        __syncthreads();
        if (kt + 2 < ntile) stage((kt + 2) % NSTAGE, kt + 2);
        const int cur = kt % NSTAGE;
        gemm_tile(aS + cur*aBufSz, bS + cur*bBufSz, m_base, n_base, lane, acc);
        __syncthreads();
    }

    float* Cf = (float*)Cout;
    bf16*  Cb = (bf16*)Cout;
    int row0 = bm + m_base + g;
    int row1 = row0 + 8;
    #pragma unroll
    for (int nt = 0; nt < 8; nt++) {
        int col = bn + n_base + nt*8 + 2*t;
        float b0 = bias[col], b1 = bias[col+1];
        float v00 = acc[nt][0] + b0;
        float v01 = acc[nt][1] + b1;
        float v10 = acc[nt][2] + b0;
        float v11 = acc[nt][3] + b1;
        if (MODE == 1) { v00 *= scale; v01 *= scale; v10 *= scale; v11 *= scale; }
        if (MODE == 2) {
            v00 = 0.5f*v00*(1.0f + erff(v00*0.70710678118654752f));
            v01 = 0.5f*v01*(1.0f + erff(v01*0.70710678118654752f));
            v10 = 0.5f*v10*(1.0f + erff(v10*0.70710678118654752f));
            v11 = 0.5f*v11*(1.0f + erff(v11*0.70710678118654752f));
        }
        if (MODE == 3) {
            float2 r0 = *(const float2*)&res[(size_t)row0*N + col];
            float2 r1 = *(const float2*)&res[(size_t)row1*N + col];
            v00 += r0.x; v01 += r0.y; v10 += r1.x; v11 += r1.y;
        }
        if (OUTBF) {
            bf162 p0 = __float22bfloat162_rn(make_float2(v00, v01));
            bf162 p1 = __float22bfloat162_rn(make_float2(v10, v11));
            *(unsigned*)&Cb[(size_t)row0*N + col] = *(unsigned*)&p0;
            *(unsigned*)&Cb[(size_t)row1*N + col] = *(unsigned*)&p1;
        } else {
            *(float2*)&Cf[(size_t)row0*N + col] = make_float2(v00, v01);
            *(float2*)&Cf[(size_t)row1*N + col] = make_float2(v10, v11);
        }
    }
}

// ---------------------------------------------------------------------------
// Fused Q + KV projection. blockIdx.x: 0 -> Q (N=128, scaled), 1..2 -> KV cols.
// All bf16 outputs. K = 128.
// ---------------------------------------------------------------------------
__global__ __launch_bounds__(256)
void qkv_gemm(const bf16* __restrict__ qn, const bf16* __restrict__ kvn,
              const float* __restrict__ bq, const float* __restrict__ bkv,
              bf16* __restrict__ qout, bf16* __restrict__ kvout)
{
    __shared__ bf16 As[NSTAGE][64*APITCH];
    __shared__ bf16 Bs[NSTAGE][32*BPITCH];

    const int cb = blockIdx.x;
    const bool isQ = (cb == 0);
    const bf16*  A    = isQ ? qn : kvn;
    const bf16*  Wb   = isQ ? g_wq : g_wkv;
    const float* bias = isQ ? bq : bkv;
    bf16*        Cb   = isQ ? qout : kvout;
    const int N  = isQ ? Cc : 2*Cc;
    const int bn = isQ ? 0 : (cb - 1) * 128;
    const int K  = Cc;
    const float scale = 0.17677669529663689f;

    const int tid  = threadIdx.x;
    const int bm   = blockIdx.y * 64;
    const int warp = tid >> 5;
    const int lane = tid & 31;
    const int g    = lane >> 2;
    const int t    = lane & 3;
    const int m_base = (warp >> 1) * 16;
    const int n_base = (warp & 1) * 64;

    const int a_r = tid >> 2, a_c = tid & 3;
    const int b_r0 = tid >> 4, b_c = tid & 15;
    const int b_r1 = b_r0 + 16;

    const bf16* Ag = A  + (size_t)bm * K;
    const bf16* Bg = Wb + bn;

    const unsigned aS = s2u(&As[0][0]);
    const unsigned bS = s2u(&Bs[0][0]);
    const unsigned aBufSz = 64*APITCH*2;
    const unsigned bBufSz = 32*BPITCH*2;
    const unsigned ad = aS + (a_r*APITCH + a_c*8)*2;
    const unsigned bd0 = bS + (b_r0*BPITCH + b_c*8)*2;
    const unsigned bd1 = bS + (b_r1*BPITCH + b_c*8)*2;

    float acc[8][4];
    #pragma unroll
    for (int nt = 0; nt < 8; nt++)
        #pragma unroll
        for (int e = 0; e < 4; e++) acc[nt][e] = 0.0f;

    const int ntile = K / 32;   // 4

    auto stage = [&](int buf, int kt) {
        CP_ASYNC16(ad  + buf*aBufSz, Ag + (size_t)a_r*K + kt*32 + a_c*8);
        CP_ASYNC16(bd0 + buf*bBufSz, Bg + (size_t)(kt*32 + b_r0)*N + b_c*8);
        CP_ASYNC16(bd1 + buf*bBufSz, Bg + (size_t)(kt*32 + b_r1)*N + b_c*8);
        asm volatile("cp.async.commit_group;");
    };

    stage(0, 0);
    stage(1, 1);

    for (int kt = 0; kt < ntile; kt++) {
        if (kt + 1 < ntile) asm volatile("cp.async.wait_group 1;");
        else                asm volatile("cp.async.wait_group 0;");
        __syncthreads();
        if (kt + 2 < ntile) stage((kt + 2) % NSTAGE, kt + 2);
        const int cur = kt % NSTAGE;
        gemm_tile(aS + cur*aBufSz, bS + cur*bBufSz, m_base, n_base, lane, acc);
        __syncthreads();
    }

    int row0 = bm + m_base + g;
    int row1 = row0 + 8;
    #pragma unroll
    for (int nt = 0; nt < 8; nt++) {
        int col = bn + n_base + nt*8 + 2*t;
        float b0 = bias[col], b1 = bias[col+1];
        float v00 = acc[nt][0] + b0;
        float v01 = acc[nt][1] + b1;
        float v10 = acc[nt][2] + b0;
        float v11 = acc[nt][3] + b1;
        if (isQ) { v00 *= scale; v01 *= scale; v10 *= scale; v11 *= scale; }
        bf162 p0 = __float22bfloat162_rn(make_float2(v00, v01));
        bf162 p1 = __float22bfloat162_rn(make_float2(v10, v11));
        *(unsigned*)&Cb[(size_t)row0*N + col] = *(unsigned*)&p0;
        *(unsigned*)&Cb[(size_t)row1*N + col] = *(unsigned*)&p1;
    }
}

// ---------------------------------------------------------------------------
// Neighborhood attention v3: one block = 8x4 query tile x ONE head.
// 256 threads (8 warps), 4 serial tasks per warp. Static smem ~23 KB.
// ---------------------------------------------------------------------------
#define PR 14
#define PC 10
#define PTOK 140
#define DPAD 40

__global__ __launch_bounds__(256)
void nat_attn3(const bf16* __restrict__ q,
               const bf16* __restrict__ kv,
               const float* __restrict__ rpb,
               bf16* __restrict__ out)
{
    __shared__ bf16 Ks[PTOK*DPAD];
    __shared__ bf16 Vs[PTOK*DPAD];
    __shared__ float rs[169];

    const int blk = blockIdx.x;          // 2048 = 4 heads * 512 tiles
    const int h   = blk & 3;
    const int r2  = blk >> 2;
    const int b   = r2 >> 7;
    const int rem = r2 & 127;
    const int it  = (rem >> 4) << 3;
    const int jt  = (rem & 15) << 2;

    int ip0 = it - 3; if (ip0 < 0) ip0 = 0; if (ip0 > Hh - PR) ip0 = Hh - PR;
    int jp0 = jt - 3; if (jp0 < 0) jp0 = 0; if (jp0 > Ww - PC) jp0 = Ww - PC;

    const int tid  = threadIdx.x;
    const int base = b * (Hh*Ww);

    // stage this head's K,V for the 14x10 patch (1120 uint4 chunks)
    const uint4* kv4 = (const uint4*)kv;
    for (int f = tid; f < PTOK*8; f += 256) {
        int tok = f >> 3;
        int c   = f & 7;
        int r   = tok / PC;
        int cc  = tok - r*PC;
        int g   = base + (ip0 + r)*Ww + (jp0 + cc);
        if (c < 4) {
            *(uint4*)&Ks[tok*DPAD + c*8] = kv4[(size_t)g*32 + h*4 + c];
        } else {
            int c2 = c - 4;
            *(uint4*)&Vs[tok*DPAD + c2*8] = kv4[(size_t)g*32 + 16 + h*4 + c2];
        }
    }
    for (int f = tid; f < 169; f += 256) rs[f] = rpb[h*169 + f];
    __syncthreads();

    const int w    = tid >> 5;
    const int lane = tid & 31;
    const uint4* qb4 = (const uint4*)q;

    #pragma unroll
    for (int s = 0; s < 4; s++) {
        const int qq = w*4 + s;              // 0..31
        const int qi = qq >> 2, qj = qq & 3;
        const int gi = it + qi, gj = jt + qj;
        int i0 = gi - 3; if (i0 < 0) i0 = 0; if (i0 > Hh - Kk) i0 = Hh - Kk;
        int j0 = gj - 3; if (j0 < 0) j0 = 0; if (j0 > Ww - Kk) j0 = Ww - Kk;
        const int ioff = i0 - ip0;
        const int joff = j0 - jp0;
        const int g = base + gi*Ww + gj;

        // q slice (32 bf16 -> fp32), broadcast global load
        float qf[32];
        #pragma unroll
        for (int u = 0; u < 4; u++) {
            uint4 v = qb4[(size_t)g*16 + h*4 + u];
            float2 f0 = __bfloat1622float2(*(const bf162*)&v.x);
            float2 f1 = __bfloat1622float2(*(const bf162*)&v.y);
            float2 f2 = __bfloat1622float2(*(const bf162*)&v.z);
            float2 f3 = __bfloat1622float2(*(const bf162*)&v.w);
            qf[u*8+0]=f0.x; qf[u*8+1]=f0.y; qf[u*8+2]=f1.x; qf[u*8+3]=f1.y;
            qf[u*8+4]=f2.x; qf[u*8+5]=f2.y; qf[u*8+6]=f3.x; qf[u*8+7]=f3.y;
        }

        float sc[2];
        #pragma unroll
        for (int r = 0; r < 2; r++) {
            int n = r*32 + lane;
            float val = -INFINITY;
            if (n < 49) {
                int ni = n / 7;
                int nj = n - ni*7;
                int lt = (ioff + ni)*PC + joff + nj;
                const uint4* kp = (const uint4*)&Ks[lt*DPAD];
                float a0 = 0.f;
                #pragma unroll
                for (int u = 0; u < 4; u++) {
                    uint4 kk4 = kp[u];
                    float2 f0 = __bfloat1622float2(*(const bf162*)&kk4.x);
                    float2 f1 = __bfloat1622float2(*(const bf162*)&kk4.y);
                    float2 f2 = __bfloat1622float2(*(const bf162*)&kk4.z);
                    float2 f3 = __bfloat1622float2(*(const bf162*)&kk4.w);
                    a0 = fmaf(qf[u*8+0], f0.x, a0);
                    a0 = fmaf(qf[u*8+1], f0.y, a0);
                    a0 = fmaf(qf[u*8+2], f1.x, a0);
                    a0 = fmaf(qf[u*8+3], f1.y, a0);
                    a0 = fmaf(qf[u*8+4], f2.x, a0);
                    a0 = fmaf(qf[u*8+5], f2.y, a0);
                    a0 = fmaf(qf[u*8+6], f3.x, a0);
                    a0 = fmaf(qf[u*8+7], f3.y, a0);
                }
                int ri = i0 + ni - gi + (Kk - 1);
                int rj = j0 + nj - gj + (Kk - 1);
                val = a0 + rs[ri*13 + rj];
            }
            sc[r] = val;
        }

        float mx = fmaxf(sc[0], sc[1]);
        #pragma unroll
        for (int off = 16; off; off >>= 1)
            mx = fmaxf(mx, __shfl_xor_sync(0xffffffff, mx, off));
        float e0 = __expf(sc[0] - mx);
        float e1 = __expf(sc[1] - mx);
        float sum = e0 + e1;
        #pragma unroll
        for (int off = 16; off; off >>= 1)
            sum += __shfl_xor_sync(0xffffffff, sum, off);
        float rinv = 1.0f / sum;
        float p0 = e0 * rinv;
        float p1 = e1 * rinv;

        float o = 0.0f;
        #pragma unroll
        for (int n = 0; n < 49; n++) {
            float pn = (n < 32) ? __shfl_sync(0xffffffff, p0, n)
                                : __shfl_sync(0xffffffff, p1, n - 32);
            int ni = n / 7;
            int nj = n - ni*7;
            int lt = (ioff + ni)*PC + joff + nj;
            float vv = __bfloat162float(Vs[lt*DPAD + lane]);
            o = fmaf(pn, vv, o);
        }
        out[(size_t)g*Cc + h*32 + lane] = __float2bfloat16(o);
    }
}

// ---------------------------------------------------------------------------
// Launch
// ---------------------------------------------------------------------------
extern "C" void kernel_launch(void* const* d_in, const int* in_sizes, int n_in,
                              void* d_out, int out_size)
{
    const float* query     = (const float*)d_in[0];
    const float* key_value = (const float*)d_in[1];
    const float* g1  = (const float*)d_in[2];
    const float* b1  = (const float*)d_in[3];
    const float* g2  = (const float*)d_in[4];
    const float* b2  = (const float*)d_in[5];
    const float* g3  = (const float*)d_in[6];
    const float* b3  = (const float*)d_in[7];
    const float* Wq  = (const float*)d_in[8];
    const float* bq  = (const float*)d_in[9];
    const float* Wkv = (const float*)d_in[10];
    const float* bkv = (const float*)d_in[11];
    const float* Wp  = (const float*)d_in[12];
    const float* bp  = (const float*)d_in[13];
    const float* rpb = (const float*)d_in[14];
    const float* W1  = (const float*)d_in[15];
    const float* bm1 = (const float*)d_in[16];
    const float* W2  = (const float*)d_in[17];
    const float* bm2 = (const float*)d_in[18];
    float* out = (float*)d_out;

    bf16*  qn     = nullptr; cudaGetSymbolAddress((void**)&qn,     g_qn);
    bf16*  kvn    = nullptr; cudaGetSymbolAddress((void**)&kvn,    g_kvn);
    bf16*  qbuf   = nullptr; cudaGetSymbolAddress((void**)&qbuf,   g_q);
    bf16*  kvbuf  = nullptr; cudaGetSymbolAddress((void**)&kvbuf,  g_kv);
    bf16*  attn   = nullptr; cudaGetSymbolAddress((void**)&attn,   g_attn);
    float* xbuf   = nullptr; cudaGetSymbolAddress((void**)&xbuf,   g_x);
    bf16*  hln    = nullptr; cudaGetSymbolAddress((void**)&hln,    g_hln);
    bf16*  hidden = nullptr; cudaGetSymbolAddress((void**)&hidden, g_hidden);
    bf16*  wpb    = nullptr; cudaGetSymbolAddress((void**)&wpb,    g_wp);
    bf16*  w1b    = nullptr; cudaGetSymbolAddress((void**)&w1b,    g_w1);
    bf16*  w2b    = nullptr; cudaGetSymbolAddress((void**)&w2b,    g_w2);

    const int lnBlocks = (NTOK * 32) / 256;

    // 0) weight conversion
    cvt_weights<<<192, 256>>>(Wq, Wkv, Wp, W1, W2);

    // 1) LayerNorms -> bf16
    ln_kernel_bf16<<<lnBlocks, 256>>>(query,     g1, b1, qn,  NTOK);
    ln_kernel_bf16<<<lnBlocks, 256>>>(key_value, g2, b2, kvn, NTOK);

    // 2) Fused Q + KV projections (bf16 out)
    qkv_gemm<<<dim3(3, NTOK/64), 256>>>(qn, kvn, bq, bkv, qbuf, kvbuf);

    // 3) Neighborhood attention (per-head blocks)
    nat_attn3<<<Bq*(Hh/8)*(Ww/4)*NHh, 256>>>(qbuf, kvbuf, rpb, attn);

    // 4) Output projection + residual (fp32 out)
    gemm_bf<3,0><<<dim3(Cc/128, NTOK/64), 256>>>(attn, wpb, bp, key_value, xbuf, NTOK, Cc, Cc, 1.0f);

    // 5) LN3 + MLP
    ln_kernel_bf16<<<lnBlocks, 256>>>(xbuf, g3, b3, hln, NTOK);
    gemm_bf<2,1><<<dim3(MLPD/128, NTOK/64), 256>>>(hln,    w1b, bm1, nullptr, hidden, NTOK, MLPD, Cc,   1.0f);
    gemm_bf<3,0><<<dim3(Cc/128,   NTOK/64), 256>>>(hidden, w2b, bm2, xbuf,    out,    NTOK, Cc,   MLPD, 1.0f);
}

// round 11
// speedup vs baseline: 1.5353x; 1.0349x over previous
#include <cuda_runtime.h>
#include <cuda_bf16.h>
#include <math.h>

// Problem constants
#define Bq  4
#define Hh  64
#define Ww  64
#define Cc  128
#define NHh 4
#define Kk  7
#define HDd 32
#define MLPD 512
#define NTOK (Bq*Hh*Ww)   // 16384

typedef __nv_bfloat16  bf16;
typedef __nv_bfloat162 bf162;

// Scratch (device globals)
__device__ __align__(16) bf16  g_qn    [NTOK*Cc];
__device__ __align__(16) bf16  g_kvn   [NTOK*Cc];
__device__ __align__(16) bf16  g_q     [NTOK*Cc];
__device__ __align__(16) bf16  g_kv    [NTOK*2*Cc];
__device__ __align__(16) bf16  g_attn  [NTOK*Cc];
__device__ __align__(16) float g_x     [NTOK*Cc];
__device__ __align__(16) bf16  g_hln   [NTOK*Cc];
__device__ __align__(16) bf16  g_hidden[NTOK*MLPD];

// bf16 weights (converted once per launch)
__device__ __align__(16) bf16  g_wq [Cc*Cc];
__device__ __align__(16) bf16  g_wkv[Cc*2*Cc];
__device__ __align__(16) bf16  g_wp [Cc*Cc];
__device__ __align__(16) bf16  g_w1 [Cc*MLPD];
__device__ __align__(16) bf16  g_w2 [MLPD*Cc];

__device__ __forceinline__ unsigned s2u(const void* p) {
    return (unsigned)__cvta_generic_to_shared(p);
}

#define CP_ASYNC16(dst, src) \
    asm volatile("cp.async.ca.shared.global [%0], [%1], 16;" :: "r"(dst), "l"(src))

// ---------------------------------------------------------------------------
// Weight conversion fp32 -> bf16
// ---------------------------------------------------------------------------
__global__ void cvt_weights(const float* __restrict__ Wq,
                            const float* __restrict__ Wkv,
                            const float* __restrict__ Wp,
                            const float* __restrict__ W1,
                            const float* __restrict__ W2)
{
    int i = blockIdx.x * blockDim.x + threadIdx.x;   // 0..49151
    const float* src; bf16* dst; int off;
    if      (i < 4096)  { src = Wq;  dst = g_wq;  off = i; }
    else if (i < 12288) { src = Wkv; dst = g_wkv; off = i - 4096; }
    else if (i < 16384) { src = Wp;  dst = g_wp;  off = i - 12288; }
    else if (i < 32768) { src = W1;  dst = g_w1;  off = i - 16384; }
    else                { src = W2;  dst = g_w2;  off = i - 32768; }
    float4 v = ((const float4*)src)[off];
    bf162 lo = __float22bfloat162_rn(make_float2(v.x, v.y));
    bf162 hi = __float22bfloat162_rn(make_float2(v.z, v.w));
    uint2 pk; pk.x = *(unsigned*)&lo; pk.y = *(unsigned*)&hi;
    ((uint2*)dst)[off] = pk;
}

// ---------------------------------------------------------------------------
// Dual LayerNorm: warps [0,NTOK) -> LN(query), [NTOK,2*NTOK) -> LN(key_value)
// ---------------------------------------------------------------------------
__global__ void ln_dual(const float* __restrict__ in1, const float* __restrict__ gg1,
                        const float* __restrict__ bb1, bf16* __restrict__ out1,
                        const float* __restrict__ in2, const float* __restrict__ gg2,
                        const float* __restrict__ bb2, bf16* __restrict__ out2)
{
    int w    = (blockIdx.x * blockDim.x + threadIdx.x) >> 5;
    int lane = threadIdx.x & 31;
    const float* in; const float* g; const float* b; bf16* out; int tok;
    if (w < NTOK) { in = in1; g = gg1; b = bb1; out = out1; tok = w; }
    else          { in = in2; g = gg2; b = bb2; out = out2; tok = w - NTOK; }

    const float4 v = *(const float4*)&in[(size_t)tok*Cc + lane*4];
    float s  = v.x + v.y + v.z + v.w;
    float sq = v.x*v.x + v.y*v.y + v.z*v.z + v.w*v.w;
    #pragma unroll
    for (int off = 16; off; off >>= 1) {
        s  += __shfl_xor_sync(0xffffffff, s,  off);
        sq += __shfl_xor_sync(0xffffffff, sq, off);
    }
    float mean = s * (1.0f/Cc);
    float var  = sq * (1.0f/Cc) - mean*mean;
    float inv  = rsqrtf(var + 1e-5f);

    const float4 gv = *(const float4*)&g[lane*4];
    const float4 bv = *(const float4*)&b[lane*4];
    bf162 o0 = __float22bfloat162_rn(make_float2((v.x-mean)*inv*gv.x + bv.x,
                                                 (v.y-mean)*inv*gv.y + bv.y));
    bf162 o1 = __float22bfloat162_rn(make_float2((v.z-mean)*inv*gv.z + bv.z,
                                                 (v.w-mean)*inv*gv.w + bv.w));
    uint2 pk; pk.x = *(unsigned*)&o0; pk.y = *(unsigned*)&o1;
    *(uint2*)&out[(size_t)tok*Cc + lane*4] = pk;
}

// ---------------------------------------------------------------------------
// MMA tile helper: one BK=32 slab. apitch/bpitch in bf16 elements.
// warp tile 16 x 64 (8 n-tiles of m16n8k16).
// ---------------------------------------------------------------------------
__device__ __forceinline__ void gemm_tile(
    unsigned aB, unsigned bB, int m_base, int n_base, int lane,
    float acc[8][4], int apitch, int bpitch)
{
    const int a_row_sel = lane & 15;
    const int a_k_sel   = (lane >> 4) << 3;
    const int b_k_sel   = (lane & 7) + (((lane >> 3) & 1) << 3);
    const int b_n_sel   = (lane >> 4) << 3;
    #pragma unroll
    for (int kk = 0; kk < 32; kk += 16) {
        unsigned af[4], bf[8][2];
        {
            unsigned addr = aB + ((m_base + a_row_sel)*apitch + kk + a_k_sel)*2;
            asm volatile("ldmatrix.sync.aligned.m8n8.x4.shared.b16 {%0,%1,%2,%3}, [%4];"
                : "=r"(af[0]), "=r"(af[1]), "=r"(af[2]), "=r"(af[3]) : "r"(addr));
        }
        #pragma unroll
        for (int np = 0; np < 4; np++) {
            unsigned r0, r1, r2, r3;
            unsigned addr = bB + ((kk + b_k_sel)*bpitch + n_base + np*16 + b_n_sel)*2;
            asm volatile("ldmatrix.sync.aligned.m8n8.x4.trans.shared.b16 {%0,%1,%2,%3}, [%4];"
                : "=r"(r0), "=r"(r1), "=r"(r2), "=r"(r3) : "r"(addr));
            bf[2*np  ][0] = r0; bf[2*np  ][1] = r1;
            bf[2*np+1][0] = r2; bf[2*np+1][1] = r3;
        }
        #pragma unroll
        for (int nt = 0; nt < 8; nt++)
            asm volatile(
                "mma.sync.aligned.m16n8k16.row.col.f32.bf16.bf16.f32 "
                "{%0,%1,%2,%3}, {%4,%5,%6,%7}, {%8,%9}, {%0,%1,%2,%3};"
                : "+f"(acc[nt][0]), "+f"(acc[nt][1]), "+f"(acc[nt][2]), "+f"(acc[nt][3])
                : "r"(af[0]), "r"(af[1]), "r"(af[2]), "r"(af[3]),
                  "r"(bf[nt][0]), "r"(bf[nt][1]));
    }
}

// ---------------------------------------------------------------------------
// Fully-staged K=128 GEMM. CTA 64xN128-slice, 256 threads (8 warps: 4m x 2n).
// Whole A (64x128) and B (128x128) staged once; 4 MMA slabs, no mid syncs.
//   MODE 0:+bias | 1:*scale | 2:gelu | 3:+res ; OUTBF: bf16/fp32 out
//   LNFUSE: (requires MODE 3, N==128) also computes LayerNorm of the output
//           rows and writes bf16 ln to lnout (xbuf still written fp32).
// Dynamic smem: (64+128)*136*2 = 52224 B.
// ---------------------------------------------------------------------------
#define KP 136

template <int MODE, int OUTBF, int LNFUSE>
__global__ __launch_bounds__(256)
void gemm_k128(const bf16* __restrict__ A,
               const bf16* __restrict__ Wb,
               const float* __restrict__ bias,
               const float* __restrict__ res,
               void* __restrict__ Cout,
               int N, float scale,
               const float* __restrict__ lng,
               const float* __restrict__ lnb,
               bf16* __restrict__ lnout)
{
    extern __shared__ bf16 sm[];
    bf16* As = sm;              // 64*136
    bf16* Bs = sm + 64*KP;      // 128*136

    const int tid  = threadIdx.x;
    const int bm   = blockIdx.y * 64;
    const int bn   = blockIdx.x * 128;
    const int warp = tid >> 5;
    const int lane = tid & 31;
    const int g    = lane >> 2;
    const int t    = lane & 3;
    const int m_base = (warp >> 1) * 16;
    const int warpN  = warp & 1;
    const int n_base = warpN * 64;

    // stage all of A (1024 chunks) and B (2048 chunks)
    {
        const unsigned aS = s2u(As);
        #pragma unroll
        for (int i = 0; i < 4; i++) {
            int id = tid + i*256;
            int r = id >> 4, c = id & 15;
            CP_ASYNC16(aS + (r*KP + c*8)*2, A + (size_t)(bm + r)*Cc + c*8);
        }
        const unsigned bS = s2u(Bs);
        #pragma unroll
        for (int i = 0; i < 8; i++) {
            int id = tid + i*256;
            int r = id >> 4, c = id & 15;
            CP_ASYNC16(bS + (r*KP + c*8)*2, Wb + (size_t)r*N + bn + c*8);
        }
        asm volatile("cp.async.commit_group;");
    }

    float acc[8][4];
    #pragma unroll
    for (int nt = 0; nt < 8; nt++)
        #pragma unroll
        for (int e = 0; e < 4; e++) acc[nt][e] = 0.0f;

    asm volatile("cp.async.wait_group 0;");
    __syncthreads();

    const unsigned aS = s2u(As);
    const unsigned bS = s2u(Bs);
    #pragma unroll
    for (int kt = 0; kt < 4; kt++)
        gemm_tile(aS + kt*32*2, bS + (kt*32*KP)*2, m_base, n_base, lane, acc, KP, KP);

    // epilogue
    float* Cf = (float*)Cout;
    bf16*  Cb = (bf16*)Cout;
    const int row0 = bm + m_base + g;
    const int row1 = row0 + 8;

    float s0 = 0.f, q0 = 0.f, s1 = 0.f, q1 = 0.f;
    float* vsm  = (float*)Bs;             // reuse: [64][132] fp32 (33.8KB)
    float* part = (float*)As;             // reuse: [64][2] float2 -> 64*4 floats

    if (LNFUSE) __syncthreads();          // smem reads of gemm done before reuse

    #pragma unroll
    for (int nt = 0; nt < 8; nt++) {
        int col = bn + n_base + nt*8 + 2*t;
        float b0 = bias[col], b1 = bias[col+1];
        float v00 = acc[nt][0] + b0;
        float v01 = acc[nt][1] + b1;
        float v10 = acc[nt][2] + b0;
        float v11 = acc[nt][3] + b1;
        if (MODE == 1) { v00 *= scale; v01 *= scale; v10 *= scale; v11 *= scale; }
        if (MODE == 2) {
            v00 = 0.5f*v00*(1.0f + erff(v00*0.70710678118654752f));
            v01 = 0.5f*v01*(1.0f + erff(v01*0.70710678118654752f));
            v10 = 0.5f*v10*(1.0f + erff(v10*0.70710678118654752f));
            v11 = 0.5f*v11*(1.0f + erff(v11*0.70710678118654752f));
        }
        if (MODE == 3) {
            float2 r0 = *(const float2*)&res[(size_t)row0*N + col];
            float2 r1 = *(const float2*)&res[(size_t)row1*N + col];
            v00 += r0.x; v01 += r0.y; v10 += r1.x; v11 += r1.y;
        }
        if (OUTBF) {
            bf162 p0 = __float22bfloat162_rn(make_float2(v00, v01));
            bf162 p1 = __float22bfloat162_rn(make_float2(v10, v11));
            *(unsigned*)&Cb[(size_t)row0*N + col] = *(unsigned*)&p0;
            *(unsigned*)&Cb[(size_t)row1*N + col] = *(unsigned*)&p1;
        } else {
            *(float2*)&Cf[(size_t)row0*N + col] = make_float2(v00, v01);
            *(float2*)&Cf[(size_t)row1*N + col] = make_float2(v10, v11);
        }
        if (LNFUSE) {
            int lc = n_base + nt*8 + 2*t;      // 0..127
            int lr0 = m_base + g, lr1 = lr0 + 8;
            vsm[lr0*132 + lc] = v00; vsm[lr0*132 + lc + 1] = v01;
            vsm[lr1*132 + lc] = v10; vsm[lr1*132 + lc + 1] = v11;
            s0 += v00 + v01;  q0 += v00*v00 + v01*v01;
            s1 += v10 + v11;  q1 += v10*v10 + v11*v11;
        }
    }

    if (LNFUSE) {
        // quad reduce (lanes g*4+t, t=0..3 share rows)
        #pragma unroll
        for (int off = 1; off < 4; off <<= 1) {
            s0 += __shfl_xor_sync(0xffffffff, s0, off);
            q0 += __shfl_xor_sync(0xffffffff, q0, off);
            s1 += __shfl_xor_sync(0xffffffff, s1, off);
            q1 += __shfl_xor_sync(0xffffffff, q1, off);
        }
        int lr0 = m_base + g, lr1 = lr0 + 8;
        if (t == 0) {
            *(float2*)&part[(lr0*2 + warpN)*2] = make_float2(s0, q0);
            *(float2*)&part[(lr1*2 + warpN)*2] = make_float2(s1, q1);
        }
        __syncthreads();

        float2 a0 = *(float2*)&part[(lr0*2 + 0)*2];
        float2 a1 = *(float2*)&part[(lr0*2 + 1)*2];
        float2 c0 = *(float2*)&part[(lr1*2 + 0)*2];
        float2 c1 = *(float2*)&part[(lr1*2 + 1)*2];
        float m0 = (a0.x + a1.x) * (1.0f/Cc);
        float v0 = (a0.y + a1.y) * (1.0f/Cc) - m0*m0;
        float i0 = rsqrtf(v0 + 1e-5f);
        float m1 = (c0.x + c1.x) * (1.0f/Cc);
        float v1 = (c0.y + c1.y) * (1.0f/Cc) - m1*m1;
        float i1 = rsqrtf(v1 + 1e-5f);

        #pragma unroll
        for (int nt = 0; nt < 8; nt++) {
            int lc  = n_base + nt*8 + 2*t;
            int col = bn + lc;
            float gg0 = lng[col], gg1b = lng[col+1];
            float bb0 = lnb[col], bb1 = lnb[col+1];
            float x00 = vsm[lr0*132 + lc], x01 = vsm[lr0*132 + lc + 1];
            float x10 = vsm[lr1*132 + lc], x11 = vsm[lr1*132 + lc + 1];
            bf162 p0 = __float22bfloat162_rn(make_float2((x00-m0)*i0*gg0 + bb0,
                                                         (x01-m0)*i0*gg1b + bb1));
            bf162 p1 = __float22bfloat162_rn(make_float2((x10-m1)*i1*gg0 + bb0,
                                                         (x11-m1)*i1*gg1b + bb1));
            *(unsigned*)&lnout[(size_t)row0*N + col] = *(unsigned*)&p0;
            *(unsigned*)&lnout[(size_t)row1*N + col] = *(unsigned*)&p1;
        }
    }
}

// ---------------------------------------------------------------------------
// Fused Q + KV projection, fully staged (K=128). blockIdx.x: 0 -> Q, 1..2 -> KV.
// ---------------------------------------------------------------------------
__global__ __launch_bounds__(256)
void qkv_k128(const bf16* __restrict__ qn, const bf16* __restrict__ kvn,
              const float* __restrict__ bq, const float* __restrict__ bkv,
              bf16* __restrict__ qout, bf16* __restrict__ kvout)
{
    extern __shared__ bf16 sm[];
    bf16* As = sm;
    bf16* Bs = sm + 64*KP;

    const int cb = blockIdx.x;
    const bool isQ = (cb == 0);
    const bf16*  A    = isQ ? qn : kvn;
    const bf16*  Wb   = isQ ? g_wq : g_wkv;
    const float* bias = isQ ? bq : bkv;
    bf16*        Cb   = isQ ? qout : kvout;
    const int N  = isQ ? Cc : 2*Cc;
    const int bn = isQ ? 0 : (cb - 1) * 128;

    const int tid  = threadIdx.x;
    const int bm   = blockIdx.y * 64;
    const int warp = tid >> 5;
    const int lane = tid & 31;
    const int g    = lane >> 2;
    const int t    = lane & 3;
    const int m_base = (warp >> 1) * 16;
    const int n_base = (warp & 1) * 64;

    {
        const unsigned aS = s2u(As);
        #pragma unroll
        for (int i = 0; i < 4; i++) {
            int id = tid + i*256;
            int r = id >> 4, c = id & 15;
            CP_ASYNC16(aS + (r*KP + c*8)*2, A + (size_t)(bm + r)*Cc + c*8);
        }
        const unsigned bS = s2u(Bs);
        #pragma unroll
        for (int i = 0; i < 8; i++) {
            int id = tid + i*256;
            int r = id >> 4, c = id & 15;
            CP_ASYNC16(bS + (r*KP + c*8)*2, Wb + (size_t)r*N + bn + c*8);
        }
        asm volatile("cp.async.commit_group;");
    }

    float acc[8][4];
    #pragma unroll
    for (int nt = 0; nt < 8; nt++)
        #pragma unroll
        for (int e = 0; e < 4; e++) acc[nt][e] = 0.0f;

    asm volatile("cp.async.wait_group 0;");
    __syncthreads();

    const unsigned aS = s2u(As);
    const unsigned bS = s2u(Bs);
    #pragma unroll
    for (int kt = 0; kt < 4; kt++)
        gemm_tile(aS + kt*32*2, bS + (kt*32*KP)*2, m_base, n_base, lane, acc, KP, KP);

    const float scale = 0.17677669529663689f;
    int row0 = bm + m_base + g;
    int row1 = row0 + 8;
    #pragma unroll
    for (int nt = 0; nt < 8; nt++) {
        int col = bn + n_base + nt*8 + 2*t;
        float b0 = bias[col], b1 = bias[col+1];
        float v00 = acc[nt][0] + b0;
        float v01 = acc[nt][1] + b1;
        float v10 = acc[nt][2] + b0;
        float v11 = acc[nt][3] + b1;
        if (isQ) { v00 *= scale; v01 *= scale; v10 *= scale; v11 *= scale; }
        bf162 p0 = __float22bfloat162_rn(make_float2(v00, v01));
        bf162 p1 = __float22bfloat162_rn(make_float2(v10, v11));
        *(unsigned*)&Cb[(size_t)row0*N + col] = *(unsigned*)&p0;
        *(unsigned*)&Cb[(size_t)row1*N + col] = *(unsigned*)&p1;
    }
}

// ---------------------------------------------------------------------------
// Ring-pipelined GEMM for K=512 (MLP second layer). Same warp layout.
// ---------------------------------------------------------------------------
#define APITCH 40
#define BPITCH 136
#define NSTAGE 3

template <int MODE, int OUTBF>
__global__ __launch_bounds__(256)
void gemm_bf(const bf16* __restrict__ A,
             const bf16* __restrict__ Wb,
             const float* __restrict__ bias,
             const float* __restrict__ res,
             void* __restrict__ Cout,
             int M, int N, int K, float scale)
{
    __shared__ bf16 As[NSTAGE][64*APITCH];
    __shared__ bf16 Bs[NSTAGE][32*BPITCH];

    const int tid  = threadIdx.x;
    const int bm   = blockIdx.y * 64;
    const int bn   = blockIdx.x * 128;
    const int warp = tid >> 5;
    const int lane = tid & 31;
    const int g    = lane >> 2;
    const int t    = lane & 3;
    const int m_base = (warp >> 1) * 16;
    const int n_base = (warp & 1) * 64;

    const int a_r = tid >> 2, a_c = tid & 3;
    const int b_r0 = tid >> 4, b_c = tid & 15;
    const int b_r1 = b_r0 + 16;

    const bf16* Ag = A  + (size_t)bm * K;
    const bf16* Bg = Wb + bn;

    const unsigned aS = s2u(&As[0][0]);
    const unsigned bS = s2u(&Bs[0][0]);
    const unsigned aBufSz = 64*APITCH*2;
    const unsigned bBufSz = 32*BPITCH*2;
    const unsigned ad = aS + (a_r*APITCH + a_c*8)*2;
    const unsigned bd0 = bS + (b_r0*BPITCH + b_c*8)*2;
    const unsigned bd1 = bS + (b_r1*BPITCH + b_c*8)*2;

    float acc[8][4];
    #pragma unroll
    for (int nt = 0; nt < 8; nt++)
        #pragma unroll
        for (int e = 0; e < 4; e++) acc[nt][e] = 0.0f;

    const int ntile = K / 32;

    auto stage = [&](int buf, int kt) {
        CP_ASYNC16(ad  + buf*aBufSz, Ag + (size_t)a_r*K + kt*32 + a_c*8);
        CP_ASYNC16(bd0 + buf*bBufSz, Bg + (size_t)(kt*32 + b_r0)*N + b_c*8);
        CP_ASYNC16(bd1 + buf*bBufSz, Bg + (size_t)(kt*32 + b_r1)*N + b_c*8);
        asm volatile("cp.async.commit_group;");
    };

    stage(0, 0);
    if (ntile > 1) stage(1, 1);

    for (int kt = 0; kt < ntile; kt++) {
        if (kt + 1 < ntile) asm volatile("cp.async.wait_group 1;");
        else                asm volatile("cp.async.wait_group 0;");
        __syncthreads();
        if (kt + 2 < ntile) stage((kt + 2) % NSTAGE, kt + 2);
        const int cur = kt % NSTAGE;
        gemm_tile(aS + cur*aBufSz, bS + cur*bBufSz, m_base, n_base, lane, acc,
                  APITCH, BPITCH);
        __syncthreads();
    }

    float* Cf = (float*)Cout;
    bf16*  Cb = (bf16*)Cout;
    int row0 = bm + m_base + g;
    int row1 = row0 + 8;
    #pragma unroll
    for (int nt = 0; nt < 8; nt++) {
        int col = bn + n_base + nt*8 + 2*t;
        float b0 = bias[col], b1 = bias[col+1];
        float v00 = acc[nt][0] + b0;
        float v01 = acc[nt][1] + b1;
        float v10 = acc[nt][2] + b0;
        float v11 = acc[nt][3] + b1;
        if (MODE == 1) { v00 *= scale; v01 *= scale; v10 *= scale; v11 *= scale; }
        if (MODE == 2) {
            v00 = 0.5f*v00*(1.0f + erff(v00*0.70710678118654752f));
            v01 = 0.5f*v01*(1.0f + erff(v01*0.70710678118654752f));
            v10 = 0.5f*v10*(1.0f + erff(v10*0.70710678118654752f));
            v11 = 0.5f*v11*(1.0f + erff(v11*0.70710678118654752f));
        }
        if (MODE == 3) {
            float2 r0 = *(const float2*)&res[(size_t)row0*N + col];
            float2 r1 = *(const float2*)&res[(size_t)row1*N + col];
            v00 += r0.x; v01 += r0.y; v10 += r1.x; v11 += r1.y;
        }
        if (OUTBF) {
            bf162 p0 = __float22bfloat162_rn(make_float2(v00, v01));
            bf162 p1 = __float22bfloat162_rn(make_float2(v10, v11));
            *(unsigned*)&Cb[(size_t)row0*N + col] = *(unsigned*)&p0;
            *(unsigned*)&Cb[(size_t)row1*N + col] = *(unsigned*)&p1;
        } else {
            *(float2*)&Cf[(size_t)row0*N + col] = make_float2(v00, v01);
            *(float2*)&Cf[(size_t)row1*N + col] = make_float2(v10, v11);
        }
    }
}

// ---------------------------------------------------------------------------
// Neighborhood attention v3: one block = 8x4 query tile x ONE head.
// ---------------------------------------------------------------------------
#define PR 14
#define PC 10
#define PTOK 140
#define DPAD 40

__global__ __launch_bounds__(256)
void nat_attn3(const bf16* __restrict__ q,
               const bf16* __restrict__ kv,
               const float* __restrict__ rpb,
               bf16* __restrict__ out)
{
    __shared__ bf16 Ks[PTOK*DPAD];
    __shared__ bf16 Vs[PTOK*DPAD];
    __shared__ float rs[169];

    const int blk = blockIdx.x;
    const int h   = blk & 3;
    const int r2  = blk >> 2;
    const int b   = r2 >> 7;
    const int rem = r2 & 127;
    const int it  = (rem >> 4) << 3;
    const int jt  = (rem & 15) << 2;

    int ip0 = it - 3; if (ip0 < 0) ip0 = 0; if (ip0 > Hh - PR) ip0 = Hh - PR;
    int jp0 = jt - 3; if (jp0 < 0) jp0 = 0; if (jp0 > Ww - PC) jp0 = Ww - PC;

    const int tid  = threadIdx.x;
    const int base = b * (Hh*Ww);

    const uint4* kv4 = (const uint4*)kv;
    for (int f = tid; f < PTOK*8; f += 256) {
        int tok = f >> 3;
        int c   = f & 7;
        int r   = tok / PC;
        int cc  = tok - r*PC;
        int g   = base + (ip0 + r)*Ww + (jp0 + cc);
        if (c < 4) {
            *(uint4*)&Ks[tok*DPAD + c*8] = kv4[(size_t)g*32 + h*4 + c];
        } else {
            int c2 = c - 4;
            *(uint4*)&Vs[tok*DPAD + c2*8] = kv4[(size_t)g*32 + 16 + h*4 + c2];
        }
    }
    for (int f = tid; f < 169; f += 256) rs[f] = rpb[h*169 + f];
    __syncthreads();

    const int w    = tid >> 5;
    const int lane = tid & 31;
    const uint4* qb4 = (const uint4*)q;

    #pragma unroll
    for (int s = 0; s < 4; s++) {
        const int qq = w*4 + s;
        const int qi = qq >> 2, qj = qq & 3;
        const int gi = it + qi, gj = jt + qj;
        int i0 = gi - 3; if (i0 < 0) i0 = 0; if (i0 > Hh - Kk) i0 = Hh - Kk;
        int j0 = gj - 3; if (j0 < 0) j0 = 0; if (j0 > Ww - Kk) j0 = Ww - Kk;
        const int ioff = i0 - ip0;
        const int joff = j0 - jp0;
        const int g = base + gi*Ww + gj;

        float qf[32];
        #pragma unroll
        for (int u = 0; u < 4; u++) {
            uint4 v = qb4[(size_t)g*16 + h*4 + u];
            float2 f0 = __bfloat1622float2(*(const bf162*)&v.x);
            float2 f1 = __bfloat1622float2(*(const bf162*)&v.y);
            float2 f2 = __bfloat1622float2(*(const bf162*)&v.z);
            float2 f3 = __bfloat1622float2(*(const bf162*)&v.w);
            qf[u*8+0]=f0.x; qf[u*8+1]=f0.y; qf[u*8+2]=f1.x; qf[u*8+3]=f1.y;
            qf[u*8+4]=f2.x; qf[u*8+5]=f2.y; qf[u*8+6]=f3.x; qf[u*8+7]=f3.y;
        }

        float sc[2];
        #pragma unroll
        for (int r = 0; r < 2; r++) {
            int n = r*32 + lane;
            float val = -INFINITY;
            if (n < 49) {
                int ni = n / 7;
                int nj = n - ni*7;
                int lt = (ioff + ni)*PC + joff + nj;
                const uint4* kp = (const uint4*)&Ks[lt*DPAD];
                float a0 = 0.f;
                #pragma unroll
                for (int u = 0; u < 4; u++) {
                    uint4 kk4 = kp[u];
                    float2 f0 = __bfloat1622float2(*(const bf162*)&kk4.x);
                    float2 f1 = __bfloat1622float2(*(const bf162*)&kk4.y);
                    float2 f2 = __bfloat1622float2(*(const bf162*)&kk4.z);
                    float2 f3 = __bfloat1622float2(*(const bf162*)&kk4.w);
                    a0 = fmaf(qf[u*8+0], f0.x, a0);
                    a0 = fmaf(qf[u*8+1], f0.y, a0);
                    a0 = fmaf(qf[u*8+2], f1.x, a0);
                    a0 = fmaf(qf[u*8+3], f1.y, a0);
                    a0 = fmaf(qf[u*8+4], f2.x, a0);
                    a0 = fmaf(qf[u*8+5], f2.y, a0);
                    a0 = fmaf(qf[u*8+6], f3.x, a0);
                    a0 = fmaf(qf[u*8+7], f3.y, a0);
                }
                int ri = i0 + ni - gi + (Kk - 1);
                int rj = j0 + nj - gj + (Kk - 1);
                val = a0 + rs[ri*13 + rj];
            }
            sc[r] = val;
        }

        float mx = fmaxf(sc[0], sc[1]);
        #pragma unroll
        for (int off = 16; off; off >>= 1)
            mx = fmaxf(mx, __shfl_xor_sync(0xffffffff, mx, off));
        float e0 = __expf(sc[0] - mx);
        float e1 = __expf(sc[1] - mx);
        float sum = e0 + e1;
        #pragma unroll
        for (int off = 16; off; off >>= 1)
            sum += __shfl_xor_sync(0xffffffff, sum, off);
        float rinv = 1.0f / sum;
        float p0 = e0 * rinv;
        float p1 = e1 * rinv;

        float o = 0.0f;
        #pragma unroll
        for (int n = 0; n < 49; n++) {
            float pn = (n < 32) ? __shfl_sync(0xffffffff, p0, n)
                                : __shfl_sync(0xffffffff, p1, n - 32);
            int ni = n / 7;
            int nj = n - ni*7;
            int lt = (ioff + ni)*PC + joff + nj;
            float vv = __bfloat162float(Vs[lt*DPAD + lane]);
            o = fmaf(pn, vv, o);
        }
        out[(size_t)g*Cc + h*32 + lane] = __float2bfloat16(o);
    }
}

// ---------------------------------------------------------------------------
// Launch
// ---------------------------------------------------------------------------
extern "C" void kernel_launch(void* const* d_in, const int* in_sizes, int n_in,
                              void* d_out, int out_size)
{
    const float* query     = (const float*)d_in[0];
    const float* key_value = (const float*)d_in[1];
    const float* g1  = (const float*)d_in[2];
    const float* b1  = (const float*)d_in[3];
    const float* g2  = (const float*)d_in[4];
    const float* b2  = (const float*)d_in[5];
    const float* g3  = (const float*)d_in[6];
    const float* b3  = (const float*)d_in[7];
    const float* Wq  = (const float*)d_in[8];
    const float* bq  = (const float*)d_in[9];
    const float* Wkv = (const float*)d_in[10];
    const float* bkv = (const float*)d_in[11];
    const float* Wp  = (const float*)d_in[12];
    const float* bp  = (const float*)d_in[13];
    const float* rpb = (const float*)d_in[14];
    const float* W1  = (const float*)d_in[15];
    const float* bm1 = (const float*)d_in[16];
    const float* W2  = (const float*)d_in[17];
    const float* bm2 = (const float*)d_in[18];
    float* out = (float*)d_out;

    bf16*  qn     = nullptr; cudaGetSymbolAddress((void**)&qn,     g_qn);
    bf16*  kvn    = nullptr; cudaGetSymbolAddress((void**)&kvn,    g_kvn);
    bf16*  qbuf   = nullptr; cudaGetSymbolAddress((void**)&qbuf,   g_q);
    bf16*  kvbuf  = nullptr; cudaGetSymbolAddress((void**)&kvbuf,  g_kv);
    bf16*  attn   = nullptr; cudaGetSymbolAddress((void**)&attn,   g_attn);
    float* xbuf   = nullptr; cudaGetSymbolAddress((void**)&xbuf,   g_x);
    bf16*  hln    = nullptr; cudaGetSymbolAddress((void**)&hln,    g_hln);
    bf16*  hidden = nullptr; cudaGetSymbolAddress((void**)&hidden, g_hidden);
    bf16*  wpb    = nullptr; cudaGetSymbolAddress((void**)&wpb,    g_wp);
    bf16*  w1b    = nullptr; cudaGetSymbolAddress((void**)&w1b,    g_w1);
    bf16*  w2b    = nullptr; cudaGetSymbolAddress((void**)&w2b,    g_w2);

    const int k128_smem = (64 + 128) * KP * 2;   // 52224 B

    static bool attr_set = false;
    if (!attr_set) {
        cudaFuncSetAttribute(qkv_k128,
                             cudaFuncAttributeMaxDynamicSharedMemorySize, k128_smem);
        cudaFuncSetAttribute(gemm_k128<3,0,1>,
                             cudaFuncAttributeMaxDynamicSharedMemorySize, k128_smem);
        cudaFuncSetAttribute(gemm_k128<2,1,0>,
                             cudaFuncAttributeMaxDynamicSharedMemorySize, k128_smem);
        attr_set = true;
    }

    // 0) weight conversion
    cvt_weights<<<192, 256>>>(Wq, Wkv, Wp, W1, W2);

    // 1) LN1 + LN2 fused launch
    ln_dual<<<(2*NTOK*32)/256, 256>>>(query, g1, b1, qn, key_value, g2, b2, kvn);

    // 2) Fused Q + KV projections (fully staged K=128)
    qkv_k128<<<dim3(3, NTOK/64), 256, k128_smem>>>(qn, kvn, bq, bkv, qbuf, kvbuf);

    // 3) Neighborhood attention
    nat_attn3<<<Bq*(Hh/8)*(Ww/4)*NHh, 256>>>(qbuf, kvbuf, rpb, attn);

    // 4) Output projection + residual + fused LN3 (xbuf fp32 + hln bf16)
    gemm_k128<3,0,1><<<dim3(1, NTOK/64), 256, k128_smem>>>(
        attn, wpb, bp, key_value, xbuf, Cc, 1.0f, g3, b3, hln);

    // 5) MLP
    gemm_k128<2,1,0><<<dim3(MLPD/128, NTOK/64), 256, k128_smem>>>(
        hln, w1b, bm1, nullptr, hidden, MLPD, 1.0f, nullptr, nullptr, nullptr);
    gemm_bf<3,0><<<dim3(Cc/128, NTOK/64), 256>>>(
        hidden, w2b, bm2, xbuf, out, NTOK, Cc, MLPD, 1.0f);
}

// round 12
// speedup vs baseline: 1.8304x; 1.1922x over previous
#include <cuda_runtime.h>
#include <cuda_bf16.h>
#include <math.h>

// Problem constants
#define Bq  4
#define Hh  64
#define Ww  64
#define Cc  128
#define NHh 4
#define Kk  7
#define HDd 32
#define MLPD 512
#define NTOK (Bq*Hh*Ww)   // 16384

typedef __nv_bfloat16  bf16;
typedef __nv_bfloat162 bf162;

// Scratch (device globals)
__device__ __align__(16) bf16  g_qn    [NTOK*Cc];
__device__ __align__(16) bf16  g_kvn   [NTOK*Cc];
__device__ __align__(16) bf16  g_q     [NTOK*Cc];
__device__ __align__(16) bf16  g_kv    [NTOK*2*Cc];
__device__ __align__(16) bf16  g_attn  [NTOK*Cc];
__device__ __align__(16) float g_x     [NTOK*Cc];
__device__ __align__(16) bf16  g_hln   [NTOK*Cc];
__device__ __align__(16) bf16  g_hidden[NTOK*MLPD];

// bf16 weights (converted once per launch)
__device__ __align__(16) bf16  g_wq [Cc*Cc];
__device__ __align__(16) bf16  g_wkv[Cc*2*Cc];
__device__ __align__(16) bf16  g_wp [Cc*Cc];
__device__ __align__(16) bf16  g_w1 [Cc*MLPD];
__device__ __align__(16) bf16  g_w2 [MLPD*Cc];

__device__ __forceinline__ unsigned s2u(const void* p) {
    return (unsigned)__cvta_generic_to_shared(p);
}

#define CP_ASYNC16(dst, src) \
    asm volatile("cp.async.ca.shared.global [%0], [%1], 16;" :: "r"(dst), "l"(src))

// ---------------------------------------------------------------------------
// Weight conversion fp32 -> bf16
// ---------------------------------------------------------------------------
__global__ void cvt_weights(const float* __restrict__ Wq,
                            const float* __restrict__ Wkv,
                            const float* __restrict__ Wp,
                            const float* __restrict__ W1,
                            const float* __restrict__ W2)
{
    int i = blockIdx.x * blockDim.x + threadIdx.x;   // 0..49151
    const float* src; bf16* dst; int off;
    if      (i < 4096)  { src = Wq;  dst = g_wq;  off = i; }
    else if (i < 12288) { src = Wkv; dst = g_wkv; off = i - 4096; }
    else if (i < 16384) { src = Wp;  dst = g_wp;  off = i - 12288; }
    else if (i < 32768) { src = W1;  dst = g_w1;  off = i - 16384; }
    else                { src = W2;  dst = g_w2;  off = i - 32768; }
    float4 v = ((const float4*)src)[off];
    bf162 lo = __float22bfloat162_rn(make_float2(v.x, v.y));
    bf162 hi = __float22bfloat162_rn(make_float2(v.z, v.w));
    uint2 pk; pk.x = *(unsigned*)&lo; pk.y = *(unsigned*)&hi;
    ((uint2*)dst)[off] = pk;
}

// ---------------------------------------------------------------------------
// Dual LayerNorm: warps [0,NTOK) -> LN(query), [NTOK,2*NTOK) -> LN(key_value)
// ---------------------------------------------------------------------------
__global__ void ln_dual(const float* __restrict__ in1, const float* __restrict__ gg1,
                        const float* __restrict__ bb1, bf16* __restrict__ out1,
                        const float* __restrict__ in2, const float* __restrict__ gg2,
                        const float* __restrict__ bb2, bf16* __restrict__ out2)
{
    int w    = (blockIdx.x * blockDim.x + threadIdx.x) >> 5;
    int lane = threadIdx.x & 31;
    const float* in; const float* g; const float* b; bf16* out; int tok;
    if (w < NTOK) { in = in1; g = gg1; b = bb1; out = out1; tok = w; }
    else          { in = in2; g = gg2; b = bb2; out = out2; tok = w - NTOK; }

    const float4 v = *(const float4*)&in[(size_t)tok*Cc + lane*4];
    float s  = v.x + v.y + v.z + v.w;
    float sq = v.x*v.x + v.y*v.y + v.z*v.z + v.w*v.w;
    #pragma unroll
    for (int off = 16; off; off >>= 1) {
        s  += __shfl_xor_sync(0xffffffff, s,  off);
        sq += __shfl_xor_sync(0xffffffff, sq, off);
    }
    float mean = s * (1.0f/Cc);
    float var  = sq * (1.0f/Cc) - mean*mean;
    float inv  = rsqrtf(var + 1e-5f);

    const float4 gv = *(const float4*)&g[lane*4];
    const float4 bv = *(const float4*)&b[lane*4];
    bf162 o0 = __float22bfloat162_rn(make_float2((v.x-mean)*inv*gv.x + bv.x,
                                                 (v.y-mean)*inv*gv.y + bv.y));
    bf162 o1 = __float22bfloat162_rn(make_float2((v.z-mean)*inv*gv.z + bv.z,
                                                 (v.w-mean)*inv*gv.w + bv.w));
    uint2 pk; pk.x = *(unsigned*)&o0; pk.y = *(unsigned*)&o1;
    *(uint2*)&out[(size_t)tok*Cc + lane*4] = pk;
}

// ---------------------------------------------------------------------------
// MMA tile helper: one BK=32 slab. apitch/bpitch in bf16 elements.
// ---------------------------------------------------------------------------
__device__ __forceinline__ void gemm_tile(
    unsigned aB, unsigned bB, int m_base, int n_base, int lane,
    float acc[8][4], int apitch, int bpitch)
{
    const int a_row_sel = lane & 15;
    const int a_k_sel   = (lane >> 4) << 3;
    const int b_k_sel   = (lane & 7) + (((lane >> 3) & 1) << 3);
    const int b_n_sel   = (lane >> 4) << 3;
    #pragma unroll
    for (int kk = 0; kk < 32; kk += 16) {
        unsigned af[4], bf[8][2];
        {
            unsigned addr = aB + ((m_base + a_row_sel)*apitch + kk + a_k_sel)*2;
            asm volatile("ldmatrix.sync.aligned.m8n8.x4.shared.b16 {%0,%1,%2,%3}, [%4];"
                : "=r"(af[0]), "=r"(af[1]), "=r"(af[2]), "=r"(af[3]) : "r"(addr));
        }
        #pragma unroll
        for (int np = 0; np < 4; np++) {
            unsigned r0, r1, r2, r3;
            unsigned addr = bB + ((kk + b_k_sel)*bpitch + n_base + np*16 + b_n_sel)*2;
            asm volatile("ldmatrix.sync.aligned.m8n8.x4.trans.shared.b16 {%0,%1,%2,%3}, [%4];"
                : "=r"(r0), "=r"(r1), "=r"(r2), "=r"(r3) : "r"(addr));
            bf[2*np  ][0] = r0; bf[2*np  ][1] = r1;
            bf[2*np+1][0] = r2; bf[2*np+1][1] = r3;
        }
        #pragma unroll
        for (int nt = 0; nt < 8; nt++)
            asm volatile(
                "mma.sync.aligned.m16n8k16.row.col.f32.bf16.bf16.f32 "
                "{%0,%1,%2,%3}, {%4,%5,%6,%7}, {%8,%9}, {%0,%1,%2,%3};"
                : "+f"(acc[nt][0]), "+f"(acc[nt][1]), "+f"(acc[nt][2]), "+f"(acc[nt][3])
                : "r"(af[0]), "r"(af[1]), "r"(af[2]), "r"(af[3]),
                  "r"(bf[nt][0]), "r"(bf[nt][1]));
    }
}

// ---------------------------------------------------------------------------
// Fully-staged K=128 GEMM (same as round 11).
// ---------------------------------------------------------------------------
#define KP 136

template <int MODE, int OUTBF, int LNFUSE>
__global__ __launch_bounds__(256)
void gemm_k128(const bf16* __restrict__ A,
               const bf16* __restrict__ Wb,
               const float* __restrict__ bias,
               const float* __restrict__ res,
               void* __restrict__ Cout,
               int N, float scale,
               const float* __restrict__ lng,
               const float* __restrict__ lnb,
               bf16* __restrict__ lnout)
{
    extern __shared__ bf16 sm[];
    bf16* As = sm;
    bf16* Bs = sm + 64*KP;

    const int tid  = threadIdx.x;
    const int bm   = blockIdx.y * 64;
    const int bn   = blockIdx.x * 128;
    const int warp = tid >> 5;
    const int lane = tid & 31;
    const int g    = lane >> 2;
    const int t    = lane & 3;
    const int m_base = (warp >> 1) * 16;
    const int warpN  = warp & 1;
    const int n_base = warpN * 64;

    {
        const unsigned aS = s2u(As);
        #pragma unroll
        for (int i = 0; i < 4; i++) {
            int id = tid + i*256;
            int r = id >> 4, c = id & 15;
            CP_ASYNC16(aS + (r*KP + c*8)*2, A + (size_t)(bm + r)*Cc + c*8);
        }
        const unsigned bS = s2u(Bs);
        #pragma unroll
        for (int i = 0; i < 8; i++) {
            int id = tid + i*256;
            int r = id >> 4, c = id & 15;
            CP_ASYNC16(bS + (r*KP + c*8)*2, Wb + (size_t)r*N + bn + c*8);
        }
        asm volatile("cp.async.commit_group;");
    }

    float acc[8][4];
    #pragma unroll
    for (int nt = 0; nt < 8; nt++)
        #pragma unroll
        for (int e = 0; e < 4; e++) acc[nt][e] = 0.0f;

    asm volatile("cp.async.wait_group 0;");
    __syncthreads();

    const unsigned aS = s2u(As);
    const unsigned bS = s2u(Bs);
    #pragma unroll
    for (int kt = 0; kt < 4; kt++)
        gemm_tile(aS + kt*32*2, bS + (kt*32*KP)*2, m_base, n_base, lane, acc, KP, KP);

    float* Cf = (float*)Cout;
    bf16*  Cb = (bf16*)Cout;
    const int row0 = bm + m_base + g;
    const int row1 = row0 + 8;

    float s0 = 0.f, q0 = 0.f, s1 = 0.f, q1 = 0.f;
    float* vsm  = (float*)Bs;
    float* part = (float*)As;

    if (LNFUSE) __syncthreads();

    #pragma unroll
    for (int nt = 0; nt < 8; nt++) {
        int col = bn + n_base + nt*8 + 2*t;
        float b0 = bias[col], b1 = bias[col+1];
        float v00 = acc[nt][0] + b0;
        float v01 = acc[nt][1] + b1;
        float v10 = acc[nt][2] + b0;
        float v11 = acc[nt][3] + b1;
        if (MODE == 1) { v00 *= scale; v01 *= scale; v10 *= scale; v11 *= scale; }
        if (MODE == 2) {
            v00 = 0.5f*v00*(1.0f + erff(v00*0.70710678118654752f));
            v01 = 0.5f*v01*(1.0f + erff(v01*0.70710678118654752f));
            v10 = 0.5f*v10*(1.0f + erff(v10*0.70710678118654752f));
            v11 = 0.5f*v11*(1.0f + erff(v11*0.70710678118654752f));
        }
        if (MODE == 3) {
            float2 r0 = *(const float2*)&res[(size_t)row0*N + col];
            float2 r1 = *(const float2*)&res[(size_t)row1*N + col];
            v00 += r0.x; v01 += r0.y; v10 += r1.x; v11 += r1.y;
        }
        if (OUTBF) {
            bf162 p0 = __float22bfloat162_rn(make_float2(v00, v01));
            bf162 p1 = __float22bfloat162_rn(make_float2(v10, v11));
            *(unsigned*)&Cb[(size_t)row0*N + col] = *(unsigned*)&p0;
            *(unsigned*)&Cb[(size_t)row1*N + col] = *(unsigned*)&p1;
        } else {
            *(float2*)&Cf[(size_t)row0*N + col] = make_float2(v00, v01);
            *(float2*)&Cf[(size_t)row1*N + col] = make_float2(v10, v11);
        }
        if (LNFUSE) {
            int lc = n_base + nt*8 + 2*t;
            int lr0 = m_base + g, lr1 = lr0 + 8;
            vsm[lr0*132 + lc] = v00; vsm[lr0*132 + lc + 1] = v01;
            vsm[lr1*132 + lc] = v10; vsm[lr1*132 + lc + 1] = v11;
            s0 += v00 + v01;  q0 += v00*v00 + v01*v01;
            s1 += v10 + v11;  q1 += v10*v10 + v11*v11;
        }
    }

    if (LNFUSE) {
        #pragma unroll
        for (int off = 1; off < 4; off <<= 1) {
            s0 += __shfl_xor_sync(0xffffffff, s0, off);
            q0 += __shfl_xor_sync(0xffffffff, q0, off);
            s1 += __shfl_xor_sync(0xffffffff, s1, off);
            q1 += __shfl_xor_sync(0xffffffff, q1, off);
        }
        int lr0 = m_base + g, lr1 = lr0 + 8;
        if (t == 0) {
            *(float2*)&part[(lr0*2 + warpN)*2] = make_float2(s0, q0);
            *(float2*)&part[(lr1*2 + warpN)*2] = make_float2(s1, q1);
        }
        __syncthreads();

        float2 a0 = *(float2*)&part[(lr0*2 + 0)*2];
        float2 a1 = *(float2*)&part[(lr0*2 + 1)*2];
        float2 c0 = *(float2*)&part[(lr1*2 + 0)*2];
        float2 c1 = *(float2*)&part[(lr1*2 + 1)*2];
        float m0 = (a0.x + a1.x) * (1.0f/Cc);
        float v0 = (a0.y + a1.y) * (1.0f/Cc) - m0*m0;
        float i0 = rsqrtf(v0 + 1e-5f);
        float m1 = (c0.x + c1.x) * (1.0f/Cc);
        float v1 = (c0.y + c1.y) * (1.0f/Cc) - m1*m1;
        float i1 = rsqrtf(v1 + 1e-5f);

        #pragma unroll
        for (int nt = 0; nt < 8; nt++) {
            int lc  = n_base + nt*8 + 2*t;
            int col = bn + lc;
            float gg0 = lng[col], gg1b = lng[col+1];
            float bb0 = lnb[col], bb1 = lnb[col+1];
            float x00 = vsm[lr0*132 + lc], x01 = vsm[lr0*132 + lc + 1];
            float x10 = vsm[lr1*132 + lc], x11 = vsm[lr1*132 + lc + 1];
            bf162 p0 = __float22bfloat162_rn(make_float2((x00-m0)*i0*gg0 + bb0,
                                                         (x01-m0)*i0*gg1b + bb1));
            bf162 p1 = __float22bfloat162_rn(make_float2((x10-m1)*i1*gg0 + bb0,
                                                         (x11-m1)*i1*gg1b + bb1));
            *(unsigned*)&lnout[(size_t)row0*N + col] = *(unsigned*)&p0;
            *(unsigned*)&lnout[(size_t)row1*N + col] = *(unsigned*)&p1;
        }
    }
}

// ---------------------------------------------------------------------------
// Fused Q + KV projection, fully staged (K=128).
// ---------------------------------------------------------------------------
__global__ __launch_bounds__(256)
void qkv_k128(const bf16* __restrict__ qn, const bf16* __restrict__ kvn,
              const float* __restrict__ bq, const float* __restrict__ bkv,
              bf16* __restrict__ qout, bf16* __restrict__ kvout)
{
    extern __shared__ bf16 sm[];
    bf16* As = sm;
    bf16* Bs = sm + 64*KP;

    const int cb = blockIdx.x;
    const bool isQ = (cb == 0);
    const bf16*  A    = isQ ? qn : kvn;
    const bf16*  Wb   = isQ ? g_wq : g_wkv;
    const float* bias = isQ ? bq : bkv;
    bf16*        Cb   = isQ ? qout : kvout;
    const int N  = isQ ? Cc : 2*Cc;
    const int bn = isQ ? 0 : (cb - 1) * 128;

    const int tid  = threadIdx.x;
    const int bm   = blockIdx.y * 64;
    const int warp = tid >> 5;
    const int lane = tid & 31;
    const int g    = lane >> 2;
    const int t    = lane & 3;
    const int m_base = (warp >> 1) * 16;
    const int n_base = (warp & 1) * 64;

    {
        const unsigned aS = s2u(As);
        #pragma unroll
        for (int i = 0; i < 4; i++) {
            int id = tid + i*256;
            int r = id >> 4, c = id & 15;
            CP_ASYNC16(aS + (r*KP + c*8)*2, A + (size_t)(bm + r)*Cc + c*8);
        }
        const unsigned bS = s2u(Bs);
        #pragma unroll
        for (int i = 0; i < 8; i++) {
            int id = tid + i*256;
            int r = id >> 4, c = id & 15;
            CP_ASYNC16(bS + (r*KP + c*8)*2, Wb + (size_t)r*N + bn + c*8);
        }
        asm volatile("cp.async.commit_group;");
    }

    float acc[8][4];
    #pragma unroll
    for (int nt = 0; nt < 8; nt++)
        #pragma unroll
        for (int e = 0; e < 4; e++) acc[nt][e] = 0.0f;

    asm volatile("cp.async.wait_group 0;");
    __syncthreads();

    const unsigned aS = s2u(As);
    const unsigned bS = s2u(Bs);
    #pragma unroll
    for (int kt = 0; kt < 4; kt++)
        gemm_tile(aS + kt*32*2, bS + (kt*32*KP)*2, m_base, n_base, lane, acc, KP, KP);

    const float scale = 0.17677669529663689f;
    int row0 = bm + m_base + g;
    int row1 = row0 + 8;
    #pragma unroll
    for (int nt = 0; nt < 8; nt++) {
        int col = bn + n_base + nt*8 + 2*t;
        float b0 = bias[col], b1 = bias[col+1];
        float v00 = acc[nt][0] + b0;
        float v01 = acc[nt][1] + b1;
        float v10 = acc[nt][2] + b0;
        float v11 = acc[nt][3] + b1;
        if (isQ) { v00 *= scale; v01 *= scale; v10 *= scale; v11 *= scale; }
        bf162 p0 = __float22bfloat162_rn(make_float2(v00, v01));
        bf162 p1 = __float22bfloat162_rn(make_float2(v10, v11));
        *(unsigned*)&Cb[(size_t)row0*N + col] = *(unsigned*)&p0;
        *(unsigned*)&Cb[(size_t)row1*N + col] = *(unsigned*)&p1;
    }
}

// ---------------------------------------------------------------------------
// Ring-pipelined GEMM for K=512 (MLP second layer).
// ---------------------------------------------------------------------------
#define APITCH 40
#define BPITCH 136
#define NSTAGE 3

template <int MODE, int OUTBF>
__global__ __launch_bounds__(256)
void gemm_bf(const bf16* __restrict__ A,
             const bf16* __restrict__ Wb,
             const float* __restrict__ bias,
             const float* __restrict__ res,
             void* __restrict__ Cout,
             int M, int N, int K, float scale)
{
    __shared__ bf16 As[NSTAGE][64*APITCH];
    __shared__ bf16 Bs[NSTAGE][32*BPITCH];

    const int tid  = threadIdx.x;
    const int bm   = blockIdx.y * 64;
    const int bn   = blockIdx.x * 128;
    const int warp = tid >> 5;
    const int lane = tid & 31;
    const int g    = lane >> 2;
    const int t    = lane & 3;
    const int m_base = (warp >> 1) * 16;
    const int n_base = (warp & 1) * 64;

    const int a_r = tid >> 2, a_c = tid & 3;
    const int b_r0 = tid >> 4, b_c = tid & 15;
    const int b_r1 = b_r0 + 16;

    const bf16* Ag = A  + (size_t)bm * K;
    const bf16* Bg = Wb + bn;

    const unsigned aS = s2u(&As[0][0]);
    const unsigned bS = s2u(&Bs[0][0]);
    const unsigned aBufSz = 64*APITCH*2;
    const unsigned bBufSz = 32*BPITCH*2;
    const unsigned ad = aS + (a_r*APITCH + a_c*8)*2;
    const unsigned bd0 = bS + (b_r0*BPITCH + b_c*8)*2;
    const unsigned bd1 = bS + (b_r1*BPITCH + b_c*8)*2;

    float acc[8][4];
    #pragma unroll
    for (int nt = 0; nt < 8; nt++)
        #pragma unroll
        for (int e = 0; e < 4; e++) acc[nt][e] = 0.0f;

    const int ntile = K / 32;

    auto stage = [&](int buf, int kt) {
        CP_ASYNC16(ad  + buf*aBufSz, Ag + (size_t)a_r*K + kt*32 + a_c*8);
        CP_ASYNC16(bd0 + buf*bBufSz, Bg + (size_t)(kt*32 + b_r0)*N + b_c*8);
        CP_ASYNC16(bd1 + buf*bBufSz, Bg + (size_t)(kt*32 + b_r1)*N + b_c*8);
        asm volatile("cp.async.commit_group;");
    };

    stage(0, 0);
    if (ntile > 1) stage(1, 1);

    for (int kt = 0; kt < ntile; kt++) {
        if (kt + 1 < ntile) asm volatile("cp.async.wait_group 1;");
        else                asm volatile("cp.async.wait_group 0;");
        __syncthreads();
        if (kt + 2 < ntile) stage((kt + 2) % NSTAGE, kt + 2);
        const int cur = kt % NSTAGE;
        gemm_tile(aS + cur*aBufSz, bS + cur*bBufSz, m_base, n_base, lane, acc,
                  APITCH, BPITCH);
        __syncthreads();
    }

    float* Cf = (float*)Cout;
    bf16*  Cb = (bf16*)Cout;
    int row0 = bm + m_base + g;
    int row1 = row0 + 8;
    #pragma unroll
    for (int nt = 0; nt < 8; nt++) {
        int col = bn + n_base + nt*8 + 2*t;
        float b0 = bias[col], b1 = bias[col+1];
        float v00 = acc[nt][0] + b0;
        float v01 = acc[nt][1] + b1;
        float v10 = acc[nt][2] + b0;
        float v11 = acc[nt][3] + b1;
        if (MODE == 1) { v00 *= scale; v01 *= scale; v10 *= scale; v11 *= scale; }
        if (MODE == 2) {
            v00 = 0.5f*v00*(1.0f + erff(v00*0.70710678118654752f));
            v01 = 0.5f*v01*(1.0f + erff(v01*0.70710678118654752f));
            v10 = 0.5f*v10*(1.0f + erff(v10*0.70710678118654752f));
            v11 = 0.5f*v11*(1.0f + erff(v11*0.70710678118654752f));
        }
        if (MODE == 3) {
            float2 r0 = *(const float2*)&res[(size_t)row0*N + col];
            float2 r1 = *(const float2*)&res[(size_t)row1*N + col];
            v00 += r0.x; v01 += r0.y; v10 += r1.x; v11 += r1.y;
        }
        if (OUTBF) {
            bf162 p0 = __float22bfloat162_rn(make_float2(v00, v01));
            bf162 p1 = __float22bfloat162_rn(make_float2(v10, v11));
            *(unsigned*)&Cb[(size_t)row0*N + col] = *(unsigned*)&p0;
            *(unsigned*)&Cb[(size_t)row1*N + col] = *(unsigned*)&p1;
        } else {
            *(float2*)&Cf[(size_t)row0*N + col] = make_float2(v00, v01);
            *(float2*)&Cf[(size_t)row1*N + col] = make_float2(v10, v11);
        }
    }
}

// ---------------------------------------------------------------------------
// Neighborhood attention v4 (tensor-core): one block = 8x4 query tile x ONE
// head. scores = Q(32x32) @ Kt(32x160) via MMA; masked softmax; out = P @ V.
// Patch 14x10 = 140 tokens, padded to 160 columns for the MMA.
// ---------------------------------------------------------------------------
#define PR 14
#define PC 10
#define PTOK 140
#define NPAD 160
#define KTP 168     // Kt pitch (bf16): [32 dims][160 toks + pad]
#define VP  40      // Vs pitch: [160 toks][32 dims + pad]
#define PP  168     // P pitch:  [32 q][160 toks + pad]
#define QP  40      // Qs pitch: [32 q][32 dims + pad]
#define SCP 164     // scores pitch (fp32)

__global__ __launch_bounds__(256)
void nat_attn4(const bf16* __restrict__ q,
               const bf16* __restrict__ kv,
               const float* __restrict__ rpb,
               bf16* __restrict__ out)
{
    extern __shared__ bf16 smb[];
    bf16*  Kt = smb;                       // [32][168]
    bf16*  Vs = Kt + 32*KTP;               // [160][40]
    bf16*  Ps = Vs + NPAD*VP;              // [32][168]
    bf16*  Qs = Ps + 32*PP;                // [32][40]
    float* scores = (float*)(Qs + 32*QP);  // [32][164]
    float* rs = scores + 32*SCP;           // [169]

    const int blk = blockIdx.x;
    const int h   = blk & 3;
    const int r2  = blk >> 2;
    const int b   = r2 >> 7;
    const int rem = r2 & 127;
    const int it  = (rem >> 4) << 3;
    const int jt  = (rem & 15) << 2;

    int ip0 = it - 3; if (ip0 < 0) ip0 = 0; if (ip0 > Hh - PR) ip0 = Hh - PR;
    int jp0 = jt - 3; if (jp0 < 0) jp0 = 0; if (jp0 > Ww - PC) jp0 = Ww - PC;

    const int tid  = threadIdx.x;
    const int base = b * (Hh*Ww);
    const uint4* kv4 = (const uint4*)kv;

    // stage K (transposed -> Kt[dim][tok]) and V (natural -> Vs[tok][dim])
    for (int f = tid; f < PTOK*4; f += 256) {
        int tok = f >> 2, c = f & 3;
        int r = (tok*205) >> 11;          // tok / 10
        int cc = tok - r*PC;
        int g = base + (ip0 + r)*Ww + (jp0 + cc);
        uint4 kvec = kv4[(size_t)g*32 + h*4 + c];
        bf16 tmp[8]; *(uint4*)tmp = kvec;
        #pragma unroll
        for (int d = 0; d < 8; d++) Kt[(c*8 + d)*KTP + tok] = tmp[d];
        *(uint4*)&Vs[tok*VP + c*8] = kv4[(size_t)g*32 + 16 + h*4 + c];
    }
    // zero V pad rows (tokens 140..159)
    for (int f = tid; f < 100; f += 256) {
        int row = PTOK + f/5, cc = (f - (f/5)*5)*8;
        uint4 z = make_uint4(0,0,0,0);
        *(uint4*)&Vs[row*VP + cc] = z;
    }
    // stage Q (32 queries x 32 dims)
    for (int f = tid; f < 128; f += 256) {
        int qq = f >> 2, c = f & 3;
        int qi = qq >> 2, qj = qq & 3;
        int g = base + (it + qi)*Ww + (jt + qj);
        *(uint4*)&Qs[qq*QP + c*8] = ((const uint4*)q)[(size_t)g*16 + h*4 + c];
    }
    for (int f = tid; f < 169; f += 256) rs[f] = rpb[h*169 + f];
    __syncthreads();

    const int w    = tid >> 5;
    const int lane = tid & 31;
    const int a_row = lane & 15;
    const int a_k   = (lane >> 4) << 3;
    const int b_k   = (lane & 7) + (((lane >> 3) & 1) << 3);
    const int b_n   = (lane >> 4) << 3;

    // ---- score GEMM: warps 2m x 4n, warp tile 16 x 40 ----
    {
        const int m_base = (w >> 2) * 16;
        const int n_base = (w & 3) * 40;
        const unsigned qS = s2u(Qs), kS = s2u(Kt);
        float acc[5][4];
        #pragma unroll
        for (int nt = 0; nt < 5; nt++)
            #pragma unroll
            for (int e = 0; e < 4; e++) acc[nt][e] = 0.0f;

        #pragma unroll
        for (int kk = 0; kk < 32; kk += 16) {
            unsigned af[4], bf[5][2];
            unsigned addr = qS + ((m_base + a_row)*QP + kk + a_k)*2;
            asm volatile("ldmatrix.sync.aligned.m8n8.x4.shared.b16 {%0,%1,%2,%3}, [%4];"
                : "=r"(af[0]), "=r"(af[1]), "=r"(af[2]), "=r"(af[3]) : "r"(addr));
            #pragma unroll
            for (int np = 0; np < 2; np++) {
                unsigned r0, r1, r2, r3;
                addr = kS + ((kk + b_k)*KTP + n_base + np*16 + b_n)*2;
                asm volatile("ldmatrix.sync.aligned.m8n8.x4.trans.shared.b16 {%0,%1,%2,%3}, [%4];"
                    : "=r"(r0), "=r"(r1), "=r"(r2), "=r"(r3) : "r"(addr));
                bf[2*np][0] = r0; bf[2*np][1] = r1;
                bf[2*np+1][0] = r2; bf[2*np+1][1] = r3;
            }
            {
                unsigned r0, r1;
                addr = kS + ((kk + b_k)*KTP + n_base + 32)*2;
                asm volatile("ldmatrix.sync.aligned.m8n8.x2.trans.shared.b16 {%0,%1}, [%2];"
                    : "=r"(r0), "=r"(r1) : "r"(addr));
                bf[4][0] = r0; bf[4][1] = r1;
            }
            #pragma unroll
            for (int nt = 0; nt < 5; nt++)
                asm volatile(
                    "mma.sync.aligned.m16n8k16.row.col.f32.bf16.bf16.f32 "
                    "{%0,%1,%2,%3}, {%4,%5,%6,%7}, {%8,%9}, {%0,%1,%2,%3};"
                    : "+f"(acc[nt][0]), "+f"(acc[nt][1]), "+f"(acc[nt][2]), "+f"(acc[nt][3])
                    : "r"(af[0]), "r"(af[1]), "r"(af[2]), "r"(af[3]),
                      "r"(bf[nt][0]), "r"(bf[nt][1]));
        }

        const int row0 = m_base + (lane >> 2);
        const int col0 = n_base + 2*(lane & 3);
        #pragma unroll
        for (int nt = 0; nt < 5; nt++) {
            *(float2*)&scores[row0*SCP + col0 + nt*8]       = make_float2(acc[nt][0], acc[nt][1]);
            *(float2*)&scores[(row0+8)*SCP + col0 + nt*8]   = make_float2(acc[nt][2], acc[nt][3]);
        }
    }
    __syncthreads();

    // ---- masked softmax: warp w handles queries 4w..4w+3 ----
    #pragma unroll
    for (int s2 = 0; s2 < 4; s2++) {
        const int qq = w*4 + s2;
        const int qi = qq >> 2, qj = qq & 3;
        const int gi = it + qi, gj = jt + qj;
        int i0 = gi - 3; if (i0 < 0) i0 = 0; if (i0 > Hh - Kk) i0 = Hh - Kk;
        int j0 = gj - 3; if (j0 < 0) j0 = 0; if (j0 > Ww - Kk) j0 = Ww - Kk;
        const int ioff = i0 - ip0;
        const int joff = j0 - jp0;

        float e[5];
        float mx = -INFINITY;
        #pragma unroll
        for (int rr = 0; rr < 5; rr++) {
            int t = lane + 32*rr;
            int r = (t*205) >> 11;
            int c = t - r*PC;
            bool valid = (t < PTOK) && (r >= ioff) && (r < ioff + Kk)
                                    && (c >= joff) && (c < joff + Kk);
            float sv = -INFINITY;
            if (valid) {
                int ri = ip0 + r - gi + (Kk - 1);
                int rj = jp0 + c - gj + (Kk - 1);
                sv = scores[qq*SCP + t] + rs[ri*13 + rj];
            }
            e[rr] = sv;
            mx = fmaxf(mx, sv);
        }
        #pragma unroll
        for (int off = 16; off; off >>= 1)
            mx = fmaxf(mx, __shfl_xor_sync(0xffffffff, mx, off));
        float sum = 0.f;
        #pragma unroll
        for (int rr = 0; rr < 5; rr++) {
            e[rr] = __expf(e[rr] - mx);
            sum += e[rr];
        }
        #pragma unroll
        for (int off = 16; off; off >>= 1)
            sum += __shfl_xor_sync(0xffffffff, sum, off);
        float rinv = 1.0f / sum;
        #pragma unroll
        for (int rr = 0; rr < 5; rr++)
            Ps[qq*PP + lane + 32*rr] = __float2bfloat16(e[rr] * rinv);
    }
    __syncthreads();

    // ---- V GEMM: warps 2m x 4n, warp tile 16 x 8, k=160 ----
    {
        const int m_base = (w >> 2) * 16;
        const int n_base = (w & 3) * 8;
        const unsigned pS = s2u(Ps), vS = s2u(Vs);
        float acc[4] = {0.f, 0.f, 0.f, 0.f};

        #pragma unroll
        for (int kt = 0; kt < 10; kt++) {
            int kk = kt*16;
            unsigned af[4];
            unsigned addr = pS + ((m_base + a_row)*PP + kk + a_k)*2;
            asm volatile("ldmatrix.sync.aligned.m8n8.x4.shared.b16 {%0,%1,%2,%3}, [%4];"
                : "=r"(af[0]), "=r"(af[1]), "=r"(af[2]), "=r"(af[3]) : "r"(addr));
            unsigned b0, b1;
            addr = vS + ((kk + b_k)*VP + n_base)*2;
            asm volatile("ldmatrix.sync.aligned.m8n8.x2.trans.shared.b16 {%0,%1}, [%2];"
                : "=r"(b0), "=r"(b1) : "r"(addr));
            asm volatile(
                "mma.sync.aligned.m16n8k16.row.col.f32.bf16.bf16.f32 "
                "{%0,%1,%2,%3}, {%4,%5,%6,%7}, {%8,%9}, {%0,%1,%2,%3};"
                : "+f"(acc[0]), "+f"(acc[1]), "+f"(acc[2]), "+f"(acc[3])
                : "r"(af[0]), "r"(af[1]), "r"(af[2]), "r"(af[3]),
                  "r"(b0), "r"(b1));
        }

        const int col = n_base + 2*(lane & 3);
        #pragma unroll
        for (int half = 0; half < 2; half++) {
            int qq = m_base + (lane >> 2) + half*8;
            int qi = qq >> 2, qj = qq & 3;
            int g = base + (it + qi)*Ww + (jt + qj);
            bf162 p = __float22bfloat162_rn(make_float2(acc[half*2], acc[half*2+1]));
            *(unsigned*)&out[(size_t)g*Cc + h*32 + col] = *(unsigned*)&p;
        }
    }
}

// ---------------------------------------------------------------------------
// Launch
// ---------------------------------------------------------------------------
extern "C" void kernel_launch(void* const* d_in, const int* in_sizes, int n_in,
                              void* d_out, int out_size)
{
    const float* query     = (const float*)d_in[0];
    const float* key_value = (const float*)d_in[1];
    const float* g1  = (const float*)d_in[2];
    const float* b1  = (const float*)d_in[3];
    const float* g2  = (const float*)d_in[4];
    const float* b2  = (const float*)d_in[5];
    const float* g3  = (const float*)d_in[6];
    const float* b3  = (const float*)d_in[7];
    const float* Wq  = (const float*)d_in[8];
    const float* bq  = (const float*)d_in[9];
    const float* Wkv = (const float*)d_in[10];
    const float* bkv = (const float*)d_in[11];
    const float* Wp  = (const float*)d_in[12];
    const float* bp  = (const float*)d_in[13];
    const float* rpb = (const float*)d_in[14];
    const float* W1  = (const float*)d_in[15];
    const float* bm1 = (const float*)d_in[16];
    const float* W2  = (const float*)d_in[17];
    const float* bm2 = (const float*)d_in[18];
    float* out = (float*)d_out;

    bf16*  qn     = nullptr; cudaGetSymbolAddress((void**)&qn,     g_qn);
    bf16*  kvn    = nullptr; cudaGetSymbolAddress((void**)&kvn,    g_kvn);
    bf16*  qbuf   = nullptr; cudaGetSymbolAddress((void**)&qbuf,   g_q);
    bf16*  kvbuf  = nullptr; cudaGetSymbolAddress((void**)&kvbuf,  g_kv);
    bf16*  attn   = nullptr; cudaGetSymbolAddress((void**)&attn,   g_attn);
    float* xbuf   = nullptr; cudaGetSymbolAddress((void**)&xbuf,   g_x);
    bf16*  hln    = nullptr; cudaGetSymbolAddress((void**)&hln,    g_hln);
    bf16*  hidden = nullptr; cudaGetSymbolAddress((void**)&hidden, g_hidden);
    bf16*  wpb    = nullptr; cudaGetSymbolAddress((void**)&wpb,    g_wp);
    bf16*  w1b    = nullptr; cudaGetSymbolAddress((void**)&w1b,    g_w1);
    bf16*  w2b    = nullptr; cudaGetSymbolAddress((void**)&w2b,    g_w2);

    const int k128_smem = (64 + 128) * KP * 2;   // 52224 B
    const int attn_smem = (32*KTP + NPAD*VP + 32*PP + 32*QP) * 2
                        + (32*SCP + 169) * 4;    // ~58.5 KB

    static bool attr_set = false;
    if (!attr_set) {
        cudaFuncSetAttribute(qkv_k128,
                             cudaFuncAttributeMaxDynamicSharedMemorySize, k128_smem);
        cudaFuncSetAttribute(gemm_k128<3,0,1>,
                             cudaFuncAttributeMaxDynamicSharedMemorySize, k128_smem);
        cudaFuncSetAttribute(gemm_k128<2,1,0>,
                             cudaFuncAttributeMaxDynamicSharedMemorySize, k128_smem);
        cudaFuncSetAttribute(nat_attn4,
                             cudaFuncAttributeMaxDynamicSharedMemorySize, attn_smem);
        attr_set = true;
    }

    // 0) weight conversion
    cvt_weights<<<192, 256>>>(Wq, Wkv, Wp, W1, W2);

    // 1) LN1 + LN2 fused launch
    ln_dual<<<(2*NTOK*32)/256, 256>>>(query, g1, b1, qn, key_value, g2, b2, kvn);

    // 2) Fused Q + KV projections (fully staged K=128)
    qkv_k128<<<dim3(3, NTOK/64), 256, k128_smem>>>(qn, kvn, bq, bkv, qbuf, kvbuf);

    // 3) Neighborhood attention (tensor-core)
    nat_attn4<<<Bq*(Hh/8)*(Ww/4)*NHh, 256, attn_smem>>>(qbuf, kvbuf, rpb, attn);

    // 4) Output projection + residual + fused LN3 (xbuf fp32 + hln bf16)
    gemm_k128<3,0,1><<<dim3(1, NTOK/64), 256, k128_smem>>>(
        attn, wpb, bp, key_value, xbuf, Cc, 1.0f, g3, b3, hln);

    // 5) MLP
    gemm_k128<2,1,0><<<dim3(MLPD/128, NTOK/64), 256, k128_smem>>>(
        hln, w1b, bm1, nullptr, hidden, MLPD, 1.0f, nullptr, nullptr, nullptr);
    gemm_bf<3,0><<<dim3(Cc/128, NTOK/64), 256>>>(
        hidden, w2b, bm2, xbuf, out, NTOK, Cc, MLPD, 1.0f);
}

// round 13
// speedup vs baseline: 2.0037x; 1.0947x over previous
#include <cuda_runtime.h>
#include <cuda_bf16.h>
#include <math.h>

// Problem constants
#define Bq  4
#define Hh  64
#define Ww  64
#define Cc  128
#define NHh 4
#define Kk  7
#define HDd 32
#define MLPD 512
#define NTOK (Bq*Hh*Ww)   // 16384

typedef __nv_bfloat16  bf16;
typedef __nv_bfloat162 bf162;

// Scratch (device globals)
__device__ __align__(16) bf16  g_qn    [NTOK*Cc];
__device__ __align__(16) bf16  g_kvn   [NTOK*Cc];
__device__ __align__(16) bf16  g_q     [NTOK*Cc];
__device__ __align__(16) bf16  g_kv    [NTOK*2*Cc];
__device__ __align__(16) bf16  g_attn  [NTOK*Cc];
__device__ __align__(16) float g_x     [NTOK*Cc];
__device__ __align__(16) bf16  g_hln   [NTOK*Cc];
__device__ __align__(16) bf16  g_hidden[NTOK*MLPD];

// bf16 weights (converted once per launch)
__device__ __align__(16) bf16  g_wq [Cc*Cc];
__device__ __align__(16) bf16  g_wkv[Cc*2*Cc];
__device__ __align__(16) bf16  g_wp [Cc*Cc];
__device__ __align__(16) bf16  g_w1 [Cc*MLPD];
__device__ __align__(16) bf16  g_w2 [MLPD*Cc];

__device__ __forceinline__ unsigned s2u(const void* p) {
    return (unsigned)__cvta_generic_to_shared(p);
}

#define CP_ASYNC16(dst, src) \
    asm volatile("cp.async.ca.shared.global [%0], [%1], 16;" :: "r"(dst), "l"(src))

// ---------------------------------------------------------------------------
// Weight conversion fp32 -> bf16
// ---------------------------------------------------------------------------
__global__ void cvt_weights(const float* __restrict__ Wq,
                            const float* __restrict__ Wkv,
                            const float* __restrict__ Wp,
                            const float* __restrict__ W1,
                            const float* __restrict__ W2)
{
    int i = blockIdx.x * blockDim.x + threadIdx.x;   // 0..49151
    const float* src; bf16* dst; int off;
    if      (i < 4096)  { src = Wq;  dst = g_wq;  off = i; }
    else if (i < 12288) { src = Wkv; dst = g_wkv; off = i - 4096; }
    else if (i < 16384) { src = Wp;  dst = g_wp;  off = i - 12288; }
    else if (i < 32768) { src = W1;  dst = g_w1;  off = i - 16384; }
    else                { src = W2;  dst = g_w2;  off = i - 32768; }
    float4 v = ((const float4*)src)[off];
    bf162 lo = __float22bfloat162_rn(make_float2(v.x, v.y));
    bf162 hi = __float22bfloat162_rn(make_float2(v.z, v.w));
    uint2 pk; pk.x = *(unsigned*)&lo; pk.y = *(unsigned*)&hi;
    ((uint2*)dst)[off] = pk;
}

// ---------------------------------------------------------------------------
// Dual LayerNorm
// ---------------------------------------------------------------------------
__global__ void ln_dual(const float* __restrict__ in1, const float* __restrict__ gg1,
                        const float* __restrict__ bb1, bf16* __restrict__ out1,
                        const float* __restrict__ in2, const float* __restrict__ gg2,
                        const float* __restrict__ bb2, bf16* __restrict__ out2)
{
    int w    = (blockIdx.x * blockDim.x + threadIdx.x) >> 5;
    int lane = threadIdx.x & 31;
    const float* in; const float* g; const float* b; bf16* out; int tok;
    if (w < NTOK) { in = in1; g = gg1; b = bb1; out = out1; tok = w; }
    else          { in = in2; g = gg2; b = bb2; out = out2; tok = w - NTOK; }

    const float4 v = *(const float4*)&in[(size_t)tok*Cc + lane*4];
    float s  = v.x + v.y + v.z + v.w;
    float sq = v.x*v.x + v.y*v.y + v.z*v.z + v.w*v.w;
    #pragma unroll
    for (int off = 16; off; off >>= 1) {
        s  += __shfl_xor_sync(0xffffffff, s,  off);
        sq += __shfl_xor_sync(0xffffffff, sq, off);
    }
    float mean = s * (1.0f/Cc);
    float var  = sq * (1.0f/Cc) - mean*mean;
    float inv  = rsqrtf(var + 1e-5f);

    const float4 gv = *(const float4*)&g[lane*4];
    const float4 bv = *(const float4*)&b[lane*4];
    bf162 o0 = __float22bfloat162_rn(make_float2((v.x-mean)*inv*gv.x + bv.x,
                                                 (v.y-mean)*inv*gv.y + bv.y));
    bf162 o1 = __float22bfloat162_rn(make_float2((v.z-mean)*inv*gv.z + bv.z,
                                                 (v.w-mean)*inv*gv.w + bv.w));
    uint2 pk; pk.x = *(unsigned*)&o0; pk.y = *(unsigned*)&o1;
    *(uint2*)&out[(size_t)tok*Cc + lane*4] = pk;
}

// ---------------------------------------------------------------------------
// MMA tile helper: one BK=32 slab (trans-B variant, [k][n] layout).
// ---------------------------------------------------------------------------
__device__ __forceinline__ void gemm_tile(
    unsigned aB, unsigned bB, int m_base, int n_base, int lane,
    float acc[8][4], int apitch, int bpitch)
{
    const int a_row_sel = lane & 15;
    const int a_k_sel   = (lane >> 4) << 3;
    const int b_k_sel   = (lane & 7) + (((lane >> 3) & 1) << 3);
    const int b_n_sel   = (lane >> 4) << 3;
    #pragma unroll
    for (int kk = 0; kk < 32; kk += 16) {
        unsigned af[4], bf[8][2];
        {
            unsigned addr = aB + ((m_base + a_row_sel)*apitch + kk + a_k_sel)*2;
            asm volatile("ldmatrix.sync.aligned.m8n8.x4.shared.b16 {%0,%1,%2,%3}, [%4];"
                : "=r"(af[0]), "=r"(af[1]), "=r"(af[2]), "=r"(af[3]) : "r"(addr));
        }
        #pragma unroll
        for (int np = 0; np < 4; np++) {
            unsigned r0, r1, r2, r3;
            unsigned addr = bB + ((kk + b_k_sel)*bpitch + n_base + np*16 + b_n_sel)*2;
            asm volatile("ldmatrix.sync.aligned.m8n8.x4.trans.shared.b16 {%0,%1,%2,%3}, [%4];"
                : "=r"(r0), "=r"(r1), "=r"(r2), "=r"(r3) : "r"(addr));
            bf[2*np  ][0] = r0; bf[2*np  ][1] = r1;
            bf[2*np+1][0] = r2; bf[2*np+1][1] = r3;
        }
        #pragma unroll
        for (int nt = 0; nt < 8; nt++)
            asm volatile(
                "mma.sync.aligned.m16n8k16.row.col.f32.bf16.bf16.f32 "
                "{%0,%1,%2,%3}, {%4,%5,%6,%7}, {%8,%9}, {%0,%1,%2,%3};"
                : "+f"(acc[nt][0]), "+f"(acc[nt][1]), "+f"(acc[nt][2]), "+f"(acc[nt][3])
                : "r"(af[0]), "r"(af[1]), "r"(af[2]), "r"(af[3]),
                  "r"(bf[nt][0]), "r"(bf[nt][1]));
    }
}

// ---------------------------------------------------------------------------
// Fully-staged K=128 GEMM (unchanged from round 12).
// ---------------------------------------------------------------------------
#define KP 136

template <int MODE, int OUTBF, int LNFUSE>
__global__ __launch_bounds__(256)
void gemm_k128(const bf16* __restrict__ A,
               const bf16* __restrict__ Wb,
               const float* __restrict__ bias,
               const float* __restrict__ res,
               void* __restrict__ Cout,
               int N, float scale,
               const float* __restrict__ lng,
               const float* __restrict__ lnb,
               bf16* __restrict__ lnout)
{
    extern __shared__ bf16 sm[];
    bf16* As = sm;
    bf16* Bs = sm + 64*KP;

    const int tid  = threadIdx.x;
    const int bm   = blockIdx.y * 64;
    const int bn   = blockIdx.x * 128;
    const int warp = tid >> 5;
    const int lane = tid & 31;
    const int g    = lane >> 2;
    const int t    = lane & 3;
    const int m_base = (warp >> 1) * 16;
    const int warpN  = warp & 1;
    const int n_base = warpN * 64;

    {
        const unsigned aS = s2u(As);
        #pragma unroll
        for (int i = 0; i < 4; i++) {
            int id = tid + i*256;
            int r = id >> 4, c = id & 15;
            CP_ASYNC16(aS + (r*KP + c*8)*2, A + (size_t)(bm + r)*Cc + c*8);
        }
        const unsigned bS = s2u(Bs);
        #pragma unroll
        for (int i = 0; i < 8; i++) {
            int id = tid + i*256;
            int r = id >> 4, c = id & 15;
            CP_ASYNC16(bS + (r*KP + c*8)*2, Wb + (size_t)r*N + bn + c*8);
        }
        asm volatile("cp.async.commit_group;");
    }

    float acc[8][4];
    #pragma unroll
    for (int nt = 0; nt < 8; nt++)
        #pragma unroll
        for (int e = 0; e < 4; e++) acc[nt][e] = 0.0f;

    asm volatile("cp.async.wait_group 0;");
    __syncthreads();

    const unsigned aS = s2u(As);
    const unsigned bS = s2u(Bs);
    #pragma unroll
    for (int kt = 0; kt < 4; kt++)
        gemm_tile(aS + kt*32*2, bS + (kt*32*KP)*2, m_base, n_base, lane, acc, KP, KP);

    float* Cf = (float*)Cout;
    bf16*  Cb = (bf16*)Cout;
    const int row0 = bm + m_base + g;
    const int row1 = row0 + 8;

    float s0 = 0.f, q0 = 0.f, s1 = 0.f, q1 = 0.f;
    float* vsm  = (float*)Bs;
    float* part = (float*)As;

    if (LNFUSE) __syncthreads();

    #pragma unroll
    for (int nt = 0; nt < 8; nt++) {
        int col = bn + n_base + nt*8 + 2*t;
        float b0 = bias[col], b1 = bias[col+1];
        float v00 = acc[nt][0] + b0;
        float v01 = acc[nt][1] + b1;
        float v10 = acc[nt][2] + b0;
        float v11 = acc[nt][3] + b1;
        if (MODE == 1) { v00 *= scale; v01 *= scale; v10 *= scale; v11 *= scale; }
        if (MODE == 2) {
            v00 = 0.5f*v00*(1.0f + erff(v00*0.70710678118654752f));
            v01 = 0.5f*v01*(1.0f + erff(v01*0.70710678118654752f));
            v10 = 0.5f*v10*(1.0f + erff(v10*0.70710678118654752f));
            v11 = 0.5f*v11*(1.0f + erff(v11*0.70710678118654752f));
        }
        if (MODE == 3) {
            float2 r0 = *(const float2*)&res[(size_t)row0*N + col];
            float2 r1 = *(const float2*)&res[(size_t)row1*N + col];
            v00 += r0.x; v01 += r0.y; v10 += r1.x; v11 += r1.y;
        }
        if (OUTBF) {
            bf162 p0 = __float22bfloat162_rn(make_float2(v00, v01));
            bf162 p1 = __float22bfloat162_rn(make_float2(v10, v11));
            *(unsigned*)&Cb[(size_t)row0*N + col] = *(unsigned*)&p0;
            *(unsigned*)&Cb[(size_t)row1*N + col] = *(unsigned*)&p1;
        } else {
            *(float2*)&Cf[(size_t)row0*N + col] = make_float2(v00, v01);
            *(float2*)&Cf[(size_t)row1*N + col] = make_float2(v10, v11);
        }
        if (LNFUSE) {
            int lc = n_base + nt*8 + 2*t;
            int lr0 = m_base + g, lr1 = lr0 + 8;
            vsm[lr0*132 + lc] = v00; vsm[lr0*132 + lc + 1] = v01;
            vsm[lr1*132 + lc] = v10; vsm[lr1*132 + lc + 1] = v11;
            s0 += v00 + v01;  q0 += v00*v00 + v01*v01;
            s1 += v10 + v11;  q1 += v10*v10 + v11*v11;
        }
    }

    if (LNFUSE) {
        #pragma unroll
        for (int off = 1; off < 4; off <<= 1) {
            s0 += __shfl_xor_sync(0xffffffff, s0, off);
            q0 += __shfl_xor_sync(0xffffffff, q0, off);
            s1 += __shfl_xor_sync(0xffffffff, s1, off);
            q1 += __shfl_xor_sync(0xffffffff, q1, off);
        }
        int lr0 = m_base + g, lr1 = lr0 + 8;
        if (t == 0) {
            *(float2*)&part[(lr0*2 + warpN)*2] = make_float2(s0, q0);
            *(float2*)&part[(lr1*2 + warpN)*2] = make_float2(s1, q1);
        }
        __syncthreads();

        float2 a0 = *(float2*)&part[(lr0*2 + 0)*2];
        float2 a1 = *(float2*)&part[(lr0*2 + 1)*2];
        float2 c0 = *(float2*)&part[(lr1*2 + 0)*2];
        float2 c1 = *(float2*)&part[(lr1*2 + 1)*2];
        float m0 = (a0.x + a1.x) * (1.0f/Cc);
        float v0 = (a0.y + a1.y) * (1.0f/Cc) - m0*m0;
        float i0 = rsqrtf(v0 + 1e-5f);
        float m1 = (c0.x + c1.x) * (1.0f/Cc);
        float v1 = (c0.y + c1.y) * (1.0f/Cc) - m1*m1;
        float i1 = rsqrtf(v1 + 1e-5f);

        #pragma unroll
        for (int nt = 0; nt < 8; nt++) {
            int lc  = n_base + nt*8 + 2*t;
            int col = bn + lc;
            float gg0 = lng[col], gg1b = lng[col+1];
            float bb0 = lnb[col], bb1 = lnb[col+1];
            float x00 = vsm[lr0*132 + lc], x01 = vsm[lr0*132 + lc + 1];
            float x10 = vsm[lr1*132 + lc], x11 = vsm[lr1*132 + lc + 1];
            bf162 p0 = __float22bfloat162_rn(make_float2((x00-m0)*i0*gg0 + bb0,
                                                         (x01-m0)*i0*gg1b + bb1));
            bf162 p1 = __float22bfloat162_rn(make_float2((x10-m1)*i1*gg0 + bb0,
                                                         (x11-m1)*i1*gg1b + bb1));
            *(unsigned*)&lnout[(size_t)row0*N + col] = *(unsigned*)&p0;
            *(unsigned*)&lnout[(size_t)row1*N + col] = *(unsigned*)&p1;
        }
    }
}

// ---------------------------------------------------------------------------
// Fused Q + KV projection, fully staged (K=128). (unchanged)
// ---------------------------------------------------------------------------
__global__ __launch_bounds__(256)
void qkv_k128(const bf16* __restrict__ qn, const bf16* __restrict__ kvn,
              const float* __restrict__ bq, const float* __restrict__ bkv,
              bf16* __restrict__ qout, bf16* __restrict__ kvout)
{
    extern __shared__ bf16 sm[];
    bf16* As = sm;
    bf16* Bs = sm + 64*KP;

    const int cb = blockIdx.x;
    const bool isQ = (cb == 0);
    const bf16*  A    = isQ ? qn : kvn;
    const bf16*  Wb   = isQ ? g_wq : g_wkv;
    const float* bias = isQ ? bq : bkv;
    bf16*        Cb   = isQ ? qout : kvout;
    const int N  = isQ ? Cc : 2*Cc;
    const int bn = isQ ? 0 : (cb - 1) * 128;

    const int tid  = threadIdx.x;
    const int bm   = blockIdx.y * 64;
    const int warp = tid >> 5;
    const int lane = tid & 31;
    const int g    = lane >> 2;
    const int t    = lane & 3;
    const int m_base = (warp >> 1) * 16;
    const int n_base = (warp & 1) * 64;

    {
        const unsigned aS = s2u(As);
        #pragma unroll
        for (int i = 0; i < 4; i++) {
            int id = tid + i*256;
            int r = id >> 4, c = id & 15;
            CP_ASYNC16(aS + (r*KP + c*8)*2, A + (size_t)(bm + r)*Cc + c*8);
        }
        const unsigned bS = s2u(Bs);
        #pragma unroll
        for (int i = 0; i < 8; i++) {
            int id = tid + i*256;
            int r = id >> 4, c = id & 15;
            CP_ASYNC16(bS + (r*KP + c*8)*2, Wb + (size_t)r*N + bn + c*8);
        }
        asm volatile("cp.async.commit_group;");
    }

    float acc[8][4];
    #pragma unroll
    for (int nt = 0; nt < 8; nt++)
        #pragma unroll
        for (int e = 0; e < 4; e++) acc[nt][e] = 0.0f;

    asm volatile("cp.async.wait_group 0;");
    __syncthreads();

    const unsigned aS = s2u(As);
    const unsigned bS = s2u(Bs);
    #pragma unroll
    for (int kt = 0; kt < 4; kt++)
        gemm_tile(aS + kt*32*2, bS + (kt*32*KP)*2, m_base, n_base, lane, acc, KP, KP);

    const float scale = 0.17677669529663689f;
    int row0 = bm + m_base + g;
    int row1 = row0 + 8;
    #pragma unroll
    for (int nt = 0; nt < 8; nt++) {
        int col = bn + n_base + nt*8 + 2*t;
        float b0 = bias[col], b1 = bias[col+1];
        float v00 = acc[nt][0] + b0;
        float v01 = acc[nt][1] + b1;
        float v10 = acc[nt][2] + b0;
        float v11 = acc[nt][3] + b1;
        if (isQ) { v00 *= scale; v01 *= scale; v10 *= scale; v11 *= scale; }
        bf162 p0 = __float22bfloat162_rn(make_float2(v00, v01));
        bf162 p1 = __float22bfloat162_rn(make_float2(v10, v11));
        *(unsigned*)&Cb[(size_t)row0*N + col] = *(unsigned*)&p0;
        *(unsigned*)&Cb[(size_t)row1*N + col] = *(unsigned*)&p1;
    }
}

// ---------------------------------------------------------------------------
// Ring-pipelined GEMM for K=512 (MLP second layer). (unchanged)
// ---------------------------------------------------------------------------
#define APITCH 40
#define BPITCH 136
#define NSTAGE 3

template <int MODE, int OUTBF>
__global__ __launch_bounds__(256)
void gemm_bf(const bf16* __restrict__ A,
             const bf16* __restrict__ Wb,
             const float* __restrict__ bias,
             const float* __restrict__ res,
             void* __restrict__ Cout,
             int M, int N, int K, float scale)
{
    __shared__ bf16 As[NSTAGE][64*APITCH];
    __shared__ bf16 Bs[NSTAGE][32*BPITCH];

    const int tid  = threadIdx.x;
    const int bm   = blockIdx.y * 64;
    const int bn   = blockIdx.x * 128;
    const int warp = tid >> 5;
    const int lane = tid & 31;
    const int g    = lane >> 2;
    const int t    = lane & 3;
    const int m_base = (warp >> 1) * 16;
    const int n_base = (warp & 1) * 64;

    const int a_r = tid >> 2, a_c = tid & 3;
    const int b_r0 = tid >> 4, b_c = tid & 15;
    const int b_r1 = b_r0 + 16;

    const bf16* Ag = A  + (size_t)bm * K;
    const bf16* Bg = Wb + bn;

    const unsigned aS = s2u(&As[0][0]);
    const unsigned bS = s2u(&Bs[0][0]);
    const unsigned aBufSz = 64*APITCH*2;
    const unsigned bBufSz = 32*BPITCH*2;
    const unsigned ad = aS + (a_r*APITCH + a_c*8)*2;
    const unsigned bd0 = bS + (b_r0*BPITCH + b_c*8)*2;
    const unsigned bd1 = bS + (b_r1*BPITCH + b_c*8)*2;

    float acc[8][4];
    #pragma unroll
    for (int nt = 0; nt < 8; nt++)
        #pragma unroll
        for (int e = 0; e < 4; e++) acc[nt][e] = 0.0f;

    const int ntile = K / 32;

    auto stage = [&](int buf, int kt) {
        CP_ASYNC16(ad  + buf*aBufSz, Ag + (size_t)a_r*K + kt*32 + a_c*8);
        CP_ASYNC16(bd0 + buf*bBufSz, Bg + (size_t)(kt*32 + b_r0)*N + b_c*8);
        CP_ASYNC16(bd1 + buf*bBufSz, Bg + (size_t)(kt*32 + b_r1)*N + b_c*8);
        asm volatile("cp.async.commit_group;");
    };

    stage(0, 0);
    if (ntile > 1) stage(1, 1);

    for (int kt = 0; kt < ntile; kt++) {
        if (kt + 1 < ntile) asm volatile("cp.async.wait_group 1;");
        else                asm volatile("cp.async.wait_group 0;");
        __syncthreads();
        if (kt + 2 < ntile) stage((kt + 2) % NSTAGE, kt + 2);
        const int cur = kt % NSTAGE;
        gemm_tile(aS + cur*aBufSz, bS + cur*bBufSz, m_base, n_base, lane, acc,
                  APITCH, BPITCH);
        __syncthreads();
    }

    float* Cf = (float*)Cout;
    bf16*  Cb = (bf16*)Cout;
    int row0 = bm + m_base + g;
    int row1 = row0 + 8;
    #pragma unroll
    for (int nt = 0; nt < 8; nt++) {
        int col = bn + n_base + nt*8 + 2*t;
        float b0 = bias[col], b1 = bias[col+1];
        float v00 = acc[nt][0] + b0;
        float v01 = acc[nt][1] + b1;
        float v10 = acc[nt][2] + b0;
        float v11 = acc[nt][3] + b1;
        if (MODE == 1) { v00 *= scale; v01 *= scale; v10 *= scale; v11 *= scale; }
        if (MODE == 2) {
            v00 = 0.5f*v00*(1.0f + erff(v00*0.70710678118654752f));
            v01 = 0.5f*v01*(1.0f + erff(v01*0.70710678118654752f));
            v10 = 0.5f*v10*(1.0f + erff(v10*0.70710678118654752f));
            v11 = 0.5f*v11*(1.0f + erff(v11*0.70710678118654752f));
        }
        if (MODE == 3) {
            float2 r0 = *(const float2*)&res[(size_t)row0*N + col];
            float2 r1 = *(const float2*)&res[(size_t)row1*N + col];
            v00 += r0.x; v01 += r0.y; v10 += r1.x; v11 += r1.y;
        }
        if (OUTBF) {
            bf162 p0 = __float22bfloat162_rn(make_float2(v00, v01));
            bf162 p1 = __float22bfloat162_rn(make_float2(v10, v11));
            *(unsigned*)&Cb[(size_t)row0*N + col] = *(unsigned*)&p0;
            *(unsigned*)&Cb[(size_t)row1*N + col] = *(unsigned*)&p1;
        } else {
            *(float2*)&Cf[(size_t)row0*N + col] = make_float2(v00, v01);
            *(float2*)&Cf[(size_t)row1*N + col] = make_float2(v10, v11);
        }
    }
}

// ---------------------------------------------------------------------------
// Neighborhood attention v5 (tensor-core, fused softmax epilogue).
// One block = 8x4 query tile x ONE head.
//  - K stored NATURALLY [tok][dim]; score-GEMM B fragments via NON-trans
//    ldmatrix (transpose in the load, not the data).
//  - Score epilogue applies mask + rpb + exp (no max subtraction; scores are
//    O(1)), writes bf16 P, and reduces row sums. Normalization folded into
//    the V-GEMM output.
// ---------------------------------------------------------------------------
#define PR 14
#define PC 10
#define PTOK 140
#define NPAD 160
#define KSP 40      // Ks/Vs pitch: [160 toks][32 dims + pad]
#define PP  168     // P pitch:  [32 q][160 toks + pad]
#define QP  40      // Qs pitch: [32 q][32 dims + pad]

__global__ __launch_bounds__(256)
void nat_attn5(const bf16* __restrict__ q,
               const bf16* __restrict__ kv,
               const float* __restrict__ rpb,
               bf16* __restrict__ out)
{
    extern __shared__ bf16 smb[];
    bf16*  Ks = smb;                       // [160][40]
    bf16*  Vs = Ks + NPAD*KSP;             // [160][40]
    bf16*  Ps = Vs + NPAD*KSP;             // [32][168]
    bf16*  Qs = Ps + 32*PP;                // [32][40]
    float* rs   = (float*)(Qs + 32*QP);    // [169]
    float* part = rs + 169;                // [32][4]

    const int blk = blockIdx.x;
    const int h   = blk & 3;
    const int r2  = blk >> 2;
    const int b   = r2 >> 7;
    const int rem = r2 & 127;
    const int it  = (rem >> 4) << 3;
    const int jt  = (rem & 15) << 2;

    int ip0 = it - 3; if (ip0 < 0) ip0 = 0; if (ip0 > Hh - PR) ip0 = Hh - PR;
    int jp0 = jt - 3; if (jp0 < 0) jp0 = 0; if (jp0 > Ww - PC) jp0 = Ww - PC;

    const int tid  = threadIdx.x;
    const int base = b * (Hh*Ww);
    const uint4* kv4 = (const uint4*)kv;

    // stage K and V naturally: [tok][dim]
    for (int f = tid; f < PTOK*8; f += 256) {
        int tok = f >> 3;
        int c   = f & 7;
        int r   = (tok*205) >> 11;        // tok / 10
        int cc  = tok - r*PC;
        int g   = base + (ip0 + r)*Ww + (jp0 + cc);
        if (c < 4) {
            *(uint4*)&Ks[tok*KSP + c*8] = kv4[(size_t)g*32 + h*4 + c];
        } else {
            int c2 = c - 4;
            *(uint4*)&Vs[tok*KSP + c2*8] = kv4[(size_t)g*32 + 16 + h*4 + c2];
        }
    }
    // zero pad rows (tokens 140..159) of Ks and Vs
    for (int f = tid; f < 200; f += 256) {
        int arr = f / 100;
        int f2  = f - arr*100;
        int row = PTOK + f2/5, cc = (f2 - (f2/5)*5)*8;
        uint4 z = make_uint4(0,0,0,0);
        if (arr == 0) *(uint4*)&Ks[row*KSP + cc] = z;
        else          *(uint4*)&Vs[row*KSP + cc] = z;
    }
    // stage Q (32 queries x 32 dims)
    for (int f = tid; f < 128; f += 256) {
        int qq = f >> 2, c = f & 3;
        int qi = qq >> 2, qj = qq & 3;
        int g = base + (it + qi)*Ww + (jt + qj);
        *(uint4*)&Qs[qq*QP + c*8] = ((const uint4*)q)[(size_t)g*16 + h*4 + c];
    }
    for (int f = tid; f < 169; f += 256) rs[f] = rpb[h*169 + f];
    __syncthreads();

    const int w    = tid >> 5;
    const int lane = tid & 31;
    const int a_row = lane & 15;
    const int a_k   = (lane >> 4) << 3;
    // non-trans B selectors (load from [n][k] layout)
    const int bn_row = (lane & 7) + ((lane >> 4) << 3);
    const int bk_col = ((lane >> 3) & 1) << 3;
    // trans B selectors (for V GEMM, [k][n] layout)
    const int b_k   = (lane & 7) + (((lane >> 3) & 1) << 3);

    const int m_base = (w >> 2) * 16;       // 2 m-warps
    const int warpN  = w & 3;               // 4 n-warps
    const int n_base = warpN * 40;

    // ---- score GEMM: Q[32x32] @ Ks^T -> 32x160, warp tile 16x40 ----
    float acc[5][4];
    {
        const unsigned qS = s2u(Qs), kS = s2u(Ks);
        #pragma unroll
        for (int nt = 0; nt < 5; nt++)
            #pragma unroll
            for (int e = 0; e < 4; e++) acc[nt][e] = 0.0f;

        #pragma unroll
        for (int kk = 0; kk < 32; kk += 16) {
            unsigned af[4], bf[5][2];
            unsigned addr = qS + ((m_base + a_row)*QP + kk + a_k)*2;
            asm volatile("ldmatrix.sync.aligned.m8n8.x4.shared.b16 {%0,%1,%2,%3}, [%4];"
                : "=r"(af[0]), "=r"(af[1]), "=r"(af[2]), "=r"(af[3]) : "r"(addr));
            #pragma unroll
            for (int np = 0; np < 2; np++) {
                unsigned r0, r1, r2, r3;
                addr = kS + ((n_base + np*16 + bn_row)*KSP + kk + bk_col)*2;
                asm volatile("ldmatrix.sync.aligned.m8n8.x4.shared.b16 {%0,%1,%2,%3}, [%4];"
                    : "=r"(r0), "=r"(r1), "=r"(r2), "=r"(r3) : "r"(addr));
                bf[2*np][0] = r0; bf[2*np][1] = r1;
                bf[2*np+1][0] = r2; bf[2*np+1][1] = r3;
            }
            {
                unsigned r0, r1;
                addr = kS + ((n_base + 32 + (lane & 7))*KSP + kk + bk_col)*2;
                asm volatile("ldmatrix.sync.aligned.m8n8.x2.shared.b16 {%0,%1}, [%2];"
                    : "=r"(r0), "=r"(r1) : "r"(addr));
                bf[4][0] = r0; bf[4][1] = r1;
            }
            #pragma unroll
            for (int nt = 0; nt < 5; nt++)
                asm volatile(
                    "mma.sync.aligned.m16n8k16.row.col.f32.bf16.bf16.f32 "
                    "{%0,%1,%2,%3}, {%4,%5,%6,%7}, {%8,%9}, {%0,%1,%2,%3};"
                    : "+f"(acc[nt][0]), "+f"(acc[nt][1]), "+f"(acc[nt][2]), "+f"(acc[nt][3])
                    : "r"(af[0]), "r"(af[1]), "r"(af[2]), "r"(af[3]),
                      "r"(bf[nt][0]), "r"(bf[nt][1]));
        }
    }

    // ---- fused epilogue: mask + rpb + exp + write bf16 P + row sums ----
    {
        const int row0 = m_base + (lane >> 2);       // query index 0..31
        const int row1 = row0 + 8;

        // per-row window info
        int gi0, gj0, io0, jo0, bi0, bj0;
        int gi1, gj1, io1, jo1, bi1, bj1;
        {
            int qi = row0 >> 2, qj = row0 & 3;
            gi0 = it + qi; gj0 = jt + qj;
            int i0 = gi0 - 3; if (i0 < 0) i0 = 0; if (i0 > Hh - Kk) i0 = Hh - Kk;
            int j0 = gj0 - 3; if (j0 < 0) j0 = 0; if (j0 > Ww - Kk) j0 = Ww - Kk;
            io0 = i0 - ip0; jo0 = j0 - jp0;
            bi0 = ip0 - gi0 + (Kk - 1); bj0 = jp0 - gj0 + (Kk - 1);
        }
        {
            int qi = row1 >> 2, qj = row1 & 3;
            gi1 = it + qi; gj1 = jt + qj;
            int i0 = gi1 - 3; if (i0 < 0) i0 = 0; if (i0 > Hh - Kk) i0 = Hh - Kk;
            int j0 = gj1 - 3; if (j0 < 0) j0 = 0; if (j0 > Ww - Kk) j0 = Ww - Kk;
            io1 = i0 - ip0; jo1 = j0 - jp0;
            bi1 = ip0 - gi1 + (Kk - 1); bj1 = jp0 - gj1 + (Kk - 1);
        }

        float s0 = 0.f, s1 = 0.f;
        #pragma unroll
        for (int nt = 0; nt < 5; nt++) {
            int colA = n_base + nt*8 + 2*(lane & 3);
            int tA = colA, tB = colA + 1;
            int rA = (tA*205) >> 11, cA = tA - rA*PC;
            int rB = (tB*205) >> 11, cB = tB - rB*PC;

            // row0
            float e00 = 0.f, e01 = 0.f;
            if (tA < PTOK && (unsigned)(rA - io0) < 7u && (unsigned)(cA - jo0) < 7u)
                e00 = __expf(acc[nt][0] + rs[(bi0 + rA)*13 + bj0 + cA]);
            if (tB < PTOK && (unsigned)(rB - io0) < 7u && (unsigned)(cB - jo0) < 7u)
                e01 = __expf(acc[nt][1] + rs[(bi0 + rB)*13 + bj0 + cB]);
            // row1
            float e10 = 0.f, e11 = 0.f;
            if (tA < PTOK && (unsigned)(rA - io1) < 7u && (unsigned)(cA - jo1) < 7u)
                e10 = __expf(acc[nt][2] + rs[(bi1 + rA)*13 + bj1 + cA]);
            if (tB < PTOK && (unsigned)(rB - io1) < 7u && (unsigned)(cB - jo1) < 7u)
                e11 = __expf(acc[nt][3] + rs[(bi1 + rB)*13 + bj1 + cB]);

            bf162 p0 = __float22bfloat162_rn(make_float2(e00, e01));
            bf162 p1 = __float22bfloat162_rn(make_float2(e10, e11));
            *(unsigned*)&Ps[row0*PP + colA] = *(unsigned*)&p0;
            *(unsigned*)&Ps[row1*PP + colA] = *(unsigned*)&p1;

            // sum the bf16-rounded values (exact normalization of stored P)
            float2 f0 = __bfloat1622float2(p0);
            float2 f1 = __bfloat1622float2(p1);
            s0 += f0.x + f0.y;
            s1 += f1.x + f1.y;
        }
        #pragma unroll
        for (int off = 1; off < 4; off <<= 1) {
            s0 += __shfl_xor_sync(0xffffffff, s0, off);
            s1 += __shfl_xor_sync(0xffffffff, s1, off);
        }
        if ((lane & 3) == 0) {
            part[row0*4 + warpN] = s0;
            part[row1*4 + warpN] = s1;
        }
    }
    __syncthreads();

    // ---- V GEMM: P[32x160] @ V[160x32], warp tile 16x8, k=160 ----
    {
        const int n_base2 = warpN * 8;
        const unsigned pS = s2u(Ps), vS = s2u(Vs);
        float acc2[4] = {0.f, 0.f, 0.f, 0.f};

        #pragma unroll
        for (int kt = 0; kt < 10; kt++) {
            int kk = kt*16;
            unsigned af[4];
            unsigned addr = pS + ((m_base + a_row)*PP + kk + a_k)*2;
            asm volatile("ldmatrix.sync.aligned.m8n8.x4.shared.b16 {%0,%1,%2,%3}, [%4];"
                : "=r"(af[0]), "=r"(af[1]), "=r"(af[2]), "=r"(af[3]) : "r"(addr));
            unsigned b0, b1;
            addr = vS + ((kk + b_k)*KSP + n_base2)*2;
            asm volatile("ldmatrix.sync.aligned.m8n8.x2.trans.shared.b16 {%0,%1}, [%2];"
                : "=r"(b0), "=r"(b1) : "r"(addr));
            asm volatile(
                "mma.sync.aligned.m16n8k16.row.col.f32.bf16.bf16.f32 "
                "{%0,%1,%2,%3}, {%4,%5,%6,%7}, {%8,%9}, {%0,%1,%2,%3};"
                : "+f"(acc2[0]), "+f"(acc2[1]), "+f"(acc2[2]), "+f"(acc2[3])
                : "r"(af[0]), "r"(af[1]), "r"(af[2]), "r"(af[3]),
                  "r"(b0), "r"(b1));
        }

        const int col = n_base2 + 2*(lane & 3);
        #pragma unroll
        for (int half = 0; half < 2; half++) {
            int qq = m_base + (lane >> 2) + half*8;
            float rinv = 1.0f / (part[qq*4+0] + part[qq*4+1] + part[qq*4+2] + part[qq*4+3]);
            int qi = qq >> 2, qj = qq & 3;
            int g = base + (it + qi)*Ww + (jt + qj);
            bf162 p = __float22bfloat162_rn(make_float2(acc2[half*2] * rinv,
                                                        acc2[half*2+1] * rinv));
            *(unsigned*)&out[(size_t)g*Cc + h*32 + col] = *(unsigned*)&p;
        }
    }
}

// ---------------------------------------------------------------------------
// Launch
// ---------------------------------------------------------------------------
extern "C" void kernel_launch(void* const* d_in, const int* in_sizes, int n_in,
                              void* d_out, int out_size)
{
    const float* query     = (const float*)d_in[0];
    const float* key_value = (const float*)d_in[1];
    const float* g1  = (const float*)d_in[2];
    const float* b1  = (const float*)d_in[3];
    const float* g2  = (const float*)d_in[4];
    const float* b2  = (const float*)d_in[5];
    const float* g3  = (const float*)d_in[6];
    const float* b3  = (const float*)d_in[7];
    const float* Wq  = (const float*)d_in[8];
    const float* bq  = (const float*)d_in[9];
    const float* Wkv = (const float*)d_in[10];
    const float* bkv = (const float*)d_in[11];
    const float* Wp  = (const float*)d_in[12];
    const float* bp  = (const float*)d_in[13];
    const float* rpb = (const float*)d_in[14];
    const float* W1  = (const float*)d_in[15];
    const float* bm1 = (const float*)d_in[16];
    const float* W2  = (const float*)d_in[17];
    const float* bm2 = (const float*)d_in[18];
    float* out = (float*)d_out;

    bf16*  qn     = nullptr; cudaGetSymbolAddress((void**)&qn,     g_qn);
    bf16*  kvn    = nullptr; cudaGetSymbolAddress((void**)&kvn,    g_kvn);
    bf16*  qbuf   = nullptr; cudaGetSymbolAddress((void**)&qbuf,   g_q);
    bf16*  kvbuf  = nullptr; cudaGetSymbolAddress((void**)&kvbuf,  g_kv);
    bf16*  attn   = nullptr; cudaGetSymbolAddress((void**)&attn,   g_attn);
    float* xbuf   = nullptr; cudaGetSymbolAddress((void**)&xbuf,   g_x);
    bf16*  hln    = nullptr; cudaGetSymbolAddress((void**)&hln,    g_hln);
    bf16*  hidden = nullptr; cudaGetSymbolAddress((void**)&hidden, g_hidden);
    bf16*  wpb    = nullptr; cudaGetSymbolAddress((void**)&wpb,    g_wp);
    bf16*  w1b    = nullptr; cudaGetSymbolAddress((void**)&w1b,    g_w1);
    bf16*  w2b    = nullptr; cudaGetSymbolAddress((void**)&w2b,    g_w2);

    const int k128_smem = (64 + 128) * KP * 2;   // 52224 B
    const int attn_smem = (2*NPAD*KSP + 32*PP + 32*QP) * 2 + (169 + 128) * 4; // ~40.1 KB

    static bool attr_set = false;
    if (!attr_set) {
        cudaFuncSetAttribute(qkv_k128,
                             cudaFuncAttributeMaxDynamicSharedMemorySize, k128_smem);
        cudaFuncSetAttribute(gemm_k128<3,0,1>,
                             cudaFuncAttributeMaxDynamicSharedMemorySize, k128_smem);
        cudaFuncSetAttribute(gemm_k128<2,1,0>,
                             cudaFuncAttributeMaxDynamicSharedMemorySize, k128_smem);
        cudaFuncSetAttribute(nat_attn5,
                             cudaFuncAttributeMaxDynamicSharedMemorySize, attn_smem);
        attr_set = true;
    }

    // 0) weight conversion
    cvt_weights<<<192, 256>>>(Wq, Wkv, Wp, W1, W2);

    // 1) LN1 + LN2 fused launch
    ln_dual<<<(2*NTOK*32)/256, 256>>>(query, g1, b1, qn, key_value, g2, b2, kvn);

    // 2) Fused Q + KV projections
    qkv_k128<<<dim3(3, NTOK/64), 256, k128_smem>>>(qn, kvn, bq, bkv, qbuf, kvbuf);

    // 3) Neighborhood attention (tensor-core, fused softmax)
    nat_attn5<<<Bq*(Hh/8)*(Ww/4)*NHh, 256, attn_smem>>>(qbuf, kvbuf, rpb, attn);

    // 4) Output projection + residual + fused LN3
    gemm_k128<3,0,1><<<dim3(1, NTOK/64), 256, k128_smem>>>(
        attn, wpb, bp, key_value, xbuf, Cc, 1.0f, g3, b3, hln);

    // 5) MLP
    gemm_k128<2,1,0><<<dim3(MLPD/128, NTOK/64), 256, k128_smem>>>(
        hln, w1b, bm1, nullptr, hidden, MLPD, 1.0f, nullptr, nullptr, nullptr);
    gemm_bf<3,0><<<dim3(Cc/128, NTOK/64), 256>>>(
        hidden, w2b, bm2, xbuf, out, NTOK, Cc, MLPD, 1.0f);
}

// round 14
// speedup vs baseline: 2.0468x; 1.0215x over previous
#include <cuda_runtime.h>
#include <cuda_bf16.h>
#include <cuda_fp16.h>
#include <math.h>

// Problem constants
#define Bq  4
#define Hh  64
#define Ww  64
#define Cc  128
#define NHh 4
#define Kk  7
#define HDd 32
#define MLPD 512
#define NTOK (Bq*Hh*Ww)   // 16384

typedef __nv_bfloat16  bf16;
typedef __nv_bfloat162 bf162;

// Scratch (device globals)
__device__ __align__(16) bf16  g_qn    [NTOK*Cc];
__device__ __align__(16) bf16  g_kvn   [NTOK*Cc];
__device__ __align__(16) bf16  g_q     [NTOK*Cc];
__device__ __align__(16) bf16  g_kv    [NTOK*2*Cc];   // K half bf16, V half f16
__device__ __align__(16) bf16  g_attn  [NTOK*Cc];
__device__ __align__(16) float g_x     [NTOK*Cc];
__device__ __align__(16) bf16  g_hln   [NTOK*Cc];
__device__ __align__(16) bf16  g_hidden[NTOK*MLPD];

// bf16 weights (converted once per launch)
__device__ __align__(16) bf16  g_wq [Cc*Cc];
__device__ __align__(16) bf16  g_wkv[Cc*2*Cc];
__device__ __align__(16) bf16  g_wp [Cc*Cc];
__device__ __align__(16) bf16  g_w1 [Cc*MLPD];
__device__ __align__(16) bf16  g_w2 [MLPD*Cc];

__device__ __forceinline__ unsigned s2u(const void* p) {
    return (unsigned)__cvta_generic_to_shared(p);
}

#define CP_ASYNC16(dst, src) \
    asm volatile("cp.async.ca.shared.global [%0], [%1], 16;" :: "r"(dst), "l"(src))

#define LOG2E 1.4426950408889634f

// ---------------------------------------------------------------------------
// Prep kernel: blocks [0,4096) = dual LayerNorm; blocks [4096,4288) = weight cvt
// ---------------------------------------------------------------------------
__global__ void prep_kernel(const float* __restrict__ in1, const float* __restrict__ gg1,
                            const float* __restrict__ bb1, bf16* __restrict__ out1,
                            const float* __restrict__ in2, const float* __restrict__ gg2,
                            const float* __restrict__ bb2, bf16* __restrict__ out2,
                            const float* __restrict__ Wq, const float* __restrict__ Wkv,
                            const float* __restrict__ Wp, const float* __restrict__ W1,
                            const float* __restrict__ W2)
{
    if (blockIdx.x >= 4096) {
        int i = (blockIdx.x - 4096) * 256 + threadIdx.x;   // 0..49151
        const float* src; bf16* dst; int off;
        if      (i < 4096)  { src = Wq;  dst = g_wq;  off = i; }
        else if (i < 12288) { src = Wkv; dst = g_wkv; off = i - 4096; }
        else if (i < 16384) { src = Wp;  dst = g_wp;  off = i - 12288; }
        else if (i < 32768) { src = W1;  dst = g_w1;  off = i - 16384; }
        else                { src = W2;  dst = g_w2;  off = i - 32768; }
        float4 v = ((const float4*)src)[off];
        bf162 lo = __float22bfloat162_rn(make_float2(v.x, v.y));
        bf162 hi = __float22bfloat162_rn(make_float2(v.z, v.w));
        uint2 pk; pk.x = *(unsigned*)&lo; pk.y = *(unsigned*)&hi;
        ((uint2*)dst)[off] = pk;
        return;
    }

    int w    = (blockIdx.x * blockDim.x + threadIdx.x) >> 5;
    int lane = threadIdx.x & 31;
    const float* in; const float* g; const float* b; bf16* out; int tok;
    if (w < NTOK) { in = in1; g = gg1; b = bb1; out = out1; tok = w; }
    else          { in = in2; g = gg2; b = bb2; out = out2; tok = w - NTOK; }

    const float4 v = *(const float4*)&in[(size_t)tok*Cc + lane*4];
    float s  = v.x + v.y + v.z + v.w;
    float sq = v.x*v.x + v.y*v.y + v.z*v.z + v.w*v.w;
    #pragma unroll
    for (int off = 16; off; off >>= 1) {
        s  += __shfl_xor_sync(0xffffffff, s,  off);
        sq += __shfl_xor_sync(0xffffffff, sq, off);
    }
    float mean = s * (1.0f/Cc);
    float var  = sq * (1.0f/Cc) - mean*mean;
    float inv  = rsqrtf(var + 1e-5f);

    const float4 gv = *(const float4*)&g[lane*4];
    const float4 bv = *(const float4*)&b[lane*4];
    bf162 o0 = __float22bfloat162_rn(make_float2((v.x-mean)*inv*gv.x + bv.x,
                                                 (v.y-mean)*inv*gv.y + bv.y));
    bf162 o1 = __float22bfloat162_rn(make_float2((v.z-mean)*inv*gv.z + bv.z,
                                                 (v.w-mean)*inv*gv.w + bv.w));
    uint2 pk; pk.x = *(unsigned*)&o0; pk.y = *(unsigned*)&o1;
    *(uint2*)&out[(size_t)tok*Cc + lane*4] = pk;
}

// ---------------------------------------------------------------------------
// MMA tile helper: one BK=32 slab (trans-B, [k][n] layout), bf16.
// ---------------------------------------------------------------------------
__device__ __forceinline__ void gemm_tile(
    unsigned aB, unsigned bB, int m_base, int n_base, int lane,
    float acc[8][4], int apitch, int bpitch)
{
    const int a_row_sel = lane & 15;
    const int a_k_sel   = (lane >> 4) << 3;
    const int b_k_sel   = (lane & 7) + (((lane >> 3) & 1) << 3);
    const int b_n_sel   = (lane >> 4) << 3;
    #pragma unroll
    for (int kk = 0; kk < 32; kk += 16) {
        unsigned af[4], bf[8][2];
        {
            unsigned addr = aB + ((m_base + a_row_sel)*apitch + kk + a_k_sel)*2;
            asm volatile("ldmatrix.sync.aligned.m8n8.x4.shared.b16 {%0,%1,%2,%3}, [%4];"
                : "=r"(af[0]), "=r"(af[1]), "=r"(af[2]), "=r"(af[3]) : "r"(addr));
        }
        #pragma unroll
        for (int np = 0; np < 4; np++) {
            unsigned r0, r1, r2, r3;
            unsigned addr = bB + ((kk + b_k_sel)*bpitch + n_base + np*16 + b_n_sel)*2;
            asm volatile("ldmatrix.sync.aligned.m8n8.x4.trans.shared.b16 {%0,%1,%2,%3}, [%4];"
                : "=r"(r0), "=r"(r1), "=r"(r2), "=r"(r3) : "r"(addr));
            bf[2*np  ][0] = r0; bf[2*np  ][1] = r1;
            bf[2*np+1][0] = r2; bf[2*np+1][1] = r3;
        }
        #pragma unroll
        for (int nt = 0; nt < 8; nt++)
            asm volatile(
                "mma.sync.aligned.m16n8k16.row.col.f32.bf16.bf16.f32 "
                "{%0,%1,%2,%3}, {%4,%5,%6,%7}, {%8,%9}, {%0,%1,%2,%3};"
                : "+f"(acc[nt][0]), "+f"(acc[nt][1]), "+f"(acc[nt][2]), "+f"(acc[nt][3])
                : "r"(af[0]), "r"(af[1]), "r"(af[2]), "r"(af[3]),
                  "r"(bf[nt][0]), "r"(bf[nt][1]));
    }
}

// ---------------------------------------------------------------------------
// Fully-staged K=128 GEMM (unchanged).
// ---------------------------------------------------------------------------
#define KP 136

template <int MODE, int OUTBF, int LNFUSE>
__global__ __launch_bounds__(256)
void gemm_k128(const bf16* __restrict__ A,
               const bf16* __restrict__ Wb,
               const float* __restrict__ bias,
               const float* __restrict__ res,
               void* __restrict__ Cout,
               int N, float scale,
               const float* __restrict__ lng,
               const float* __restrict__ lnb,
               bf16* __restrict__ lnout)
{
    extern __shared__ bf16 sm[];
    bf16* As = sm;
    bf16* Bs = sm + 64*KP;

    const int tid  = threadIdx.x;
    const int bm   = blockIdx.y * 64;
    const int bn   = blockIdx.x * 128;
    const int warp = tid >> 5;
    const int lane = tid & 31;
    const int g    = lane >> 2;
    const int t    = lane & 3;
    const int m_base = (warp >> 1) * 16;
    const int warpN  = warp & 1;
    const int n_base = warpN * 64;

    {
        const unsigned aS = s2u(As);
        #pragma unroll
        for (int i = 0; i < 4; i++) {
            int id = tid + i*256;
            int r = id >> 4, c = id & 15;
            CP_ASYNC16(aS + (r*KP + c*8)*2, A + (size_t)(bm + r)*Cc + c*8);
        }
        const unsigned bS = s2u(Bs);
        #pragma unroll
        for (int i = 0; i < 8; i++) {
            int id = tid + i*256;
            int r = id >> 4, c = id & 15;
            CP_ASYNC16(bS + (r*KP + c*8)*2, Wb + (size_t)r*N + bn + c*8);
        }
        asm volatile("cp.async.commit_group;");
    }

    float acc[8][4];
    #pragma unroll
    for (int nt = 0; nt < 8; nt++)
        #pragma unroll
        for (int e = 0; e < 4; e++) acc[nt][e] = 0.0f;

    asm volatile("cp.async.wait_group 0;");
    __syncthreads();

    const unsigned aS = s2u(As);
    const unsigned bS = s2u(Bs);
    #pragma unroll
    for (int kt = 0; kt < 4; kt++)
        gemm_tile(aS + kt*32*2, bS + (kt*32*KP)*2, m_base, n_base, lane, acc, KP, KP);

    float* Cf = (float*)Cout;
    bf16*  Cb = (bf16*)Cout;
    const int row0 = bm + m_base + g;
    const int row1 = row0 + 8;

    float s0 = 0.f, q0 = 0.f, s1 = 0.f, q1 = 0.f;
    float* vsm  = (float*)Bs;
    float* part = (float*)As;

    if (LNFUSE) __syncthreads();

    #pragma unroll
    for (int nt = 0; nt < 8; nt++) {
        int col = bn + n_base + nt*8 + 2*t;
        float b0 = bias[col], b1 = bias[col+1];
        float v00 = acc[nt][0] + b0;
        float v01 = acc[nt][1] + b1;
        float v10 = acc[nt][2] + b0;
        float v11 = acc[nt][3] + b1;
        if (MODE == 1) { v00 *= scale; v01 *= scale; v10 *= scale; v11 *= scale; }
        if (MODE == 2) {
            v00 = 0.5f*v00*(1.0f + erff(v00*0.70710678118654752f));
            v01 = 0.5f*v01*(1.0f + erff(v01*0.70710678118654752f));
            v10 = 0.5f*v10*(1.0f + erff(v10*0.70710678118654752f));
            v11 = 0.5f*v11*(1.0f + erff(v11*0.70710678118654752f));
        }
        if (MODE == 3) {
            float2 r0 = *(const float2*)&res[(size_t)row0*N + col];
            float2 r1 = *(const float2*)&res[(size_t)row1*N + col];
            v00 += r0.x; v01 += r0.y; v10 += r1.x; v11 += r1.y;
        }
        if (OUTBF) {
            bf162 p0 = __float22bfloat162_rn(make_float2(v00, v01));
            bf162 p1 = __float22bfloat162_rn(make_float2(v10, v11));
            *(unsigned*)&Cb[(size_t)row0*N + col] = *(unsigned*)&p0;
            *(unsigned*)&Cb[(size_t)row1*N + col] = *(unsigned*)&p1;
        } else {
            *(float2*)&Cf[(size_t)row0*N + col] = make_float2(v00, v01);
            *(float2*)&Cf[(size_t)row1*N + col] = make_float2(v10, v11);
        }
        if (LNFUSE) {
            int lc = n_base + nt*8 + 2*t;
            int lr0 = m_base + g, lr1 = lr0 + 8;
            vsm[lr0*132 + lc] = v00; vsm[lr0*132 + lc + 1] = v01;
            vsm[lr1*132 + lc] = v10; vsm[lr1*132 + lc + 1] = v11;
            s0 += v00 + v01;  q0 += v00*v00 + v01*v01;
            s1 += v10 + v11;  q1 += v10*v10 + v11*v11;
        }
    }

    if (LNFUSE) {
        #pragma unroll
        for (int off = 1; off < 4; off <<= 1) {
            s0 += __shfl_xor_sync(0xffffffff, s0, off);
            q0 += __shfl_xor_sync(0xffffffff, q0, off);
            s1 += __shfl_xor_sync(0xffffffff, s1, off);
            q1 += __shfl_xor_sync(0xffffffff, q1, off);
        }
        int lr0 = m_base + g, lr1 = lr0 + 8;
        if (t == 0) {
            *(float2*)&part[(lr0*2 + warpN)*2] = make_float2(s0, q0);
            *(float2*)&part[(lr1*2 + warpN)*2] = make_float2(s1, q1);
        }
        __syncthreads();

        float2 a0 = *(float2*)&part[(lr0*2 + 0)*2];
        float2 a1 = *(float2*)&part[(lr0*2 + 1)*2];
        float2 c0 = *(float2*)&part[(lr1*2 + 0)*2];
        float2 c1 = *(float2*)&part[(lr1*2 + 1)*2];
        float m0 = (a0.x + a1.x) * (1.0f/Cc);
        float v0 = (a0.y + a1.y) * (1.0f/Cc) - m0*m0;
        float i0 = rsqrtf(v0 + 1e-5f);
        float m1 = (c0.x + c1.x) * (1.0f/Cc);
        float v1 = (c0.y + c1.y) * (1.0f/Cc) - m1*m1;
        float i1 = rsqrtf(v1 + 1e-5f);

        #pragma unroll
        for (int nt = 0; nt < 8; nt++) {
            int lc  = n_base + nt*8 + 2*t;
            int col = bn + lc;
            float gg0 = lng[col], gg1b = lng[col+1];
            float bb0 = lnb[col], bb1 = lnb[col+1];
            float x00 = vsm[lr0*132 + lc], x01 = vsm[lr0*132 + lc + 1];
            float x10 = vsm[lr1*132 + lc], x11 = vsm[lr1*132 + lc + 1];
            bf162 p0 = __float22bfloat162_rn(make_float2((x00-m0)*i0*gg0 + bb0,
                                                         (x01-m0)*i0*gg1b + bb1));
            bf162 p1 = __float22bfloat162_rn(make_float2((x10-m1)*i1*gg0 + bb0,
                                                         (x11-m1)*i1*gg1b + bb1));
            *(unsigned*)&lnout[(size_t)row0*N + col] = *(unsigned*)&p0;
            *(unsigned*)&lnout[(size_t)row1*N + col] = *(unsigned*)&p1;
        }
    }
}

// ---------------------------------------------------------------------------
// Fused Q + KV projection, fully staged (K=128).
// cb 0 -> Q (scaled by HD^-0.5 * log2e, bf16), cb 1 -> K (bf16), cb 2 -> V (f16)
// ---------------------------------------------------------------------------
__global__ __launch_bounds__(256)
void qkv_k128(const bf16* __restrict__ qn, const bf16* __restrict__ kvn,
              const float* __restrict__ bq, const float* __restrict__ bkv,
              bf16* __restrict__ qout, bf16* __restrict__ kvout)
{
    extern __shared__ bf16 sm[];
    bf16* As = sm;
    bf16* Bs = sm + 64*KP;

    const int cb = blockIdx.x;
    const bool isQ = (cb == 0);
    const bf16*  A    = isQ ? qn : kvn;
    const bf16*  Wb   = isQ ? g_wq : g_wkv;
    const float* bias = isQ ? bq : bkv;
    bf16*        Cb   = isQ ? qout : kvout;
    const int N  = isQ ? Cc : 2*Cc;
    const int bn = isQ ? 0 : (cb - 1) * 128;

    const int tid  = threadIdx.x;
    const int bm   = blockIdx.y * 64;
    const int warp = tid >> 5;
    const int lane = tid & 31;
    const int g    = lane >> 2;
    const int t    = lane & 3;
    const int m_base = (warp >> 1) * 16;
    const int n_base = (warp & 1) * 64;

    {
        const unsigned aS = s2u(As);
        #pragma unroll
        for (int i = 0; i < 4; i++) {
            int id = tid + i*256;
            int r = id >> 4, c = id & 15;
            CP_ASYNC16(aS + (r*KP + c*8)*2, A + (size_t)(bm + r)*Cc + c*8);
        }
        const unsigned bS = s2u(Bs);
        #pragma unroll
        for (int i = 0; i < 8; i++) {
            int id = tid + i*256;
            int r = id >> 4, c = id & 15;
            CP_ASYNC16(bS + (r*KP + c*8)*2, Wb + (size_t)r*N + bn + c*8);
        }
        asm volatile("cp.async.commit_group;");
    }

    float acc[8][4];
    #pragma unroll
    for (int nt = 0; nt < 8; nt++)
        #pragma unroll
        for (int e = 0; e < 4; e++) acc[nt][e] = 0.0f;

    asm volatile("cp.async.wait_group 0;");
    __syncthreads();

    const unsigned aS = s2u(As);
    const unsigned bS = s2u(Bs);
    #pragma unroll
    for (int kt = 0; kt < 4; kt++)
        gemm_tile(aS + kt*32*2, bS + (kt*32*KP)*2, m_base, n_base, lane, acc, KP, KP);

    // Q scale includes log2e so attention exps run in the exp2 domain.
    const float scale = 0.17677669529663689f * LOG2E;
    int row0 = bm + m_base + g;
    int row1 = row0 + 8;
    #pragma unroll
    for (int nt = 0; nt < 8; nt++) {
        int col = bn + n_base + nt*8 + 2*t;
        float b0 = bias[col], b1 = bias[col+1];
        float v00 = acc[nt][0] + b0;
        float v01 = acc[nt][1] + b1;
        float v10 = acc[nt][2] + b0;
        float v11 = acc[nt][3] + b1;
        if (isQ) { v00 *= scale; v01 *= scale; v10 *= scale; v11 *= scale; }
        if (cb == 2) {
            // V half -> f16
            __half2 p0 = __floats2half2_rn(v00, v01);
            __half2 p1 = __floats2half2_rn(v10, v11);
            *(unsigned*)&Cb[(size_t)row0*N + col] = *(unsigned*)&p0;
            *(unsigned*)&Cb[(size_t)row1*N + col] = *(unsigned*)&p1;
        } else {
            bf162 p0 = __float22bfloat162_rn(make_float2(v00, v01));
            bf162 p1 = __float22bfloat162_rn(make_float2(v10, v11));
            *(unsigned*)&Cb[(size_t)row0*N + col] = *(unsigned*)&p0;
            *(unsigned*)&Cb[(size_t)row1*N + col] = *(unsigned*)&p1;
        }
    }
}

// ---------------------------------------------------------------------------
// Ring-pipelined GEMM for K=512 (MLP second layer). (unchanged)
// ---------------------------------------------------------------------------
#define APITCH 40
#define BPITCH 136
#define NSTAGE 3

template <int MODE, int OUTBF>
__global__ __launch_bounds__(256)
void gemm_bf(const bf16* __restrict__ A,
             const bf16* __restrict__ Wb,
             const float* __restrict__ bias,
             const float* __restrict__ res,
             void* __restrict__ Cout,
             int M, int N, int K, float scale)
{
    __shared__ bf16 As[NSTAGE][64*APITCH];
    __shared__ bf16 Bs[NSTAGE][32*BPITCH];

    const int tid  = threadIdx.x;
    const int bm   = blockIdx.y * 64;
    const int bn   = blockIdx.x * 128;
    const int warp = tid >> 5;
    const int lane = tid & 31;
    const int g    = lane >> 2;
    const int t    = lane & 3;
    const int m_base = (warp >> 1) * 16;
    const int n_base = (warp & 1) * 64;

    const int a_r = tid >> 2, a_c = tid & 3;
    const int b_r0 = tid >> 4, b_c = tid & 15;
    const int b_r1 = b_r0 + 16;

    const bf16* Ag = A  + (size_t)bm * K;
    const bf16* Bg = Wb + bn;

    const unsigned aS = s2u(&As[0][0]);
    const unsigned bS = s2u(&Bs[0][0]);
    const unsigned aBufSz = 64*APITCH*2;
    const unsigned bBufSz = 32*BPITCH*2;
    const unsigned ad = aS + (a_r*APITCH + a_c*8)*2;
    const unsigned bd0 = bS + (b_r0*BPITCH + b_c*8)*2;
    const unsigned bd1 = bS + (b_r1*BPITCH + b_c*8)*2;

    float acc[8][4];
    #pragma unroll
    for (int nt = 0; nt < 8; nt++)
        #pragma unroll
        for (int e = 0; e < 4; e++) acc[nt][e] = 0.0f;

    const int ntile = K / 32;

    auto stage = [&](int buf, int kt) {
        CP_ASYNC16(ad  + buf*aBufSz, Ag + (size_t)a_r*K + kt*32 + a_c*8);
        CP_ASYNC16(bd0 + buf*bBufSz, Bg + (size_t)(kt*32 + b_r0)*N + b_c*8);
        CP_ASYNC16(bd1 + buf*bBufSz, Bg + (size_t)(kt*32 + b_r1)*N + b_c*8);
        asm volatile("cp.async.commit_group;");
    };

    stage(0, 0);
    if (ntile > 1) stage(1, 1);

    for (int kt = 0; kt < ntile; kt++) {
        if (kt + 1 < ntile) asm volatile("cp.async.wait_group 1;");
        else                asm volatile("cp.async.wait_group 0;");
        __syncthreads();
        if (kt + 2 < ntile) stage((kt + 2) % NSTAGE, kt + 2);
        const int cur = kt % NSTAGE;
        gemm_tile(aS + cur*aBufSz, bS + cur*bBufSz, m_base, n_base, lane, acc,
                  APITCH, BPITCH);
        __syncthreads();
    }

    float* Cf = (float*)Cout;
    bf16*  Cb = (bf16*)Cout;
    int row0 = bm + m_base + g;
    int row1 = row0 + 8;
    #pragma unroll
    for (int nt = 0; nt < 8; nt++) {
        int col = bn + n_base + nt*8 + 2*t;
        float b0 = bias[col], b1 = bias[col+1];
        float v00 = acc[nt][0] + b0;
        float v01 = acc[nt][1] + b1;
        float v10 = acc[nt][2] + b0;
        float v11 = acc[nt][3] + b1;
        if (MODE == 1) { v00 *= scale; v01 *= scale; v10 *= scale; v11 *= scale; }
        if (MODE == 2) {
            v00 = 0.5f*v00*(1.0f + erff(v00*0.70710678118654752f));
            v01 = 0.5f*v01*(1.0f + erff(v01*0.70710678118654752f));
            v10 = 0.5f*v10*(1.0f + erff(v10*0.70710678118654752f));
            v11 = 0.5f*v11*(1.0f + erff(v11*0.70710678118654752f));
        }
        if (MODE == 3) {
            float2 r0 = *(const float2*)&res[(size_t)row0*N + col];
            float2 r1 = *(const float2*)&res[(size_t)row1*N + col];
            v00 += r0.x; v01 += r0.y; v10 += r1.x; v11 += r1.y;
        }
        if (OUTBF) {
            bf162 p0 = __float22bfloat162_rn(make_float2(v00, v01));
            bf162 p1 = __float22bfloat162_rn(make_float2(v10, v11));
            *(unsigned*)&Cb[(size_t)row0*N + col] = *(unsigned*)&p0;
            *(unsigned*)&Cb[(size_t)row1*N + col] = *(unsigned*)&p1;
        } else {
            *(float2*)&Cf[(size_t)row0*N + col] = make_float2(v00, v01);
            *(float2*)&Cf[(size_t)row1*N + col] = make_float2(v10, v11);
        }
    }
}

// ---------------------------------------------------------------------------
// Neighborhood attention v6: tensor-core + paired f16 exp2 (halved MUFU).
// One block = 8x4 query tile x ONE head.
//  - scores already in exp2 domain (Q pre-scaled by log2e; rpb scaled at stage)
//  - epilogue: mask -> pack pair to f16x2 -> h2exp2 (1 MUFU / 2 elems) -> P f16
//  - V is f16 (from qkv), P@V via f16 MMA.
// ---------------------------------------------------------------------------
#define PR 14
#define PC 10
#define PTOK 140
#define NPAD 160
#define KSP 40      // Ks/Vs pitch: [160 toks][32 dims + pad]
#define PP  168     // P pitch:  [32 q][160 toks + pad]
#define QP  40      // Qs pitch: [32 q][32 dims + pad]

__global__ __launch_bounds__(256)
void nat_attn6(const bf16* __restrict__ q,
               const bf16* __restrict__ kv,
               const float* __restrict__ rpb,
               bf16* __restrict__ out)
{
    extern __shared__ char smc[];
    bf16*   Ks = (bf16*)smc;                      // [160][40] (pad rows garbage, masked)
    __half* Vs = (__half*)(Ks + NPAD*KSP);        // [160][40] f16, pad rows zeroed
    __half* Ps = (__half*)(Vs + NPAD*KSP);        // [32][168] f16
    bf16*   Qs = (bf16*)(Ps + 32*PP);             // [32][40]
    float*  rs   = (float*)(Qs + 32*QP);          // [169] (scaled by log2e)
    float*  part = rs + 169;                      // [32][4]

    const int blk = blockIdx.x;
    const int h   = blk & 3;
    const int r2  = blk >> 2;
    const int b   = r2 >> 7;
    const int rem = r2 & 127;
    const int it  = (rem >> 4) << 3;
    const int jt  = (rem & 15) << 2;

    int ip0 = it - 3; if (ip0 < 0) ip0 = 0; if (ip0 > Hh - PR) ip0 = Hh - PR;
    int jp0 = jt - 3; if (jp0 < 0) jp0 = 0; if (jp0 > Ww - PC) jp0 = Ww - PC;

    const int tid  = threadIdx.x;
    const int base = b * (Hh*Ww);
    const uint4* kv4 = (const uint4*)kv;

    // stage K (bf16) and V (f16) naturally: [tok][dim]
    for (int f = tid; f < PTOK*8; f += 256) {
        int tok = f >> 3;
        int c   = f & 7;
        int r   = (tok*205) >> 11;        // tok / 10
        int cc  = tok - r*PC;
        int g   = base + (ip0 + r)*Ww + (jp0 + cc);
        if (c < 4) {
            *(uint4*)&Ks[tok*KSP + c*8] = kv4[(size_t)g*32 + h*4 + c];
        } else {
            int c2 = c - 4;
            *(uint4*)&Vs[tok*KSP + c2*8] = kv4[(size_t)g*32 + 16 + h*4 + c2];
        }
    }
    // zero V pad rows only (P pad cols are exact 0, but 0*NaN != 0)
    for (int f = tid; f < 100; f += 256) {
        int row = PTOK + f/5, cc = (f - (f/5)*5)*8;
        uint4 z = make_uint4(0,0,0,0);
        *(uint4*)&Vs[row*KSP + cc] = z;
    }
    // stage Q
    for (int f = tid; f < 128; f += 256) {
        int qq = f >> 2, c = f & 3;
        int qi = qq >> 2, qj = qq & 3;
        int g = base + (it + qi)*Ww + (jt + qj);
        *(uint4*)&Qs[qq*QP + c*8] = ((const uint4*)q)[(size_t)g*16 + h*4 + c];
    }
    for (int f = tid; f < 169; f += 256) rs[f] = rpb[h*169 + f] * LOG2E;
    __syncthreads();

    const int w    = tid >> 5;
    const int lane = tid & 31;
    const int a_row = lane & 15;
    const int a_k   = (lane >> 4) << 3;
    const int bn_row = (lane & 7) + ((lane >> 4) << 3);
    const int bk_col = ((lane >> 3) & 1) << 3;
    const int b_k   = (lane & 7) + (((lane >> 3) & 1) << 3);

    const int m_base = (w >> 2) * 16;
    const int warpN  = w & 3;
    const int n_base = warpN * 40;

    // ---- score GEMM: Q[32x32] @ Ks^T -> 32x160, warp tile 16x40 ----
    float acc[5][4];
    {
        const unsigned qS = s2u(Qs), kS = s2u(Ks);
        #pragma unroll
        for (int nt = 0; nt < 5; nt++)
            #pragma unroll
            for (int e = 0; e < 4; e++) acc[nt][e] = 0.0f;

        #pragma unroll
        for (int kk = 0; kk < 32; kk += 16) {
            unsigned af[4], bf[5][2];
            unsigned addr = qS + ((m_base + a_row)*QP + kk + a_k)*2;
            asm volatile("ldmatrix.sync.aligned.m8n8.x4.shared.b16 {%0,%1,%2,%3}, [%4];"
                : "=r"(af[0]), "=r"(af[1]), "=r"(af[2]), "=r"(af[3]) : "r"(addr));
            #pragma unroll
            for (int np = 0; np < 2; np++) {
                unsigned r0, r1, r2, r3;
                addr = kS + ((n_base + np*16 + bn_row)*KSP + kk + bk_col)*2;
                asm volatile("ldmatrix.sync.aligned.m8n8.x4.shared.b16 {%0,%1,%2,%3}, [%4];"
                    : "=r"(r0), "=r"(r1), "=r"(r2), "=r"(r3) : "r"(addr));
                bf[2*np][0] = r0; bf[2*np][1] = r1;
                bf[2*np+1][0] = r2; bf[2*np+1][1] = r3;
            }
            {
                unsigned r0, r1;
                addr = kS + ((n_base + 32 + (lane & 7))*KSP + kk + bk_col)*2;
                asm volatile("ldmatrix.sync.aligned.m8n8.x2.shared.b16 {%0,%1}, [%2];"
                    : "=r"(r0), "=r"(r1) : "r"(addr));
                bf[4][0] = r0; bf[4][1] = r1;
            }
            #pragma unroll
            for (int nt = 0; nt < 5; nt++)
                asm volatile(
                    "mma.sync.aligned.m16n8k16.row.col.f32.bf16.bf16.f32 "
                    "{%0,%1,%2,%3}, {%4,%5,%6,%7}, {%8,%9}, {%0,%1,%2,%3};"
                    : "+f"(acc[nt][0]), "+f"(acc[nt][1]), "+f"(acc[nt][2]), "+f"(acc[nt][3])
                    : "r"(af[0]), "r"(af[1]), "r"(af[2]), "r"(af[3]),
                      "r"(bf[nt][0]), "r"(bf[nt][1]));
        }
    }

    // ---- fused epilogue: mask + bias + exp2 (f16x2 pairs) + P f16 + row sums ----
    {
        const int row0 = m_base + (lane >> 2);
        const int row1 = row0 + 8;

        int io0, jo0, bi0, bj0, io1, jo1, bi1, bj1;
        {
            int qi = row0 >> 2, qj = row0 & 3;
            int gi = it + qi, gj = jt + qj;
            int i0 = gi - 3; if (i0 < 0) i0 = 0; if (i0 > Hh - Kk) i0 = Hh - Kk;
            int j0 = gj - 3; if (j0 < 0) j0 = 0; if (j0 > Ww - Kk) j0 = Ww - Kk;
            io0 = i0 - ip0; jo0 = j0 - jp0;
            bi0 = ip0 - gi + (Kk - 1); bj0 = jp0 - gj + (Kk - 1);
        }
        {
            int qi = row1 >> 2, qj = row1 & 3;
            int gi = it + qi, gj = jt + qj;
            int i0 = gi - 3; if (i0 < 0) i0 = 0; if (i0 > Hh - Kk) i0 = Hh - Kk;
            int j0 = gj - 3; if (j0 < 0) j0 = 0; if (j0 > Ww - Kk) j0 = Ww - Kk;
            io1 = i0 - ip0; jo1 = j0 - jp0;
            bi1 = ip0 - gi + (Kk - 1); bj1 = jp0 - gj + (Kk - 1);
        }

        float s0 = 0.f, s1 = 0.f;
        #pragma unroll
        for (int nt = 0; nt < 5; nt++) {
            int colA = n_base + nt*8 + 2*(lane & 3);
            int tA = colA, tB = colA + 1;
            int rA = (tA*205) >> 11, cA = tA - rA*PC;
            int rB = (tB*205) >> 11, cB = tB - rB*PC;
            bool inA = (tA < PTOK), inB = (tB < PTOK);

            // row0
            {
                bool vA = inA && (unsigned)(rA - io0) < 7u && (unsigned)(cA - jo0) < 7u;
                bool vB = inB && (unsigned)(rB - io0) < 7u && (unsigned)(cB - jo0) < 7u;
                unsigned pk = 0u;
                if (vA | vB) {
                    float y0 = vA ? acc[nt][0] + rs[(bi0 + rA)*13 + bj0 + cA] : -88.f;
                    float y1 = vB ? acc[nt][1] + rs[(bi0 + rB)*13 + bj0 + cB] : -88.f;
                    __half2 e2 = h2exp2(__floats2half2_rn(y0, y1));
                    pk = *(unsigned*)&e2;
                    float2 f = __half22float2(e2);
                    s0 += f.x + f.y;
                }
                *(unsigned*)&Ps[row0*PP + colA] = pk;
            }
            // row1
            {
                bool vA = inA && (unsigned)(rA - io1) < 7u && (unsigned)(cA - jo1) < 7u;
                bool vB = inB && (unsigned)(rB - io1) < 7u && (unsigned)(cB - jo1) < 7u;
                unsigned pk = 0u;
                if (vA | vB) {
                    float y0 = vA ? acc[nt][2] + rs[(bi1 + rA)*13 + bj1 + cA] : -88.f;
                    float y1 = vB ? acc[nt][3] + rs[(bi1 + rB)*13 + bj1 + cB] : -88.f;
                    __half2 e2 = h2exp2(__floats2half2_rn(y0, y1));
                    pk = *(unsigned*)&e2;
                    float2 f = __half22float2(e2);
                    s1 += f.x + f.y;
                }
                *(unsigned*)&Ps[row1*PP + colA] = pk;
            }
        }
        #pragma unroll
        for (int off = 1; off < 4; off <<= 1) {
            s0 += __shfl_xor_sync(0xffffffff, s0, off);
            s1 += __shfl_xor_sync(0xffffffff, s1, off);
        }
        if ((lane & 3) == 0) {
            part[row0*4 + warpN] = s0;
            part[row1*4 + warpN] = s1;
        }
    }
    __syncthreads();

    // ---- V GEMM: P[32x160](f16) @ V[160x32](f16), warp tile 16x8, k=160 ----
    {
        const int n_base2 = warpN * 8;
        const unsigned pS = s2u(Ps), vS = s2u(Vs);
        float acc2[4] = {0.f, 0.f, 0.f, 0.f};

        #pragma unroll
        for (int kt = 0; kt < 10; kt++) {
            int kk = kt*16;
            unsigned af[4];
            unsigned addr = pS + ((m_base + a_row)*PP + kk + a_k)*2;
            asm volatile("ldmatrix.sync.aligned.m8n8.x4.shared.b16 {%0,%1,%2,%3}, [%4];"
                : "=r"(af[0]), "=r"(af[1]), "=r"(af[2]), "=r"(af[3]) : "r"(addr));
            unsigned b0, b1;
            addr = vS + ((kk + b_k)*KSP + n_base2)*2;
            asm volatile("ldmatrix.sync.aligned.m8n8.x2.trans.shared.b16 {%0,%1}, [%2];"
                : "=r"(b0), "=r"(b1) : "r"(addr));
            asm volatile(
                "mma.sync.aligned.m16n8k16.row.col.f32.f16.f16.f32 "
                "{%0,%1,%2,%3}, {%4,%5,%6,%7}, {%8,%9}, {%0,%1,%2,%3};"
                : "+f"(acc2[0]), "+f"(acc2[1]), "+f"(acc2[2]), "+f"(acc2[3])
                : "r"(af[0]), "r"(af[1]), "r"(af[2]), "r"(af[3]),
                  "r"(b0), "r"(b1));
        }

        const int col = n_base2 + 2*(lane & 3);
        #pragma unroll
        for (int half = 0; half < 2; half++) {
            int qq = m_base + (lane >> 2) + half*8;
            float rinv = 1.0f / (part[qq*4+0] + part[qq*4+1] + part[qq*4+2] + part[qq*4+3]);
            int qi = qq >> 2, qj = qq & 3;
            int g = base + (it + qi)*Ww + (jt + qj);
            bf162 p = __float22bfloat162_rn(make_float2(acc2[half*2] * rinv,
                                                        acc2[half*2+1] * rinv));
            *(unsigned*)&out[(size_t)g*Cc + h*32 + col] = *(unsigned*)&p;
        }
    }
}

// ---------------------------------------------------------------------------
// Launch
// ---------------------------------------------------------------------------
extern "C" void kernel_launch(void* const* d_in, const int* in_sizes, int n_in,
                              void* d_out, int out_size)
{
    const float* query     = (const float*)d_in[0];
    const float* key_value = (const float*)d_in[1];
    const float* g1  = (const float*)d_in[2];
    const float* b1  = (const float*)d_in[3];
    const float* g2  = (const float*)d_in[4];
    const float* b2  = (const float*)d_in[5];
    const float* g3  = (const float*)d_in[6];
    const float* b3  = (const float*)d_in[7];
    const float* Wq  = (const float*)d_in[8];
    const float* bq  = (const float*)d_in[9];
    const float* Wkv = (const float*)d_in[10];
    const float* bkv = (const float*)d_in[11];
    const float* Wp  = (const float*)d_in[12];
    const float* bp  = (const float*)d_in[13];
    const float* rpb = (const float*)d_in[14];
    const float* W1  = (const float*)d_in[15];
    const float* bm1 = (const float*)d_in[16];
    const float* W2  = (const float*)d_in[17];
    const float* bm2 = (const float*)d_in[18];
    float* out = (float*)d_out;

    bf16*  qn     = nullptr; cudaGetSymbolAddress((void**)&qn,     g_qn);
    bf16*  kvn    = nullptr; cudaGetSymbolAddress((void**)&kvn,    g_kvn);
    bf16*  qbuf   = nullptr; cudaGetSymbolAddress((void**)&qbuf,   g_q);
    bf16*  kvbuf  = nullptr; cudaGetSymbolAddress((void**)&kvbuf,  g_kv);
    bf16*  attn   = nullptr; cudaGetSymbolAddress((void**)&attn,   g_attn);
    float* xbuf   = nullptr; cudaGetSymbolAddress((void**)&xbuf,   g_x);
    bf16*  hln    = nullptr; cudaGetSymbolAddress((void**)&hln,    g_hln);
    bf16*  hidden = nullptr; cudaGetSymbolAddress((void**)&hidden, g_hidden);
    bf16*  wpb    = nullptr; cudaGetSymbolAddress((void**)&wpb,    g_wp);
    bf16*  w1b    = nullptr; cudaGetSymbolAddress((void**)&w1b,    g_w1);
    bf16*  w2b    = nullptr; cudaGetSymbolAddress((void**)&w2b,    g_w2);

    const int k128_smem = (64 + 128) * KP * 2;   // 52224 B
    const int attn_smem = (2*NPAD*KSP + 32*PP + 32*QP) * 2 + (169 + 128) * 4; // ~40.1 KB

    static bool attr_set = false;
    if (!attr_set) {
        cudaFuncSetAttribute(qkv_k128,
                             cudaFuncAttributeMaxDynamicSharedMemorySize, k128_smem);
        cudaFuncSetAttribute(gemm_k128<3,0,1>,
                             cudaFuncAttributeMaxDynamicSharedMemorySize, k128_smem);
        cudaFuncSetAttribute(gemm_k128<2,1,0>,
                             cudaFuncAttributeMaxDynamicSharedMemorySize, k128_smem);
        cudaFuncSetAttribute(nat_attn6,
                             cudaFuncAttributeMaxDynamicSharedMemorySize, attn_smem);
        attr_set = true;
    }

    // 1) LN1 + LN2 + weight conversion in ONE launch
    prep_kernel<<<4288, 256>>>(query, g1, b1, qn, key_value, g2, b2, kvn,
                               Wq, Wkv, Wp, W1, W2);

    // 2) Fused Q + KV projections (Q pre-scaled with log2e; V written as f16)
    qkv_k128<<<dim3(3, NTOK/64), 256, k128_smem>>>(qn, kvn, bq, bkv, qbuf, kvbuf);

    // 3) Neighborhood attention (tensor-core, paired f16 exp2)
    nat_attn6<<<Bq*(Hh/8)*(Ww/4)*NHh, 256, attn_smem>>>(qbuf, kvbuf, rpb, attn);

    // 4) Output projection + residual + fused LN3
    gemm_k128<3,0,1><<<dim3(1, NTOK/64), 256, k128_smem>>>(
        attn, wpb, bp, key_value, xbuf, Cc, 1.0f, g3, b3, hln);

    // 5) MLP
    gemm_k128<2,1,0><<<dim3(MLPD/128, NTOK/64), 256, k128_smem>>>(
        hln, w1b, bm1, nullptr, hidden, MLPD, 1.0f, nullptr, nullptr, nullptr);
    gemm_bf<3,0><<<dim3(Cc/128, NTOK/64), 256>>>(
        hidden, w2b, bm2, xbuf, out, NTOK, Cc, MLPD, 1.0f);
}

// round 15
// speedup vs baseline: 2.1568x; 1.0537x over previous
#include <cuda_runtime.h>
#include <cuda_bf16.h>
#include <cuda_fp16.h>
#include <math.h>

// Problem constants
#define Bq  4
#define Hh  64
#define Ww  64
#define Cc  128
#define NHh 4
#define Kk  7
#define HDd 32
#define MLPD 512
#define NTOK (Bq*Hh*Ww)   // 16384

typedef __nv_bfloat16  bf16;
typedef __nv_bfloat162 bf162;

// Scratch (device globals)
__device__ __align__(16) bf16  g_qn    [NTOK*Cc];
__device__ __align__(16) bf16  g_kvn   [NTOK*Cc];
__device__ __align__(16) bf16  g_q     [NTOK*Cc];
__device__ __align__(16) bf16  g_kv    [NTOK*2*Cc];   // K half bf16, V half f16
__device__ __align__(16) bf16  g_attn  [NTOK*Cc];
__device__ __align__(16) float g_x     [NTOK*Cc];
__device__ __align__(16) bf16  g_hln   [NTOK*Cc];

// bf16 weights (converted once per launch)
__device__ __align__(16) bf16  g_wq [Cc*Cc];
__device__ __align__(16) bf16  g_wkv[Cc*2*Cc];
__device__ __align__(16) bf16  g_wp [Cc*Cc];
__device__ __align__(16) bf16  g_w1 [Cc*MLPD];
__device__ __align__(16) bf16  g_w2 [MLPD*Cc];

__device__ __forceinline__ unsigned s2u(const void* p) {
    return (unsigned)__cvta_generic_to_shared(p);
}

#define CP_ASYNC16(dst, src) \
    asm volatile("cp.async.ca.shared.global [%0], [%1], 16;" :: "r"(dst), "l"(src))

#define LOG2E 1.4426950408889634f

// ---------------------------------------------------------------------------
// Prep kernel: blocks [0,4096) = dual LayerNorm; blocks [4096,4288) = weight cvt
// ---------------------------------------------------------------------------
__global__ void prep_kernel(const float* __restrict__ in1, const float* __restrict__ gg1,
                            const float* __restrict__ bb1, bf16* __restrict__ out1,
                            const float* __restrict__ in2, const float* __restrict__ gg2,
                            const float* __restrict__ bb2, bf16* __restrict__ out2,
                            const float* __restrict__ Wq, const float* __restrict__ Wkv,
                            const float* __restrict__ Wp, const float* __restrict__ W1,
                            const float* __restrict__ W2)
{
    if (blockIdx.x >= 4096) {
        int i = (blockIdx.x - 4096) * 256 + threadIdx.x;   // 0..49151
        const float* src; bf16* dst; int off;
        if      (i < 4096)  { src = Wq;  dst = g_wq;  off = i; }
        else if (i < 12288) { src = Wkv; dst = g_wkv; off = i - 4096; }
        else if (i < 16384) { src = Wp;  dst = g_wp;  off = i - 12288; }
        else if (i < 32768) { src = W1;  dst = g_w1;  off = i - 16384; }
        else                { src = W2;  dst = g_w2;  off = i - 32768; }
        float4 v = ((const float4*)src)[off];
        bf162 lo = __float22bfloat162_rn(make_float2(v.x, v.y));
        bf162 hi = __float22bfloat162_rn(make_float2(v.z, v.w));
        uint2 pk; pk.x = *(unsigned*)&lo; pk.y = *(unsigned*)&hi;
        ((uint2*)dst)[off] = pk;
        return;
    }

    int w    = (blockIdx.x * blockDim.x + threadIdx.x) >> 5;
    int lane = threadIdx.x & 31;
    const float* in; const float* g; const float* b; bf16* out; int tok;
    if (w < NTOK) { in = in1; g = gg1; b = bb1; out = out1; tok = w; }
    else          { in = in2; g = gg2; b = bb2; out = out2; tok = w - NTOK; }

    const float4 v = *(const float4*)&in[(size_t)tok*Cc + lane*4];
    float s  = v.x + v.y + v.z + v.w;
    float sq = v.x*v.x + v.y*v.y + v.z*v.z + v.w*v.w;
    #pragma unroll
    for (int off = 16; off; off >>= 1) {
        s  += __shfl_xor_sync(0xffffffff, s,  off);
        sq += __shfl_xor_sync(0xffffffff, sq, off);
    }
    float mean = s * (1.0f/Cc);
    float var  = sq * (1.0f/Cc) - mean*mean;
    float inv  = rsqrtf(var + 1e-5f);

    const float4 gv = *(const float4*)&g[lane*4];
    const float4 bv = *(const float4*)&b[lane*4];
    bf162 o0 = __float22bfloat162_rn(make_float2((v.x-mean)*inv*gv.x + bv.x,
                                                 (v.y-mean)*inv*gv.y + bv.y));
    bf162 o1 = __float22bfloat162_rn(make_float2((v.z-mean)*inv*gv.z + bv.z,
                                                 (v.w-mean)*inv*gv.w + bv.w));
    uint2 pk; pk.x = *(unsigned*)&o0; pk.y = *(unsigned*)&o1;
    *(uint2*)&out[(size_t)tok*Cc + lane*4] = pk;
}

// ---------------------------------------------------------------------------
// MMA tile helper: one BK=32 slab (trans-B, [k][n] layout), bf16.
// ---------------------------------------------------------------------------
__device__ __forceinline__ void gemm_tile(
    unsigned aB, unsigned bB, int m_base, int n_base, int lane,
    float acc[8][4], int apitch, int bpitch)
{
    const int a_row_sel = lane & 15;
    const int a_k_sel   = (lane >> 4) << 3;
    const int b_k_sel   = (lane & 7) + (((lane >> 3) & 1) << 3);
    const int b_n_sel   = (lane >> 4) << 3;
    #pragma unroll
    for (int kk = 0; kk < 32; kk += 16) {
        unsigned af[4], bf[8][2];
        {
            unsigned addr = aB + ((m_base + a_row_sel)*apitch + kk + a_k_sel)*2;
            asm volatile("ldmatrix.sync.aligned.m8n8.x4.shared.b16 {%0,%1,%2,%3}, [%4];"
                : "=r"(af[0]), "=r"(af[1]), "=r"(af[2]), "=r"(af[3]) : "r"(addr));
        }
        #pragma unroll
        for (int np = 0; np < 4; np++) {
            unsigned r0, r1, r2, r3;
            unsigned addr = bB + ((kk + b_k_sel)*bpitch + n_base + np*16 + b_n_sel)*2;
            asm volatile("ldmatrix.sync.aligned.m8n8.x4.trans.shared.b16 {%0,%1,%2,%3}, [%4];"
                : "=r"(r0), "=r"(r1), "=r"(r2), "=r"(r3) : "r"(addr));
            bf[2*np  ][0] = r0; bf[2*np  ][1] = r1;
            bf[2*np+1][0] = r2; bf[2*np+1][1] = r3;
        }
        #pragma unroll
        for (int nt = 0; nt < 8; nt++)
            asm volatile(
                "mma.sync.aligned.m16n8k16.row.col.f32.bf16.bf16.f32 "
                "{%0,%1,%2,%3}, {%4,%5,%6,%7}, {%8,%9}, {%0,%1,%2,%3};"
                : "+f"(acc[nt][0]), "+f"(acc[nt][1]), "+f"(acc[nt][2]), "+f"(acc[nt][3])
                : "r"(af[0]), "r"(af[1]), "r"(af[2]), "r"(af[3]),
                  "r"(bf[nt][0]), "r"(bf[nt][1]));
    }
}

// ---------------------------------------------------------------------------
// Fully-staged K=128 GEMM (proj + residual + fused LN3).
// ---------------------------------------------------------------------------
#define KP 136

template <int MODE, int OUTBF, int LNFUSE>
__global__ __launch_bounds__(256)
void gemm_k128(const bf16* __restrict__ A,
               const bf16* __restrict__ Wb,
               const float* __restrict__ bias,
               const float* __restrict__ res,
               void* __restrict__ Cout,
               int N, float scale,
               const float* __restrict__ lng,
               const float* __restrict__ lnb,
               bf16* __restrict__ lnout)
{
    extern __shared__ bf16 sm[];
    bf16* As = sm;
    bf16* Bs = sm + 64*KP;

    const int tid  = threadIdx.x;
    const int bm   = blockIdx.y * 64;
    const int bn   = blockIdx.x * 128;
    const int warp = tid >> 5;
    const int lane = tid & 31;
    const int g    = lane >> 2;
    const int t    = lane & 3;
    const int m_base = (warp >> 1) * 16;
    const int warpN  = warp & 1;
    const int n_base = warpN * 64;

    {
        const unsigned aS = s2u(As);
        #pragma unroll
        for (int i = 0; i < 4; i++) {
            int id = tid + i*256;
            int r = id >> 4, c = id & 15;
            CP_ASYNC16(aS + (r*KP + c*8)*2, A + (size_t)(bm + r)*Cc + c*8);
        }
        const unsigned bS = s2u(Bs);
        #pragma unroll
        for (int i = 0; i < 8; i++) {
            int id = tid + i*256;
            int r = id >> 4, c = id & 15;
            CP_ASYNC16(bS + (r*KP + c*8)*2, Wb + (size_t)r*N + bn + c*8);
        }
        asm volatile("cp.async.commit_group;");
    }

    float acc[8][4];
    #pragma unroll
    for (int nt = 0; nt < 8; nt++)
        #pragma unroll
        for (int e = 0; e < 4; e++) acc[nt][e] = 0.0f;

    asm volatile("cp.async.wait_group 0;");
    __syncthreads();

    const unsigned aS = s2u(As);
    const unsigned bS = s2u(Bs);
    #pragma unroll
    for (int kt = 0; kt < 4; kt++)
        gemm_tile(aS + kt*32*2, bS + (kt*32*KP)*2, m_base, n_base, lane, acc, KP, KP);

    float* Cf = (float*)Cout;
    bf16*  Cb = (bf16*)Cout;
    const int row0 = bm + m_base + g;
    const int row1 = row0 + 8;

    float s0 = 0.f, q0 = 0.f, s1 = 0.f, q1 = 0.f;
    float* vsm  = (float*)Bs;
    float* part = (float*)As;

    if (LNFUSE) __syncthreads();

    #pragma unroll
    for (int nt = 0; nt < 8; nt++) {
        int col = bn + n_base + nt*8 + 2*t;
        float b0 = bias[col], b1 = bias[col+1];
        float v00 = acc[nt][0] + b0;
        float v01 = acc[nt][1] + b1;
        float v10 = acc[nt][2] + b0;
        float v11 = acc[nt][3] + b1;
        if (MODE == 1) { v00 *= scale; v01 *= scale; v10 *= scale; v11 *= scale; }
        if (MODE == 2) {
            v00 = 0.5f*v00*(1.0f + erff(v00*0.70710678118654752f));
            v01 = 0.5f*v01*(1.0f + erff(v01*0.70710678118654752f));
            v10 = 0.5f*v10*(1.0f + erff(v10*0.70710678118654752f));
            v11 = 0.5f*v11*(1.0f + erff(v11*0.70710678118654752f));
        }
        if (MODE == 3) {
            float2 r0 = *(const float2*)&res[(size_t)row0*N + col];
            float2 r1 = *(const float2*)&res[(size_t)row1*N + col];
            v00 += r0.x; v01 += r0.y; v10 += r1.x; v11 += r1.y;
        }
        if (OUTBF) {
            bf162 p0 = __float22bfloat162_rn(make_float2(v00, v01));
            bf162 p1 = __float22bfloat162_rn(make_float2(v10, v11));
            *(unsigned*)&Cb[(size_t)row0*N + col] = *(unsigned*)&p0;
            *(unsigned*)&Cb[(size_t)row1*N + col] = *(unsigned*)&p1;
        } else {
            *(float2*)&Cf[(size_t)row0*N + col] = make_float2(v00, v01);
            *(float2*)&Cf[(size_t)row1*N + col] = make_float2(v10, v11);
        }
        if (LNFUSE) {
            int lc = n_base + nt*8 + 2*t;
            int lr0 = m_base + g, lr1 = lr0 + 8;
            vsm[lr0*132 + lc] = v00; vsm[lr0*132 + lc + 1] = v01;
            vsm[lr1*132 + lc] = v10; vsm[lr1*132 + lc + 1] = v11;
            s0 += v00 + v01;  q0 += v00*v00 + v01*v01;
            s1 += v10 + v11;  q1 += v10*v10 + v11*v11;
        }
    }

    if (LNFUSE) {
        #pragma unroll
        for (int off = 1; off < 4; off <<= 1) {
            s0 += __shfl_xor_sync(0xffffffff, s0, off);
            q0 += __shfl_xor_sync(0xffffffff, q0, off);
            s1 += __shfl_xor_sync(0xffffffff, s1, off);
            q1 += __shfl_xor_sync(0xffffffff, q1, off);
        }
        int lr0 = m_base + g, lr1 = lr0 + 8;
        if (t == 0) {
            *(float2*)&part[(lr0*2 + warpN)*2] = make_float2(s0, q0);
            *(float2*)&part[(lr1*2 + warpN)*2] = make_float2(s1, q1);
        }
        __syncthreads();

        float2 a0 = *(float2*)&part[(lr0*2 + 0)*2];
        float2 a1 = *(float2*)&part[(lr0*2 + 1)*2];
        float2 c0 = *(float2*)&part[(lr1*2 + 0)*2];
        float2 c1 = *(float2*)&part[(lr1*2 + 1)*2];
        float m0 = (a0.x + a1.x) * (1.0f/Cc);
        float v0 = (a0.y + a1.y) * (1.0f/Cc) - m0*m0;
        float i0 = rsqrtf(v0 + 1e-5f);
        float m1 = (c0.x + c1.x) * (1.0f/Cc);
        float v1 = (c0.y + c1.y) * (1.0f/Cc) - m1*m1;
        float i1 = rsqrtf(v1 + 1e-5f);

        #pragma unroll
        for (int nt = 0; nt < 8; nt++) {
            int lc  = n_base + nt*8 + 2*t;
            int col = bn + lc;
            float gg0 = lng[col], gg1b = lng[col+1];
            float bb0 = lnb[col], bb1 = lnb[col+1];
            float x00 = vsm[lr0*132 + lc], x01 = vsm[lr0*132 + lc + 1];
            float x10 = vsm[lr1*132 + lc], x11 = vsm[lr1*132 + lc + 1];
            bf162 p0 = __float22bfloat162_rn(make_float2((x00-m0)*i0*gg0 + bb0,
                                                         (x01-m0)*i0*gg1b + bb1));
            bf162 p1 = __float22bfloat162_rn(make_float2((x10-m1)*i1*gg0 + bb0,
                                                         (x11-m1)*i1*gg1b + bb1));
            *(unsigned*)&lnout[(size_t)row0*N + col] = *(unsigned*)&p0;
            *(unsigned*)&lnout[(size_t)row1*N + col] = *(unsigned*)&p1;
        }
    }
}

// ---------------------------------------------------------------------------
// Fused Q + KV projection, fully staged (K=128).
// cb 0 -> Q (scaled by HD^-0.5 * log2e, bf16), cb 1 -> K (bf16), cb 2 -> V (f16)
// ---------------------------------------------------------------------------
__global__ __launch_bounds__(256)
void qkv_k128(const bf16* __restrict__ qn, const bf16* __restrict__ kvn,
              const float* __restrict__ bq, const float* __restrict__ bkv,
              bf16* __restrict__ qout, bf16* __restrict__ kvout)
{
    extern __shared__ bf16 sm[];
    bf16* As = sm;
    bf16* Bs = sm + 64*KP;

    const int cb = blockIdx.x;
    const bool isQ = (cb == 0);
    const bf16*  A    = isQ ? qn : kvn;
    const bf16*  Wb   = isQ ? g_wq : g_wkv;
    const float* bias = isQ ? bq : bkv;
    bf16*        Cb   = isQ ? qout : kvout;
    const int N  = isQ ? Cc : 2*Cc;
    const int bn = isQ ? 0 : (cb - 1) * 128;

    const int tid  = threadIdx.x;
    const int bm   = blockIdx.y * 64;
    const int warp = tid >> 5;
    const int lane = tid & 31;
    const int g    = lane >> 2;
    const int t    = lane & 3;
    const int m_base = (warp >> 1) * 16;
    const int n_base = (warp & 1) * 64;

    {
        const unsigned aS = s2u(As);
        #pragma unroll
        for (int i = 0; i < 4; i++) {
            int id = tid + i*256;
            int r = id >> 4, c = id & 15;
            CP_ASYNC16(aS + (r*KP + c*8)*2, A + (size_t)(bm + r)*Cc + c*8);
        }
        const unsigned bS = s2u(Bs);
        #pragma unroll
        for (int i = 0; i < 8; i++) {
            int id = tid + i*256;
            int r = id >> 4, c = id & 15;
            CP_ASYNC16(bS + (r*KP + c*8)*2, Wb + (size_t)r*N + bn + c*8);
        }
        asm volatile("cp.async.commit_group;");
    }

    float acc[8][4];
    #pragma unroll
    for (int nt = 0; nt < 8; nt++)
        #pragma unroll
        for (int e = 0; e < 4; e++) acc[nt][e] = 0.0f;

    asm volatile("cp.async.wait_group 0;");
    __syncthreads();

    const unsigned aS = s2u(As);
    const unsigned bS = s2u(Bs);
    #pragma unroll
    for (int kt = 0; kt < 4; kt++)
        gemm_tile(aS + kt*32*2, bS + (kt*32*KP)*2, m_base, n_base, lane, acc, KP, KP);

    // Q scale includes log2e so attention exps run in the exp2 domain.
    const float scale = 0.17677669529663689f * LOG2E;
    int row0 = bm + m_base + g;
    int row1 = row0 + 8;
    #pragma unroll
    for (int nt = 0; nt < 8; nt++) {
        int col = bn + n_base + nt*8 + 2*t;
        float b0 = bias[col], b1 = bias[col+1];
        float v00 = acc[nt][0] + b0;
        float v01 = acc[nt][1] + b1;
        float v10 = acc[nt][2] + b0;
        float v11 = acc[nt][3] + b1;
        if (isQ) { v00 *= scale; v01 *= scale; v10 *= scale; v11 *= scale; }
        if (cb == 2) {
            __half2 p0 = __floats2half2_rn(v00, v01);
            __half2 p1 = __floats2half2_rn(v10, v11);
            *(unsigned*)&Cb[(size_t)row0*N + col] = *(unsigned*)&p0;
            *(unsigned*)&Cb[(size_t)row1*N + col] = *(unsigned*)&p1;
        } else {
            bf162 p0 = __float22bfloat162_rn(make_float2(v00, v01));
            bf162 p1 = __float22bfloat162_rn(make_float2(v10, v11));
            *(unsigned*)&Cb[(size_t)row0*N + col] = *(unsigned*)&p0;
            *(unsigned*)&Cb[(size_t)row1*N + col] = *(unsigned*)&p1;
        }
    }
}

// ---------------------------------------------------------------------------
// Fused MLP: out = xres + gelu(hln @ W1 + bm1) @ W2 + bm2, hidden never
// leaves the CTA. Per 64-row CTA: 4 chunk-steps of (phase A: 64x128x128
// GEMM + gelu -> Hc smem; phase B: accumulate Hc @ W2chunk into registers).
// W1/W2 chunks stream through a double-buffered cp.async ring.
// smem: As 64x136 + Hc 64x136 + 2 x (128x136) = 104448 B.
// ---------------------------------------------------------------------------
__global__ __launch_bounds__(256)
void mlp_fused(const bf16* __restrict__ hln,
               const float* __restrict__ bm1,
               const float* __restrict__ bm2,
               const float* __restrict__ xres,
               float* __restrict__ out)
{
    extern __shared__ bf16 sm[];
    bf16* As  = sm;                    // [64][136]
    bf16* Hc  = sm + 64*KP;            // [64][136]
    bf16* Wb0 = sm + 128*KP;           // [128][136]
    bf16* Wb1 = sm + 256*KP;           // [128][136]

    const int tid  = threadIdx.x;
    const int bm   = blockIdx.x * 64;
    const int warp = tid >> 5;
    const int lane = tid & 31;
    const int g    = lane >> 2;
    const int t    = lane & 3;
    const int m_base = (warp >> 1) * 16;
    const int n_base = (warp & 1) * 64;

    const unsigned aS = s2u(As);
    const unsigned hS = s2u(Hc);
    const unsigned wS0 = s2u(Wb0);
    const unsigned wS1 = s2u(Wb1);

    // stage A (hln tile 64x128) + chunk 0 (W1 cols 0..127) as group 0
    #pragma unroll
    for (int i = 0; i < 4; i++) {
        int id = tid + i*256;
        int r = id >> 4, c = id & 15;
        CP_ASYNC16(aS + (r*KP + c*8)*2, hln + (size_t)(bm + r)*Cc + c*8);
    }
    #pragma unroll
    for (int i = 0; i < 8; i++) {
        int id = tid + i*256;
        int r = id >> 4, c = id & 15;
        CP_ASYNC16(wS0 + (r*KP + c*8)*2, g_w1 + (size_t)r*MLPD + c*8);
    }
    asm volatile("cp.async.commit_group;");

    float accB[8][4];
    #pragma unroll
    for (int nt = 0; nt < 8; nt++)
        #pragma unroll
        for (int e = 0; e < 4; e++) accB[nt][e] = 0.0f;

    #pragma unroll
    for (int step = 0; step < 8; step++) {
        // prefetch next chunk into the other buffer
        const int nxt = step + 1;
        if (nxt < 8) {
            const int cc = nxt >> 1;
            const unsigned dst = (nxt & 1) ? wS1 : wS0;
            if ((nxt & 1) == 0) {
                // W1 chunk cc: rows 0..127 (k), cols cc*128..+127 of N=512
                #pragma unroll
                for (int i = 0; i < 8; i++) {
                    int id = tid + i*256;
                    int r = id >> 4, c = id & 15;
                    CP_ASYNC16(dst + (r*KP + c*8)*2,
                               g_w1 + (size_t)r*MLPD + cc*128 + c*8);
                }
            } else {
                // W2 chunk cc: rows cc*128..+127 (k), cols 0..127 of N=128
                #pragma unroll
                for (int i = 0; i < 8; i++) {
                    int id = tid + i*256;
                    int r = id >> 4, c = id & 15;
                    CP_ASYNC16(dst + (r*KP + c*8)*2,
                               g_w2 + (size_t)(cc*128 + r)*Cc + c*8);
                }
            }
            asm volatile("cp.async.commit_group;");
            asm volatile("cp.async.wait_group 1;");
        } else {
            asm volatile("cp.async.wait_group 0;");
        }
        __syncthreads();

        const unsigned wS = (step & 1) ? wS1 : wS0;
        if ((step & 1) == 0) {
            // phase A: accA = As @ W1chunk, gelu -> Hc
            const int cc = step >> 1;
            float accA[8][4];
            #pragma unroll
            for (int nt = 0; nt < 8; nt++)
                #pragma unroll
                for (int e = 0; e < 4; e++) accA[nt][e] = 0.0f;
            #pragma unroll
            for (int kt = 0; kt < 4; kt++)
                gemm_tile(aS + kt*32*2, wS + (kt*32*KP)*2, m_base, n_base, lane,
                          accA, KP, KP);

            const int lr0 = m_base + g, lr1 = lr0 + 8;
            #pragma unroll
            for (int nt = 0; nt < 8; nt++) {
                int lc  = n_base + nt*8 + 2*t;
                int col = cc*128 + lc;
                float b0 = bm1[col], b1 = bm1[col+1];
                float v00 = accA[nt][0] + b0;
                float v01 = accA[nt][1] + b1;
                float v10 = accA[nt][2] + b0;
                float v11 = accA[nt][3] + b1;
                v00 = 0.5f*v00*(1.0f + erff(v00*0.70710678118654752f));
                v01 = 0.5f*v01*(1.0f + erff(v01*0.70710678118654752f));
                v10 = 0.5f*v10*(1.0f + erff(v10*0.70710678118654752f));
                v11 = 0.5f*v11*(1.0f + erff(v11*0.70710678118654752f));
                bf162 p0 = __float22bfloat162_rn(make_float2(v00, v01));
                bf162 p1 = __float22bfloat162_rn(make_float2(v10, v11));
                *(unsigned*)&Hc[lr0*KP + lc] = *(unsigned*)&p0;
                *(unsigned*)&Hc[lr1*KP + lc] = *(unsigned*)&p1;
            }
            __syncthreads();   // Hc ready for phase B
        } else {
            // phase B: accB += Hc @ W2chunk
            #pragma unroll
            for (int kt = 0; kt < 4; kt++)
                gemm_tile(hS + kt*32*2, wS + (kt*32*KP)*2, m_base, n_base, lane,
                          accB, KP, KP);
            __syncthreads();   // protect Hc / W buffers before reuse
        }
    }

    // final epilogue: out = accB + bm2 + xres (fp32)
    const int row0 = bm + m_base + g;
    const int row1 = row0 + 8;
    #pragma unroll
    for (int nt = 0; nt < 8; nt++) {
        int col = n_base + nt*8 + 2*t;
        float b0 = bm2[col], b1 = bm2[col+1];
        float2 r0 = *(const float2*)&xres[(size_t)row0*Cc + col];
        float2 r1 = *(const float2*)&xres[(size_t)row1*Cc + col];
        *(float2*)&out[(size_t)row0*Cc + col] =
            make_float2(accB[nt][0] + b0 + r0.x, accB[nt][1] + b1 + r0.y);
        *(float2*)&out[(size_t)row1*Cc + col] =
            make_float2(accB[nt][2] + b0 + r1.x, accB[nt][3] + b1 + r1.y);
    }
}

// ---------------------------------------------------------------------------
// Neighborhood attention v6 (unchanged from round 14).
// ---------------------------------------------------------------------------
#define PR 14
#define PC 10
#define PTOK 140
#define NPAD 160
#define KSP 40
#define PP  168
#define QP  40

__global__ __launch_bounds__(256)
void nat_attn6(const bf16* __restrict__ q,
               const bf16* __restrict__ kv,
               const float* __restrict__ rpb,
               bf16* __restrict__ out)
{
    extern __shared__ char smc[];
    bf16*   Ks = (bf16*)smc;
    __half* Vs = (__half*)(Ks + NPAD*KSP);
    __half* Ps = (__half*)(Vs + NPAD*KSP);
    bf16*   Qs = (bf16*)(Ps + 32*PP);
    float*  rs   = (float*)(Qs + 32*QP);
    float*  part = rs + 169;

    const int blk = blockIdx.x;
    const int h   = blk & 3;
    const int r2  = blk >> 2;
    const int b   = r2 >> 7;
    const int rem = r2 & 127;
    const int it  = (rem >> 4) << 3;
    const int jt  = (rem & 15) << 2;

    int ip0 = it - 3; if (ip0 < 0) ip0 = 0; if (ip0 > Hh - PR) ip0 = Hh - PR;
    int jp0 = jt - 3; if (jp0 < 0) jp0 = 0; if (jp0 > Ww - PC) jp0 = Ww - PC;

    const int tid  = threadIdx.x;
    const int base = b * (Hh*Ww);
    const uint4* kv4 = (const uint4*)kv;

    for (int f = tid; f < PTOK*8; f += 256) {
        int tok = f >> 3;
        int c   = f & 7;
        int r   = (tok*205) >> 11;
        int cc  = tok - r*PC;
        int g   = base + (ip0 + r)*Ww + (jp0 + cc);
        if (c < 4) {
            *(uint4*)&Ks[tok*KSP + c*8] = kv4[(size_t)g*32 + h*4 + c];
        } else {
            int c2 = c - 4;
            *(uint4*)&Vs[tok*KSP + c2*8] = kv4[(size_t)g*32 + 16 + h*4 + c2];
        }
    }
    for (int f = tid; f < 100; f += 256) {
        int row = PTOK + f/5, cc = (f - (f/5)*5)*8;
        uint4 z = make_uint4(0,0,0,0);
        *(uint4*)&Vs[row*KSP + cc] = z;
    }
    for (int f = tid; f < 128; f += 256) {
        int qq = f >> 2, c = f & 3;
        int qi = qq >> 2, qj = qq & 3;
        int g = base + (it + qi)*Ww + (jt + qj);
        *(uint4*)&Qs[qq*QP + c*8] = ((const uint4*)q)[(size_t)g*16 + h*4 + c];
    }
    for (int f = tid; f < 169; f += 256) rs[f] = rpb[h*169 + f] * LOG2E;
    __syncthreads();

    const int w    = tid >> 5;
    const int lane = tid & 31;
    const int a_row = lane & 15;
    const int a_k   = (lane >> 4) << 3;
    const int bn_row = (lane & 7) + ((lane >> 4) << 3);
    const int bk_col = ((lane >> 3) & 1) << 3;
    const int b_k   = (lane & 7) + (((lane >> 3) & 1) << 3);

    const int m_base = (w >> 2) * 16;
    const int warpN  = w & 3;
    const int n_base = warpN * 40;

    float acc[5][4];
    {
        const unsigned qS = s2u(Qs), kS = s2u(Ks);
        #pragma unroll
        for (int nt = 0; nt < 5; nt++)
            #pragma unroll
            for (int e = 0; e < 4; e++) acc[nt][e] = 0.0f;

        #pragma unroll
        for (int kk = 0; kk < 32; kk += 16) {
            unsigned af[4], bf[5][2];
            unsigned addr = qS + ((m_base + a_row)*QP + kk + a_k)*2;
            asm volatile("ldmatrix.sync.aligned.m8n8.x4.shared.b16 {%0,%1,%2,%3}, [%4];"
                : "=r"(af[0]), "=r"(af[1]), "=r"(af[2]), "=r"(af[3]) : "r"(addr));
            #pragma unroll
            for (int np = 0; np < 2; np++) {
                unsigned r0, r1, r2, r3;
                addr = kS + ((n_base + np*16 + bn_row)*KSP + kk + bk_col)*2;
                asm volatile("ldmatrix.sync.aligned.m8n8.x4.shared.b16 {%0,%1,%2,%3}, [%4];"
                    : "=r"(r0), "=r"(r1), "=r"(r2), "=r"(r3) : "r"(addr));
                bf[2*np][0] = r0; bf[2*np][1] = r1;
                bf[2*np+1][0] = r2; bf[2*np+1][1] = r3;
            }
            {
                unsigned r0, r1;
                addr = kS + ((n_base + 32 + (lane & 7))*KSP + kk + bk_col)*2;
                asm volatile("ldmatrix.sync.aligned.m8n8.x2.shared.b16 {%0,%1}, [%2];"
                    : "=r"(r0), "=r"(r1) : "r"(addr));
                bf[4][0] = r0; bf[4][1] = r1;
            }
            #pragma unroll
            for (int nt = 0; nt < 5; nt++)
                asm volatile(
                    "mma.sync.aligned.m16n8k16.row.col.f32.bf16.bf16.f32 "
                    "{%0,%1,%2,%3}, {%4,%5,%6,%7}, {%8,%9}, {%0,%1,%2,%3};"
                    : "+f"(acc[nt][0]), "+f"(acc[nt][1]), "+f"(acc[nt][2]), "+f"(acc[nt][3])
                    : "r"(af[0]), "r"(af[1]), "r"(af[2]), "r"(af[3]),
                      "r"(bf[nt][0]), "r"(bf[nt][1]));
        }
    }

    {
        const int row0 = m_base + (lane >> 2);
        const int row1 = row0 + 8;

        int io0, jo0, bi0, bj0, io1, jo1, bi1, bj1;
        {
            int qi = row0 >> 2, qj = row0 & 3;
            int gi = it + qi, gj = jt + qj;
            int i0 = gi - 3; if (i0 < 0) i0 = 0; if (i0 > Hh - Kk) i0 = Hh - Kk;
            int j0 = gj - 3; if (j0 < 0) j0 = 0; if (j0 > Ww - Kk) j0 = Ww - Kk;
            io0 = i0 - ip0; jo0 = j0 - jp0;
            bi0 = ip0 - gi + (Kk - 1); bj0 = jp0 - gj + (Kk - 1);
        }
        {
            int qi = row1 >> 2, qj = row1 & 3;
            int gi = it + qi, gj = jt + qj;
            int i0 = gi - 3; if (i0 < 0) i0 = 0; if (i0 > Hh - Kk) i0 = Hh - Kk;
            int j0 = gj - 3; if (j0 < 0) j0 = 0; if (j0 > Ww - Kk) j0 = Ww - Kk;
            io1 = i0 - ip0; jo1 = j0 - jp0;
            bi1 = ip0 - gi + (Kk - 1); bj1 = jp0 - gj + (Kk - 1);
        }

        float s0 = 0.f, s1 = 0.f;
        #pragma unroll
        for (int nt = 0; nt < 5; nt++) {
            int colA = n_base + nt*8 + 2*(lane & 3);
            int tA = colA, tB = colA + 1;
            int rA = (tA*205) >> 11, cA = tA - rA*PC;
            int rB = (tB*205) >> 11, cB = tB - rB*PC;
            bool inA = (tA < PTOK), inB = (tB < PTOK);

            {
                bool vA = inA && (unsigned)(rA - io0) < 7u && (unsigned)(cA - jo0) < 7u;
                bool vB = inB && (unsigned)(rB - io0) < 7u && (unsigned)(cB - jo0) < 7u;
                unsigned pk = 0u;
                if (vA | vB) {
                    float y0 = vA ? acc[nt][0] + rs[(bi0 + rA)*13 + bj0 + cA] : -88.f;
                    float y1 = vB ? acc[nt][1] + rs[(bi0 + rB)*13 + bj0 + cB] : -88.f;
                    __half2 e2 = h2exp2(__floats2half2_rn(y0, y1));
                    pk = *(unsigned*)&e2;
                    float2 f = __half22float2(e2);
                    s0 += f.x + f.y;
                }
                *(unsigned*)&Ps[row0*PP + colA] = pk;
            }
            {
                bool vA = inA && (unsigned)(rA - io1) < 7u && (unsigned)(cA - jo1) < 7u;
                bool vB = inB && (unsigned)(rB - io1) < 7u && (unsigned)(cB - jo1) < 7u;
                unsigned pk = 0u;
                if (vA | vB) {
                    float y0 = vA ? acc[nt][2] + rs[(bi1 + rA)*13 + bj1 + cA] : -88.f;
                    float y1 = vB ? acc[nt][3] + rs[(bi1 + rB)*13 + bj1 + cB] : -88.f;
                    __half2 e2 = h2exp2(__floats2half2_rn(y0, y1));
                    pk = *(unsigned*)&e2;
                    float2 f = __half22float2(e2);
                    s1 += f.x + f.y;
                }
                *(unsigned*)&Ps[row1*PP + colA] = pk;
            }
        }
        #pragma unroll
        for (int off = 1; off < 4; off <<= 1) {
            s0 += __shfl_xor_sync(0xffffffff, s0, off);
            s1 += __shfl_xor_sync(0xffffffff, s1, off);
        }
        if ((lane & 3) == 0) {
            part[row0*4 + warpN] = s0;
            part[row1*4 + warpN] = s1;
        }
    }
    __syncthreads();

    {
        const int n_base2 = warpN * 8;
        const unsigned pS = s2u(Ps), vS = s2u(Vs);
        float acc2[4] = {0.f, 0.f, 0.f, 0.f};

        #pragma unroll
        for (int kt = 0; kt < 10; kt++) {
            int kk = kt*16;
            unsigned af[4];
            unsigned addr = pS + ((m_base + a_row)*PP + kk + a_k)*2;
            asm volatile("ldmatrix.sync.aligned.m8n8.x4.shared.b16 {%0,%1,%2,%3}, [%4];"
                : "=r"(af[0]), "=r"(af[1]), "=r"(af[2]), "=r"(af[3]) : "r"(addr));
            unsigned b0, b1;
            addr = vS + ((kk + b_k)*KSP + n_base2)*2;
            asm volatile("ldmatrix.sync.aligned.m8n8.x2.trans.shared.b16 {%0,%1}, [%2];"
                : "=r"(b0), "=r"(b1) : "r"(addr));
            asm volatile(
                "mma.sync.aligned.m16n8k16.row.col.f32.f16.f16.f32 "
                "{%0,%1,%2,%3}, {%4,%5,%6,%7}, {%8,%9}, {%0,%1,%2,%3};"
                : "+f"(acc2[0]), "+f"(acc2[1]), "+f"(acc2[2]), "+f"(acc2[3])
                : "r"(af[0]), "r"(af[1]), "r"(af[2]), "r"(af[3]),
                  "r"(b0), "r"(b1));
        }

        const int col = n_base2 + 2*(lane & 3);
        #pragma unroll
        for (int half = 0; half < 2; half++) {
            int qq = m_base + (lane >> 2) + half*8;
            float rinv = 1.0f / (part[qq*4+0] + part[qq*4+1] + part[qq*4+2] + part[qq*4+3]);
            int qi = qq >> 2, qj = qq & 3;
            int g = base + (it + qi)*Ww + (jt + qj);
            bf162 p = __float22bfloat162_rn(make_float2(acc2[half*2] * rinv,
                                                        acc2[half*2+1] * rinv));
            *(unsigned*)&out[(size_t)g*Cc + h*32 + col] = *(unsigned*)&p;
        }
    }
}

// ---------------------------------------------------------------------------
// Launch
// ---------------------------------------------------------------------------
extern "C" void kernel_launch(void* const* d_in, const int* in_sizes, int n_in,
                              void* d_out, int out_size)
{
    const float* query     = (const float*)d_in[0];
    const float* key_value = (const float*)d_in[1];
    const float* g1  = (const float*)d_in[2];
    const float* b1  = (const float*)d_in[3];
    const float* g2  = (const float*)d_in[4];
    const float* b2  = (const float*)d_in[5];
    const float* g3  = (const float*)d_in[6];
    const float* b3  = (const float*)d_in[7];
    const float* Wq  = (const float*)d_in[8];
    const float* bq  = (const float*)d_in[9];
    const float* Wkv = (const float*)d_in[10];
    const float* bkv = (const float*)d_in[11];
    const float* Wp  = (const float*)d_in[12];
    const float* bp  = (const float*)d_in[13];
    const float* rpb = (const float*)d_in[14];
    const float* W1  = (const float*)d_in[15];
    const float* bm1 = (const float*)d_in[16];
    const float* W2  = (const float*)d_in[17];
    const float* bm2 = (const float*)d_in[18];
    float* out = (float*)d_out;

    bf16*  qn     = nullptr; cudaGetSymbolAddress((void**)&qn,     g_qn);
    bf16*  kvn    = nullptr; cudaGetSymbolAddress((void**)&kvn,    g_kvn);
    bf16*  qbuf   = nullptr; cudaGetSymbolAddress((void**)&qbuf,   g_q);
    bf16*  kvbuf  = nullptr; cudaGetSymbolAddress((void**)&kvbuf,  g_kv);
    bf16*  attn   = nullptr; cudaGetSymbolAddress((void**)&attn,   g_attn);
    float* xbuf   = nullptr; cudaGetSymbolAddress((void**)&xbuf,   g_x);
    bf16*  hln    = nullptr; cudaGetSymbolAddress((void**)&hln,    g_hln);
    bf16*  wpb    = nullptr; cudaGetSymbolAddress((void**)&wpb,    g_wp);

    const int k128_smem = (64 + 128) * KP * 2;   // 52224 B
    const int attn_smem = (2*NPAD*KSP + 32*PP + 32*QP) * 2 + (169 + 128) * 4;
    const int mlp_smem  = 384 * KP * 2;          // 104448 B

    static bool attr_set = false;
    if (!attr_set) {
        cudaFuncSetAttribute(qkv_k128,
                             cudaFuncAttributeMaxDynamicSharedMemorySize, k128_smem);
        cudaFuncSetAttribute(gemm_k128<3,0,1>,
                             cudaFuncAttributeMaxDynamicSharedMemorySize, k128_smem);
        cudaFuncSetAttribute(nat_attn6,
                             cudaFuncAttributeMaxDynamicSharedMemorySize, attn_smem);
        cudaFuncSetAttribute(mlp_fused,
                             cudaFuncAttributeMaxDynamicSharedMemorySize, mlp_smem);
        attr_set = true;
    }

    // 1) LN1 + LN2 + weight conversion in ONE launch
    prep_kernel<<<4288, 256>>>(query, g1, b1, qn, key_value, g2, b2, kvn,
                               Wq, Wkv, Wp, W1, W2);

    // 2) Fused Q + KV projections (Q pre-scaled with log2e; V written as f16)
    qkv_k128<<<dim3(3, NTOK/64), 256, k128_smem>>>(qn, kvn, bq, bkv, qbuf, kvbuf);

    // 3) Neighborhood attention (tensor-core, paired f16 exp2)
    nat_attn6<<<Bq*(Hh/8)*(Ww/4)*NHh, 256, attn_smem>>>(qbuf, kvbuf, rpb, attn);

    // 4) Output projection + residual + fused LN3
    gemm_k128<3,0,1><<<dim3(1, NTOK/64), 256, k128_smem>>>(
        attn, wpb, bp, key_value, xbuf, Cc, 1.0f, g3, b3, hln);

    // 5) Fused MLP (hidden never hits HBM)
    mlp_fused<<<NTOK/64, 256, mlp_smem>>>(hln, bm1, bm2, xbuf, out);
}

// round 16
// speedup vs baseline: 2.2141x; 1.0266x over previous
#include <cuda_runtime.h>
#include <cuda_bf16.h>
#include <cuda_fp16.h>
#include <math.h>

// Problem constants
#define Bq  4
#define Hh  64
#define Ww  64
#define Cc  128
#define NHh 4
#define Kk  7
#define HDd 32
#define MLPD 512
#define NTOK (Bq*Hh*Ww)   // 16384

typedef __nv_bfloat16  bf16;
typedef __nv_bfloat162 bf162;

// Scratch (device globals)
__device__ __align__(16) bf16  g_qn    [NTOK*Cc];
__device__ __align__(16) bf16  g_kvn   [NTOK*Cc];
__device__ __align__(16) bf16  g_q     [NTOK*Cc];
__device__ __align__(16) bf16  g_kv    [NTOK*2*Cc];   // K half bf16, V half f16
__device__ __align__(16) bf16  g_attn  [NTOK*Cc];
__device__ __align__(16) float g_x     [NTOK*Cc];

// bf16 weights (converted once per launch)
__device__ __align__(16) bf16  g_wq [Cc*Cc];
__device__ __align__(16) bf16  g_wkv[Cc*2*Cc];
__device__ __align__(16) bf16  g_wp [Cc*Cc];
__device__ __align__(16) bf16  g_w1 [Cc*MLPD];
__device__ __align__(16) bf16  g_w2 [MLPD*Cc];

__device__ __forceinline__ unsigned s2u(const void* p) {
    return (unsigned)__cvta_generic_to_shared(p);
}

#define CP_ASYNC16(dst, src) \
    asm volatile("cp.async.ca.shared.global [%0], [%1], 16;" :: "r"(dst), "l"(src))

#define LOG2E 1.4426950408889634f

// ---------------------------------------------------------------------------
// Prep kernel: blocks [0,4096) = dual LayerNorm; blocks [4096,4288) = weight cvt
// ---------------------------------------------------------------------------
__global__ void prep_kernel(const float* __restrict__ in1, const float* __restrict__ gg1,
                            const float* __restrict__ bb1, bf16* __restrict__ out1,
                            const float* __restrict__ in2, const float* __restrict__ gg2,
                            const float* __restrict__ bb2, bf16* __restrict__ out2,
                            const float* __restrict__ Wq, const float* __restrict__ Wkv,
                            const float* __restrict__ Wp, const float* __restrict__ W1,
                            const float* __restrict__ W2)
{
    if (blockIdx.x >= 4096) {
        int i = (blockIdx.x - 4096) * 256 + threadIdx.x;   // 0..49151
        const float* src; bf16* dst; int off;
        if      (i < 4096)  { src = Wq;  dst = g_wq;  off = i; }
        else if (i < 12288) { src = Wkv; dst = g_wkv; off = i - 4096; }
        else if (i < 16384) { src = Wp;  dst = g_wp;  off = i - 12288; }
        else if (i < 32768) { src = W1;  dst = g_w1;  off = i - 16384; }
        else                { src = W2;  dst = g_w2;  off = i - 32768; }
        float4 v = ((const float4*)src)[off];
        bf162 lo = __float22bfloat162_rn(make_float2(v.x, v.y));
        bf162 hi = __float22bfloat162_rn(make_float2(v.z, v.w));
        uint2 pk; pk.x = *(unsigned*)&lo; pk.y = *(unsigned*)&hi;
        ((uint2*)dst)[off] = pk;
        return;
    }

    int w    = (blockIdx.x * blockDim.x + threadIdx.x) >> 5;
    int lane = threadIdx.x & 31;
    const float* in; const float* g; const float* b; bf16* out; int tok;
    if (w < NTOK) { in = in1; g = gg1; b = bb1; out = out1; tok = w; }
    else          { in = in2; g = gg2; b = bb2; out = out2; tok = w - NTOK; }

    const float4 v = *(const float4*)&in[(size_t)tok*Cc + lane*4];
    float s  = v.x + v.y + v.z + v.w;
    float sq = v.x*v.x + v.y*v.y + v.z*v.z + v.w*v.w;
    #pragma unroll
    for (int off = 16; off; off >>= 1) {
        s  += __shfl_xor_sync(0xffffffff, s,  off);
        sq += __shfl_xor_sync(0xffffffff, sq, off);
    }
    float mean = s * (1.0f/Cc);
    float var  = sq * (1.0f/Cc) - mean*mean;
    float inv  = rsqrtf(var + 1e-5f);

    const float4 gv = *(const float4*)&g[lane*4];
    const float4 bv = *(const float4*)&b[lane*4];
    bf162 o0 = __float22bfloat162_rn(make_float2((v.x-mean)*inv*gv.x + bv.x,
                                                 (v.y-mean)*inv*gv.y + bv.y));
    bf162 o1 = __float22bfloat162_rn(make_float2((v.z-mean)*inv*gv.z + bv.z,
                                                 (v.w-mean)*inv*gv.w + bv.w));
    uint2 pk; pk.x = *(unsigned*)&o0; pk.y = *(unsigned*)&o1;
    *(uint2*)&out[(size_t)tok*Cc + lane*4] = pk;
}

// ---------------------------------------------------------------------------
// MMA tile helper: one BK=32 slab (trans-B, [k][n] layout), bf16.
// ---------------------------------------------------------------------------
__device__ __forceinline__ void gemm_tile(
    unsigned aB, unsigned bB, int m_base, int n_base, int lane,
    float acc[8][4], int apitch, int bpitch)
{
    const int a_row_sel = lane & 15;
    const int a_k_sel   = (lane >> 4) << 3;
    const int b_k_sel   = (lane & 7) + (((lane >> 3) & 1) << 3);
    const int b_n_sel   = (lane >> 4) << 3;
    #pragma unroll
    for (int kk = 0; kk < 32; kk += 16) {
        unsigned af[4], bf[8][2];
        {
            unsigned addr = aB + ((m_base + a_row_sel)*apitch + kk + a_k_sel)*2;
            asm volatile("ldmatrix.sync.aligned.m8n8.x4.shared.b16 {%0,%1,%2,%3}, [%4];"
                : "=r"(af[0]), "=r"(af[1]), "=r"(af[2]), "=r"(af[3]) : "r"(addr));
        }
        #pragma unroll
        for (int np = 0; np < 4; np++) {
            unsigned r0, r1, r2, r3;
            unsigned addr = bB + ((kk + b_k_sel)*bpitch + n_base + np*16 + b_n_sel)*2;
            asm volatile("ldmatrix.sync.aligned.m8n8.x4.trans.shared.b16 {%0,%1,%2,%3}, [%4];"
                : "=r"(r0), "=r"(r1), "=r"(r2), "=r"(r3) : "r"(addr));
            bf[2*np  ][0] = r0; bf[2*np  ][1] = r1;
            bf[2*np+1][0] = r2; bf[2*np+1][1] = r3;
        }
        #pragma unroll
        for (int nt = 0; nt < 8; nt++)
            asm volatile(
                "mma.sync.aligned.m16n8k16.row.col.f32.bf16.bf16.f32 "
                "{%0,%1,%2,%3}, {%4,%5,%6,%7}, {%8,%9}, {%0,%1,%2,%3};"
                : "+f"(acc[nt][0]), "+f"(acc[nt][1]), "+f"(acc[nt][2]), "+f"(acc[nt][3])
                : "r"(af[0]), "r"(af[1]), "r"(af[2]), "r"(af[3]),
                  "r"(bf[nt][0]), "r"(bf[nt][1]));
    }
}

// ---------------------------------------------------------------------------
// Fully-staged K=128 GEMM (plain epilogue; LN fusion removed).
// ---------------------------------------------------------------------------
#define KP 136

template <int MODE, int OUTBF>
__global__ __launch_bounds__(256)
void gemm_k128(const bf16* __restrict__ A,
               const bf16* __restrict__ Wb,
               const float* __restrict__ bias,
               const float* __restrict__ res,
               void* __restrict__ Cout,
               int N, float scale)
{
    extern __shared__ bf16 sm[];
    bf16* As = sm;
    bf16* Bs = sm + 64*KP;

    const int tid  = threadIdx.x;
    const int bm   = blockIdx.y * 64;
    const int bn   = blockIdx.x * 128;
    const int warp = tid >> 5;
    const int lane = tid & 31;
    const int g    = lane >> 2;
    const int t    = lane & 3;
    const int m_base = (warp >> 1) * 16;
    const int n_base = (warp & 1) * 64;

    {
        const unsigned aS = s2u(As);
        #pragma unroll
        for (int i = 0; i < 4; i++) {
            int id = tid + i*256;
            int r = id >> 4, c = id & 15;
            CP_ASYNC16(aS + (r*KP + c*8)*2, A + (size_t)(bm + r)*Cc + c*8);
        }
        const unsigned bS = s2u(Bs);
        #pragma unroll
        for (int i = 0; i < 8; i++) {
            int id = tid + i*256;
            int r = id >> 4, c = id & 15;
            CP_ASYNC16(bS + (r*KP + c*8)*2, Wb + (size_t)r*N + bn + c*8);
        }
        asm volatile("cp.async.commit_group;");
    }

    float acc[8][4];
    #pragma unroll
    for (int nt = 0; nt < 8; nt++)
        #pragma unroll
        for (int e = 0; e < 4; e++) acc[nt][e] = 0.0f;

    asm volatile("cp.async.wait_group 0;");
    __syncthreads();

    const unsigned aS = s2u(As);
    const unsigned bS = s2u(Bs);
    #pragma unroll
    for (int kt = 0; kt < 4; kt++)
        gemm_tile(aS + kt*32*2, bS + (kt*32*KP)*2, m_base, n_base, lane, acc, KP, KP);

    float* Cf = (float*)Cout;
    bf16*  Cb = (bf16*)Cout;
    const int row0 = bm + m_base + g;
    const int row1 = row0 + 8;

    #pragma unroll
    for (int nt = 0; nt < 8; nt++) {
        int col = bn + n_base + nt*8 + 2*t;
        float b0 = bias[col], b1 = bias[col+1];
        float v00 = acc[nt][0] + b0;
        float v01 = acc[nt][1] + b1;
        float v10 = acc[nt][2] + b0;
        float v11 = acc[nt][3] + b1;
        if (MODE == 1) { v00 *= scale; v01 *= scale; v10 *= scale; v11 *= scale; }
        if (MODE == 3) {
            float2 r0 = *(const float2*)&res[(size_t)row0*N + col];
            float2 r1 = *(const float2*)&res[(size_t)row1*N + col];
            v00 += r0.x; v01 += r0.y; v10 += r1.x; v11 += r1.y;
        }
        if (OUTBF) {
            bf162 p0 = __float22bfloat162_rn(make_float2(v00, v01));
            bf162 p1 = __float22bfloat162_rn(make_float2(v10, v11));
            *(unsigned*)&Cb[(size_t)row0*N + col] = *(unsigned*)&p0;
            *(unsigned*)&Cb[(size_t)row1*N + col] = *(unsigned*)&p1;
        } else {
            *(float2*)&Cf[(size_t)row0*N + col] = make_float2(v00, v01);
            *(float2*)&Cf[(size_t)row1*N + col] = make_float2(v10, v11);
        }
    }
}

// ---------------------------------------------------------------------------
// Fused Q + KV projection, fully staged (K=128).
// cb 0 -> Q (scaled by HD^-0.5 * log2e, bf16), cb 1 -> K (bf16), cb 2 -> V (f16)
// ---------------------------------------------------------------------------
__global__ __launch_bounds__(256)
void qkv_k128(const bf16* __restrict__ qn, const bf16* __restrict__ kvn,
              const float* __restrict__ bq, const float* __restrict__ bkv,
              bf16* __restrict__ qout, bf16* __restrict__ kvout)
{
    extern __shared__ bf16 sm[];
    bf16* As = sm;
    bf16* Bs = sm + 64*KP;

    const int cb = blockIdx.x;
    const bool isQ = (cb == 0);
    const bf16*  A    = isQ ? qn : kvn;
    const bf16*  Wb   = isQ ? g_wq : g_wkv;
    const float* bias = isQ ? bq : bkv;
    bf16*        Cb   = isQ ? qout : kvout;
    const int N  = isQ ? Cc : 2*Cc;
    const int bn = isQ ? 0 : (cb - 1) * 128;

    const int tid  = threadIdx.x;
    const int bm   = blockIdx.y * 64;
    const int warp = tid >> 5;
    const int lane = tid & 31;
    const int g    = lane >> 2;
    const int t    = lane & 3;
    const int m_base = (warp >> 1) * 16;
    const int n_base = (warp & 1) * 64;

    {
        const unsigned aS = s2u(As);
        #pragma unroll
        for (int i = 0; i < 4; i++) {
            int id = tid + i*256;
            int r = id >> 4, c = id & 15;
            CP_ASYNC16(aS + (r*KP + c*8)*2, A + (size_t)(bm + r)*Cc + c*8);
        }
        const unsigned bS = s2u(Bs);
        #pragma unroll
        for (int i = 0; i < 8; i++) {
            int id = tid + i*256;
            int r = id >> 4, c = id & 15;
            CP_ASYNC16(bS + (r*KP + c*8)*2, Wb + (size_t)r*N + bn + c*8);
        }
        asm volatile("cp.async.commit_group;");
    }

    float acc[8][4];
    #pragma unroll
    for (int nt = 0; nt < 8; nt++)
        #pragma unroll
        for (int e = 0; e < 4; e++) acc[nt][e] = 0.0f;

    asm volatile("cp.async.wait_group 0;");
    __syncthreads();

    const unsigned aS = s2u(As);
    const unsigned bS = s2u(Bs);
    #pragma unroll
    for (int kt = 0; kt < 4; kt++)
        gemm_tile(aS + kt*32*2, bS + (kt*32*KP)*2, m_base, n_base, lane, acc, KP, KP);

    const float scale = 0.17677669529663689f * LOG2E;
    int row0 = bm + m_base + g;
    int row1 = row0 + 8;
    #pragma unroll
    for (int nt = 0; nt < 8; nt++) {
        int col = bn + n_base + nt*8 + 2*t;
        float b0 = bias[col], b1 = bias[col+1];
        float v00 = acc[nt][0] + b0;
        float v01 = acc[nt][1] + b1;
        float v10 = acc[nt][2] + b0;
        float v11 = acc[nt][3] + b1;
        if (isQ) { v00 *= scale; v01 *= scale; v10 *= scale; v11 *= scale; }
        if (cb == 2) {
            __half2 p0 = __floats2half2_rn(v00, v01);
            __half2 p1 = __floats2half2_rn(v10, v11);
            *(unsigned*)&Cb[(size_t)row0*N + col] = *(unsigned*)&p0;
            *(unsigned*)&Cb[(size_t)row1*N + col] = *(unsigned*)&p1;
        } else {
            bf162 p0 = __float22bfloat162_rn(make_float2(v00, v01));
            bf162 p1 = __float22bfloat162_rn(make_float2(v10, v11));
            *(unsigned*)&Cb[(size_t)row0*N + col] = *(unsigned*)&p0;
            *(unsigned*)&Cb[(size_t)row1*N + col] = *(unsigned*)&p1;
        }
    }
}

// ---------------------------------------------------------------------------
// Fused LN3 + MLP: out = x + gelu(LN3(x) @ W1 + bm1) @ W2 + bm2.
// LN3 computed in-kernel from xbuf (fp32) into the As bf16 smem tile,
// overlapped with W1-chunk-0 cp.async. hidden never leaves the CTA.
// smem: As 64x136 + Hc 64x136 + 2 x (128x136) = 104448 B.
// ---------------------------------------------------------------------------
__global__ __launch_bounds__(256)
void mlp_fused(const float* __restrict__ xbuf,
               const float* __restrict__ lng,
               const float* __restrict__ lnb,
               const float* __restrict__ bm1,
               const float* __restrict__ bm2,
               float* __restrict__ out)
{
    extern __shared__ bf16 sm[];
    bf16* As  = sm;                    // [64][136]
    bf16* Hc  = sm + 64*KP;            // [64][136]
    bf16* Wb0 = sm + 128*KP;           // [128][136]
    bf16* Wb1 = sm + 256*KP;           // [128][136]

    const int tid  = threadIdx.x;
    const int bm   = blockIdx.x * 64;
    const int warp = tid >> 5;
    const int lane = tid & 31;
    const int g    = lane >> 2;
    const int t    = lane & 3;
    const int m_base = (warp >> 1) * 16;
    const int n_base = (warp & 1) * 64;

    const unsigned aS = s2u(As);
    const unsigned hS = s2u(Hc);
    const unsigned wS0 = s2u(Wb0);
    const unsigned wS1 = s2u(Wb1);

    // kick off W1 chunk 0 first (overlaps with the LN prologue below)
    #pragma unroll
    for (int i = 0; i < 8; i++) {
        int id = tid + i*256;
        int r = id >> 4, c = id & 15;
        CP_ASYNC16(wS0 + (r*KP + c*8)*2, g_w1 + (size_t)r*MLPD + c*8);
    }
    asm volatile("cp.async.commit_group;");

    // LN3 prologue: warp w normalizes rows w*8..w*8+7 of the xbuf tile -> As
    {
        const float4 gv = *(const float4*)&lng[lane*4];
        const float4 bv = *(const float4*)&lnb[lane*4];
        #pragma unroll
        for (int rr = 0; rr < 8; rr++) {
            int row = warp*8 + rr;
            const float4 v = *(const float4*)&xbuf[(size_t)(bm + row)*Cc + lane*4];
            float s  = v.x + v.y + v.z + v.w;
            float sq = v.x*v.x + v.y*v.y + v.z*v.z + v.w*v.w;
            #pragma unroll
            for (int off = 16; off; off >>= 1) {
                s  += __shfl_xor_sync(0xffffffff, s,  off);
                sq += __shfl_xor_sync(0xffffffff, sq, off);
            }
            float mean = s * (1.0f/Cc);
            float var  = sq * (1.0f/Cc) - mean*mean;
            float inv  = rsqrtf(var + 1e-5f);
            bf162 o0 = __float22bfloat162_rn(make_float2((v.x-mean)*inv*gv.x + bv.x,
                                                         (v.y-mean)*inv*gv.y + bv.y));
            bf162 o1 = __float22bfloat162_rn(make_float2((v.z-mean)*inv*gv.z + bv.z,
                                                         (v.w-mean)*inv*gv.w + bv.w));
            uint2 pk; pk.x = *(unsigned*)&o0; pk.y = *(unsigned*)&o1;
            *(uint2*)&As[row*KP + lane*4] = pk;
        }
    }

    float accB[8][4];
    #pragma unroll
    for (int nt = 0; nt < 8; nt++)
        #pragma unroll
        for (int e = 0; e < 4; e++) accB[nt][e] = 0.0f;

    #pragma unroll
    for (int step = 0; step < 8; step++) {
        const int nxt = step + 1;
        if (nxt < 8) {
            const int cc = nxt >> 1;
            const unsigned dst = (nxt & 1) ? wS1 : wS0;
            if ((nxt & 1) == 0) {
                #pragma unroll
                for (int i = 0; i < 8; i++) {
                    int id = tid + i*256;
                    int r = id >> 4, c = id & 15;
                    CP_ASYNC16(dst + (r*KP + c*8)*2,
                               g_w1 + (size_t)r*MLPD + cc*128 + c*8);
                }
            } else {
                #pragma unroll
                for (int i = 0; i < 8; i++) {
                    int id = tid + i*256;
                    int r = id >> 4, c = id & 15;
                    CP_ASYNC16(dst + (r*KP + c*8)*2,
                               g_w2 + (size_t)(cc*128 + r)*Cc + c*8);
                }
            }
            asm volatile("cp.async.commit_group;");
            asm volatile("cp.async.wait_group 1;");
        } else {
            asm volatile("cp.async.wait_group 0;");
        }
        __syncthreads();

        const unsigned wS = (step & 1) ? wS1 : wS0;
        if ((step & 1) == 0) {
            const int cc = step >> 1;
            float accA[8][4];
            #pragma unroll
            for (int nt = 0; nt < 8; nt++)
                #pragma unroll
                for (int e = 0; e < 4; e++) accA[nt][e] = 0.0f;
            #pragma unroll
            for (int kt = 0; kt < 4; kt++)
                gemm_tile(aS + kt*32*2, wS + (kt*32*KP)*2, m_base, n_base, lane,
                          accA, KP, KP);

            const int lr0 = m_base + g, lr1 = lr0 + 8;
            #pragma unroll
            for (int nt = 0; nt < 8; nt++) {
                int lc  = n_base + nt*8 + 2*t;
                int col = cc*128 + lc;
                float b0 = bm1[col], b1 = bm1[col+1];
                float v00 = accA[nt][0] + b0;
                float v01 = accA[nt][1] + b1;
                float v10 = accA[nt][2] + b0;
                float v11 = accA[nt][3] + b1;
                v00 = 0.5f*v00*(1.0f + erff(v00*0.70710678118654752f));
                v01 = 0.5f*v01*(1.0f + erff(v01*0.70710678118654752f));
                v10 = 0.5f*v10*(1.0f + erff(v10*0.70710678118654752f));
                v11 = 0.5f*v11*(1.0f + erff(v11*0.70710678118654752f));
                bf162 p0 = __float22bfloat162_rn(make_float2(v00, v01));
                bf162 p1 = __float22bfloat162_rn(make_float2(v10, v11));
                *(unsigned*)&Hc[lr0*KP + lc] = *(unsigned*)&p0;
                *(unsigned*)&Hc[lr1*KP + lc] = *(unsigned*)&p1;
            }
            __syncthreads();
        } else {
            #pragma unroll
            for (int kt = 0; kt < 4; kt++)
                gemm_tile(hS + kt*32*2, wS + (kt*32*KP)*2, m_base, n_base, lane,
                          accB, KP, KP);
            __syncthreads();
        }
    }

    // final epilogue: out = accB + bm2 + xbuf (fp32 residual, L2-resident)
    const int row0 = bm + m_base + g;
    const int row1 = row0 + 8;
    #pragma unroll
    for (int nt = 0; nt < 8; nt++) {
        int col = n_base + nt*8 + 2*t;
        float b0 = bm2[col], b1 = bm2[col+1];
        float2 r0 = *(const float2*)&xbuf[(size_t)row0*Cc + col];
        float2 r1 = *(const float2*)&xbuf[(size_t)row1*Cc + col];
        *(float2*)&out[(size_t)row0*Cc + col] =
            make_float2(accB[nt][0] + b0 + r0.x, accB[nt][1] + b1 + r0.y);
        *(float2*)&out[(size_t)row1*Cc + col] =
            make_float2(accB[nt][2] + b0 + r1.x, accB[nt][3] + b1 + r1.y);
    }
}

// ---------------------------------------------------------------------------
// Neighborhood attention v6 (unchanged).
// ---------------------------------------------------------------------------
#define PR 14
#define PC 10
#define PTOK 140
#define NPAD 160
#define KSP 40
#define PP  168
#define QP  40

__global__ __launch_bounds__(256)
void nat_attn6(const bf16* __restrict__ q,
               const bf16* __restrict__ kv,
               const float* __restrict__ rpb,
               bf16* __restrict__ out)
{
    extern __shared__ char smc[];
    bf16*   Ks = (bf16*)smc;
    __half* Vs = (__half*)(Ks + NPAD*KSP);
    __half* Ps = (__half*)(Vs + NPAD*KSP);
    bf16*   Qs = (bf16*)(Ps + 32*PP);
    float*  rs   = (float*)(Qs + 32*QP);
    float*  part = rs + 169;

    const int blk = blockIdx.x;
    const int h   = blk & 3;
    const int r2  = blk >> 2;
    const int b   = r2 >> 7;
    const int rem = r2 & 127;
    const int it  = (rem >> 4) << 3;
    const int jt  = (rem & 15) << 2;

    int ip0 = it - 3; if (ip0 < 0) ip0 = 0; if (ip0 > Hh - PR) ip0 = Hh - PR;
    int jp0 = jt - 3; if (jp0 < 0) jp0 = 0; if (jp0 > Ww - PC) jp0 = Ww - PC;

    const int tid  = threadIdx.x;
    const int base = b * (Hh*Ww);
    const uint4* kv4 = (const uint4*)kv;

    for (int f = tid; f < PTOK*8; f += 256) {
        int tok = f >> 3;
        int c   = f & 7;
        int r   = (tok*205) >> 11;
        int cc  = tok - r*PC;
        int g   = base + (ip0 + r)*Ww + (jp0 + cc);
        if (c < 4) {
            *(uint4*)&Ks[tok*KSP + c*8] = kv4[(size_t)g*32 + h*4 + c];
        } else {
            int c2 = c - 4;
            *(uint4*)&Vs[tok*KSP + c2*8] = kv4[(size_t)g*32 + 16 + h*4 + c2];
        }
    }
    for (int f = tid; f < 100; f += 256) {
        int row = PTOK + f/5, cc = (f - (f/5)*5)*8;
        uint4 z = make_uint4(0,0,0,0);
        *(uint4*)&Vs[row*KSP + cc] = z;
    }
    for (int f = tid; f < 128; f += 256) {
        int qq = f >> 2, c = f & 3;
        int qi = qq >> 2, qj = qq & 3;
        int g = base + (it + qi)*Ww + (jt + qj);
        *(uint4*)&Qs[qq*QP + c*8] = ((const uint4*)q)[(size_t)g*16 + h*4 + c];
    }
    for (int f = tid; f < 169; f += 256) rs[f] = rpb[h*169 + f] * LOG2E;
    __syncthreads();

    const int w    = tid >> 5;
    const int lane = tid & 31;
    const int a_row = lane & 15;
    const int a_k   = (lane >> 4) << 3;
    const int bn_row = (lane & 7) + ((lane >> 4) << 3);
    const int bk_col = ((lane >> 3) & 1) << 3;
    const int b_k   = (lane & 7) + (((lane >> 3) & 1) << 3);

    const int m_base = (w >> 2) * 16;
    const int warpN  = w & 3;
    const int n_base = warpN * 40;

    float acc[5][4];
    {
        const unsigned qS = s2u(Qs), kS = s2u(Ks);
        #pragma unroll
        for (int nt = 0; nt < 5; nt++)
            #pragma unroll
            for (int e = 0; e < 4; e++) acc[nt][e] = 0.0f;

        #pragma unroll
        for (int kk = 0; kk < 32; kk += 16) {
            unsigned af[4], bf[5][2];
            unsigned addr = qS + ((m_base + a_row)*QP + kk + a_k)*2;
            asm volatile("ldmatrix.sync.aligned.m8n8.x4.shared.b16 {%0,%1,%2,%3}, [%4];"
                : "=r"(af[0]), "=r"(af[1]), "=r"(af[2]), "=r"(af[3]) : "r"(addr));
            #pragma unroll
            for (int np = 0; np < 2; np++) {
                unsigned r0, r1, r2, r3;
                addr = kS + ((n_base + np*16 + bn_row)*KSP + kk + bk_col)*2;
                asm volatile("ldmatrix.sync.aligned.m8n8.x4.shared.b16 {%0,%1,%2,%3}, [%4];"
                    : "=r"(r0), "=r"(r1), "=r"(r2), "=r"(r3) : "r"(addr));
                bf[2*np][0] = r0; bf[2*np][1] = r1;
                bf[2*np+1][0] = r2; bf[2*np+1][1] = r3;
            }
            {
                unsigned r0, r1;
                addr = kS + ((n_base + 32 + (lane & 7))*KSP + kk + bk_col)*2;
                asm volatile("ldmatrix.sync.aligned.m8n8.x2.shared.b16 {%0,%1}, [%2];"
                    : "=r"(r0), "=r"(r1) : "r"(addr));
                bf[4][0] = r0; bf[4][1] = r1;
            }
            #pragma unroll
            for (int nt = 0; nt < 5; nt++)
                asm volatile(
                    "mma.sync.aligned.m16n8k16.row.col.f32.bf16.bf16.f32 "
                    "{%0,%1,%2,%3}, {%4,%5,%6,%7}, {%8,%9}, {%0,%1,%2,%3};"
                    : "+f"(acc[nt][0]), "+f"(acc[nt][1]), "+f"(acc[nt][2]), "+f"(acc[nt][3])
                    : "r"(af[0]), "r"(af[1]), "r"(af[2]), "r"(af[3]),
                      "r"(bf[nt][0]), "r"(bf[nt][1]));
        }
    }

    {
        const int row0 = m_base + (lane >> 2);
        const int row1 = row0 + 8;

        int io0, jo0, bi0, bj0, io1, jo1, bi1, bj1;
        {
            int qi = row0 >> 2, qj = row0 & 3;
            int gi = it + qi, gj = jt + qj;
            int i0 = gi - 3; if (i0 < 0) i0 = 0; if (i0 > Hh - Kk) i0 = Hh - Kk;
            int j0 = gj - 3; if (j0 < 0) j0 = 0; if (j0 > Ww - Kk) j0 = Ww - Kk;
            io0 = i0 - ip0; jo0 = j0 - jp0;
            bi0 = ip0 - gi + (Kk - 1); bj0 = jp0 - gj + (Kk - 1);
        }
        {
            int qi = row1 >> 2, qj = row1 & 3;
            int gi = it + qi, gj = jt + qj;
            int i0 = gi - 3; if (i0 < 0) i0 = 0; if (i0 > Hh - Kk) i0 = Hh - Kk;
            int j0 = gj - 3; if (j0 < 0) j0 = 0; if (j0 > Ww - Kk) j0 = Ww - Kk;
            io1 = i0 - ip0; jo1 = j0 - jp0;
            bi1 = ip0 - gi + (Kk - 1); bj1 = jp0 - gj + (Kk - 1);
        }

        float s0 = 0.f, s1 = 0.f;
        #pragma unroll
        for (int nt = 0; nt < 5; nt++) {
            int colA = n_base + nt*8 + 2*(lane & 3);
            int tA = colA, tB = colA + 1;
            int rA = (tA*205) >> 11, cA = tA - rA*PC;
            int rB = (tB*205) >> 11, cB = tB - rB*PC;
            bool inA = (tA < PTOK), inB = (tB < PTOK);

            {
                bool vA = inA && (unsigned)(rA - io0) < 7u && (unsigned)(cA - jo0) < 7u;
                bool vB = inB && (unsigned)(rB - io0) < 7u && (unsigned)(cB - jo0) < 7u;
                unsigned pk = 0u;
                if (vA | vB) {
                    float y0 = vA ? acc[nt][0] + rs[(bi0 + rA)*13 + bj0 + cA] : -88.f;
                    float y1 = vB ? acc[nt][1] + rs[(bi0 + rB)*13 + bj0 + cB] : -88.f;
                    __half2 e2 = h2exp2(__floats2half2_rn(y0, y1));
                    pk = *(unsigned*)&e2;
                    float2 f = __half22float2(e2);
                    s0 += f.x + f.y;
                }
                *(unsigned*)&Ps[row0*PP + colA] = pk;
            }
            {
                bool vA = inA && (unsigned)(rA - io1) < 7u && (unsigned)(cA - jo1) < 7u;
                bool vB = inB && (unsigned)(rB - io1) < 7u && (unsigned)(cB - jo1) < 7u;
                unsigned pk = 0u;
                if (vA | vB) {
                    float y0 = vA ? acc[nt][2] + rs[(bi1 + rA)*13 + bj1 + cA] : -88.f;
                    float y1 = vB ? acc[nt][3] + rs[(bi1 + rB)*13 + bj1 + cB] : -88.f;
                    __half2 e2 = h2exp2(__floats2half2_rn(y0, y1));
                    pk = *(unsigned*)&e2;
                    float2 f = __half22float2(e2);
                    s1 += f.x + f.y;
                }
                *(unsigned*)&Ps[row1*PP + colA] = pk;
            }
        }
        #pragma unroll
        for (int off = 1; off < 4; off <<= 1) {
            s0 += __shfl_xor_sync(0xffffffff, s0, off);
            s1 += __shfl_xor_sync(0xffffffff, s1, off);
        }
        if ((lane & 3) == 0) {
            part[row0*4 + warpN] = s0;
            part[row1*4 + warpN] = s1;
        }
    }
    __syncthreads();

    {
        const int n_base2 = warpN * 8;
        const unsigned pS = s2u(Ps), vS = s2u(Vs);
        float acc2[4] = {0.f, 0.f, 0.f, 0.f};

        #pragma unroll
        for (int kt = 0; kt < 10; kt++) {
            int kk = kt*16;
            unsigned af[4];
            unsigned addr = pS + ((m_base + a_row)*PP + kk + a_k)*2;
            asm volatile("ldmatrix.sync.aligned.m8n8.x4.shared.b16 {%0,%1,%2,%3}, [%4];"
                : "=r"(af[0]), "=r"(af[1]), "=r"(af[2]), "=r"(af[3]) : "r"(addr));
            unsigned b0, b1;
            addr = vS + ((kk + b_k)*KSP + n_base2)*2;
            asm volatile("ldmatrix.sync.aligned.m8n8.x2.trans.shared.b16 {%0,%1}, [%2];"
                : "=r"(b0), "=r"(b1) : "r"(addr));
            asm volatile(
                "mma.sync.aligned.m16n8k16.row.col.f32.f16.f16.f32 "
                "{%0,%1,%2,%3}, {%4,%5,%6,%7}, {%8,%9}, {%0,%1,%2,%3};"
                : "+f"(acc2[0]), "+f"(acc2[1]), "+f"(acc2[2]), "+f"(acc2[3])
                : "r"(af[0]), "r"(af[1]), "r"(af[2]), "r"(af[3]),
                  "r"(b0), "r"(b1));
        }

        const int col = n_base2 + 2*(lane & 3);
        #pragma unroll
        for (int half = 0; half < 2; half++) {
            int qq = m_base + (lane >> 2) + half*8;
            float rinv = 1.0f / (part[qq*4+0] + part[qq*4+1] + part[qq*4+2] + part[qq*4+3]);
            int qi = qq >> 2, qj = qq & 3;
            int g = base + (it + qi)*Ww + (jt + qj);
            bf162 p = __float22bfloat162_rn(make_float2(acc2[half*2] * rinv,
                                                        acc2[half*2+1] * rinv));
            *(unsigned*)&out[(size_t)g*Cc + h*32 + col] = *(unsigned*)&p;
        }
    }
}

// ---------------------------------------------------------------------------
// Launch
// ---------------------------------------------------------------------------
extern "C" void kernel_launch(void* const* d_in, const int* in_sizes, int n_in,
                              void* d_out, int out_size)
{
    const float* query     = (const float*)d_in[0];
    const float* key_value = (const float*)d_in[1];
    const float* g1  = (const float*)d_in[2];
    const float* b1  = (const float*)d_in[3];
    const float* g2  = (const float*)d_in[4];
    const float* b2  = (const float*)d_in[5];
    const float* g3  = (const float*)d_in[6];
    const float* b3  = (const float*)d_in[7];
    const float* Wq  = (const float*)d_in[8];
    const float* bq  = (const float*)d_in[9];
    const float* Wkv = (const float*)d_in[10];
    const float* bkv = (const float*)d_in[11];
    const float* Wp  = (const float*)d_in[12];
    const float* bp  = (const float*)d_in[13];
    const float* rpb = (const float*)d_in[14];
    const float* W1  = (const float*)d_in[15];
    const float* bm1 = (const float*)d_in[16];
    const float* W2  = (const float*)d_in[17];
    const float* bm2 = (const float*)d_in[18];
    float* out = (float*)d_out;

    bf16*  qn     = nullptr; cudaGetSymbolAddress((void**)&qn,     g_qn);
    bf16*  kvn    = nullptr; cudaGetSymbolAddress((void**)&kvn,    g_kvn);
    bf16*  qbuf   = nullptr; cudaGetSymbolAddress((void**)&qbuf,   g_q);
    bf16*  kvbuf  = nullptr; cudaGetSymbolAddress((void**)&kvbuf,  g_kv);
    bf16*  attn   = nullptr; cudaGetSymbolAddress((void**)&attn,   g_attn);
    float* xbuf   = nullptr; cudaGetSymbolAddress((void**)&xbuf,   g_x);
    bf16*  wpb    = nullptr; cudaGetSymbolAddress((void**)&wpb,    g_wp);

    const int k128_smem = (64 + 128) * KP * 2;   // 52224 B
    const int attn_smem = (2*NPAD*KSP + 32*PP + 32*QP) * 2 + (169 + 128) * 4;
    const int mlp_smem  = 384 * KP * 2;          // 104448 B

    static bool attr_set = false;
    if (!attr_set) {
        cudaFuncSetAttribute(qkv_k128,
                             cudaFuncAttributeMaxDynamicSharedMemorySize, k128_smem);
        cudaFuncSetAttribute(gemm_k128<3,0>,
                             cudaFuncAttributeMaxDynamicSharedMemorySize, k128_smem);
        cudaFuncSetAttribute(nat_attn6,
                             cudaFuncAttributeMaxDynamicSharedMemorySize, attn_smem);
        cudaFuncSetAttribute(mlp_fused,
                             cudaFuncAttributeMaxDynamicSharedMemorySize, mlp_smem);
        attr_set = true;
    }

    // 1) LN1 + LN2 + weight conversion in ONE launch
    prep_kernel<<<4288, 256>>>(query, g1, b1, qn, key_value, g2, b2, kvn,
                               Wq, Wkv, Wp, W1, W2);

    // 2) Fused Q + KV projections (Q pre-scaled with log2e; V written as f16)
    qkv_k128<<<dim3(3, NTOK/64), 256, k128_smem>>>(qn, kvn, bq, bkv, qbuf, kvbuf);

    // 3) Neighborhood attention (tensor-core, paired f16 exp2)
    nat_attn6<<<Bq*(Hh/8)*(Ww/4)*NHh, 256, attn_smem>>>(qbuf, kvbuf, rpb, attn);

    // 4) Output projection + residual (plain epilogue, fp32 xbuf)
    gemm_k128<3,0><<<dim3(1, NTOK/64), 256, k128_smem>>>(
        attn, wpb, bp, key_value, xbuf, Cc, 1.0f);

    // 5) Fused LN3 + MLP (hidden never hits HBM)
    mlp_fused<<<NTOK/64, 256, mlp_smem>>>(xbuf, g3, b3, bm1, bm2, out);
}